// round 1
// baseline (speedup 1.0000x reference)
#include <cuda_runtime.h>
#include <math.h>

// Problem constants
#define BATCH   8
#define SEQ     2048
#define DIM     512
#define HEADS   8
#define DHEAD   64
#define ROWS    (BATCH * SEQ)          // 16384
#define TRIPLE  (3 * DIM)              // 1536

// ---------------- scratch (device globals; no runtime allocation) ----------
__device__ float g_xn [ROWS * DIM];    // layernorm output, [row, dim]
__device__ float g_q  [ROWS * DIM];    // [b][h][n][d], pre-scaled by 1/8
__device__ float g_k  [ROWS * DIM];    // [b][h][n][d]
__device__ float g_v  [ROWS * DIM];    // [b][h][n][d]
__device__ float g_att[ROWS * DIM];    // [b][n][h*64+d]

// ========================= LayerNorm ======================================
__global__ void __launch_bounds__(128)
ln_kernel(const float* __restrict__ x,
          const float* __restrict__ gamma,
          const float* __restrict__ beta)
{
    int row = blockIdx.x;
    int t   = threadIdx.x;                      // 128 threads, 4 floats each
    const float4* xr = reinterpret_cast<const float4*>(x) + (size_t)row * 128;
    float4 v = xr[t];

    __shared__ float red[4];
    float s = v.x + v.y + v.z + v.w;
    #pragma unroll
    for (int o = 16; o; o >>= 1) s += __shfl_xor_sync(0xffffffffu, s, o);
    if ((t & 31) == 0) red[t >> 5] = s;
    __syncthreads();
    float mu = (red[0] + red[1] + red[2] + red[3]) * (1.0f / 512.0f);

    float dx0 = v.x - mu, dx1 = v.y - mu, dx2 = v.z - mu, dx3 = v.w - mu;
    float s2 = dx0*dx0 + dx1*dx1 + dx2*dx2 + dx3*dx3;
    #pragma unroll
    for (int o = 16; o; o >>= 1) s2 += __shfl_xor_sync(0xffffffffu, s2, o);
    __syncthreads();
    if ((t & 31) == 0) red[t >> 5] = s2;
    __syncthreads();
    float var  = (red[0] + red[1] + red[2] + red[3]) * (1.0f / 512.0f);
    float rstd = rsqrtf(var + 1e-6f);

    float4 g  = reinterpret_cast<const float4*>(gamma)[t];
    float4 bb = reinterpret_cast<const float4*>(beta)[t];
    float4 o4;
    o4.x = dx0 * rstd * g.x + bb.x;
    o4.y = dx1 * rstd * g.y + bb.y;
    o4.z = dx2 * rstd * g.z + bb.z;
    o4.w = dx3 * rstd * g.w + bb.w;
    (reinterpret_cast<float4*>(g_xn) + (size_t)row * 128)[t] = o4;
}

// ========================= QKV GEMM + scatter =============================
// C[m, c] = sum_k g_xn[m,k] * w_qkv[c,k];  c in [0,1536).
// Scatter into g_q/g_k/g_v with layout [b][h][n][d]; q is scaled by 0.125.
__global__ void __launch_bounds__(256)
qkv_gemm(const float* __restrict__ W)
{
    __shared__ float As[16][68];
    __shared__ float Bs[16][68];

    int tid = threadIdx.x;
    int tx = tid & 15, ty = tid >> 4;
    int m0 = blockIdx.y * 64;
    int n0 = blockIdx.x * 64;

    int lm = tid >> 2;            // 0..63
    int lk = (tid & 3) << 2;      // 0,4,8,12
    const float* aptr = g_xn + (size_t)(m0 + lm) * 512 + lk;
    const float* bptr = W    + (size_t)(n0 + lm) * 512 + lk;

    float acc[4][4] = {};

    for (int k0 = 0; k0 < 512; k0 += 16) {
        float4 a4 = *reinterpret_cast<const float4*>(aptr + k0);
        float4 b4 = *reinterpret_cast<const float4*>(bptr + k0);
        As[lk+0][lm] = a4.x; As[lk+1][lm] = a4.y; As[lk+2][lm] = a4.z; As[lk+3][lm] = a4.w;
        Bs[lk+0][lm] = b4.x; Bs[lk+1][lm] = b4.y; Bs[lk+2][lm] = b4.z; Bs[lk+3][lm] = b4.w;
        __syncthreads();
        #pragma unroll
        for (int kk = 0; kk < 16; kk++) {
            float4 av = *reinterpret_cast<const float4*>(&As[kk][ty * 4]);
            float4 bv = *reinterpret_cast<const float4*>(&Bs[kk][tx * 4]);
            acc[0][0] += av.x*bv.x; acc[0][1] += av.x*bv.y; acc[0][2] += av.x*bv.z; acc[0][3] += av.x*bv.w;
            acc[1][0] += av.y*bv.x; acc[1][1] += av.y*bv.y; acc[1][2] += av.y*bv.z; acc[1][3] += av.y*bv.w;
            acc[2][0] += av.z*bv.x; acc[2][1] += av.z*bv.y; acc[2][2] += av.z*bv.z; acc[2][3] += av.z*bv.w;
            acc[3][0] += av.w*bv.x; acc[3][1] += av.w*bv.y; acc[3][2] += av.w*bv.z; acc[3][3] += av.w*bv.w;
        }
        __syncthreads();
    }

    int col0   = n0 + tx * 4;
    int which  = col0 >> 9;          // 0=q 1=k 2=v
    int within = col0 & 511;
    int h      = within >> 6;
    int d0     = within & 63;
    float* dst = (which == 0) ? g_q : (which == 1) ? g_k : g_v;
    float  scl = (which == 0) ? 0.125f : 1.0f;

    #pragma unroll
    for (int r = 0; r < 4; r++) {
        int m = m0 + ty * 4 + r;
        int b = m >> 11;
        int n = m & 2047;
        float4 o4 = make_float4(acc[r][0]*scl, acc[r][1]*scl, acc[r][2]*scl, acc[r][3]*scl);
        *reinterpret_cast<float4*>(&dst[((size_t)((b << 3) + h) * 2048 + n) * 64 + d0]) = o4;
    }
}

// ========================= Flash attention ================================
// grid: (32 q-tiles, 64 bh), block 256 (16x16), Br=Bc=64, online softmax.
#define QS_OFF 0
#define KS_OFF 4352
#define VS_OFF 8704
#define SS_OFF 12800
#define MS_OFF 17152
#define LS_OFF 17216
#define FS_OFF 17280
#define FLASH_SMEM_BYTES (17344 * 4)

__global__ void __launch_bounds__(256)
flash_kernel()
{
    extern __shared__ float sm[];
    float* Qs  = sm + QS_OFF;   // [64 d][68] transposed
    float* Ks  = sm + KS_OFF;   // [64 d][68] transposed
    float* Vs  = sm + VS_OFF;   // [64 j][64 d]
    float* Ss  = sm + SS_OFF;   // [64 i][68]
    float* m_s = sm + MS_OFF;
    float* l_s = sm + LS_OFF;
    float* f_s = sm + FS_OFF;

    int bh = blockIdx.y;
    int qt = blockIdx.x;
    int tid = threadIdx.x;
    int tx = tid & 15, ty = tid >> 4;

    const float* qbase = g_q + ((size_t)bh * 2048 + qt * 64) * 64;

    // load Q transposed: Qs[d][i]
    for (int i = tid; i < 1024; i += 256) {
        int r  = i >> 4;
        int dq = (i & 15) << 2;
        float4 val = *reinterpret_cast<const float4*>(qbase + r * 64 + dq);
        Qs[(dq + 0) * 68 + r] = val.x;
        Qs[(dq + 1) * 68 + r] = val.y;
        Qs[(dq + 2) * 68 + r] = val.z;
        Qs[(dq + 3) * 68 + r] = val.w;
    }
    if (tid < 64) { m_s[tid] = -1e30f; l_s[tid] = 0.0f; }

    float o[4][4] = {};
    __syncthreads();

    for (int kt = 0; kt < 32; kt++) {
        const float* kbase = g_k + ((size_t)bh * 2048 + kt * 64) * 64;
        const float* vbase = g_v + ((size_t)bh * 2048 + kt * 64) * 64;
        for (int i = tid; i < 1024; i += 256) {
            int r  = i >> 4;
            int dq = (i & 15) << 2;
            float4 kv = *reinterpret_cast<const float4*>(kbase + r * 64 + dq);
            Ks[(dq + 0) * 68 + r] = kv.x;
            Ks[(dq + 1) * 68 + r] = kv.y;
            Ks[(dq + 2) * 68 + r] = kv.z;
            Ks[(dq + 3) * 68 + r] = kv.w;
            float4 vv = *reinterpret_cast<const float4*>(vbase + r * 64 + dq);
            *reinterpret_cast<float4*>(&Vs[r * 64 + dq]) = vv;
        }
        __syncthreads();

        // S = Q K^T (scale already folded into q)
        float acc[4][4] = {};
        #pragma unroll 8
        for (int d = 0; d < 64; d++) {
            float4 av = *reinterpret_cast<const float4*>(&Qs[d * 68 + ty * 4]);
            float4 bv = *reinterpret_cast<const float4*>(&Ks[d * 68 + tx * 4]);
            acc[0][0] += av.x*bv.x; acc[0][1] += av.x*bv.y; acc[0][2] += av.x*bv.z; acc[0][3] += av.x*bv.w;
            acc[1][0] += av.y*bv.x; acc[1][1] += av.y*bv.y; acc[1][2] += av.y*bv.z; acc[1][3] += av.y*bv.w;
            acc[2][0] += av.z*bv.x; acc[2][1] += av.z*bv.y; acc[2][2] += av.z*bv.z; acc[2][3] += av.z*bv.w;
            acc[3][0] += av.w*bv.x; acc[3][1] += av.w*bv.y; acc[3][2] += av.w*bv.z; acc[3][3] += av.w*bv.w;
        }
        #pragma unroll
        for (int r = 0; r < 4; r++)
            *reinterpret_cast<float4*>(&Ss[(ty * 4 + r) * 68 + tx * 4]) =
                make_float4(acc[r][0], acc[r][1], acc[r][2], acc[r][3]);
        __syncthreads();

        // online softmax: warp w owns rows [8w, 8w+8)
        int w = tid >> 5, lane = tid & 31;
        for (int rr = 0; rr < 8; rr++) {
            int row = w * 8 + rr;
            float s1 = Ss[row * 68 + lane];
            float s2 = Ss[row * 68 + 32 + lane];
            float mx = fmaxf(s1, s2);
            #pragma unroll
            for (int oo = 16; oo; oo >>= 1) mx = fmaxf(mx, __shfl_xor_sync(0xffffffffu, mx, oo));
            float m_old = m_s[row];
            float m_new = fmaxf(m_old, mx);
            float p1 = __expf(s1 - m_new);
            float p2 = __expf(s2 - m_new);
            Ss[row * 68 + lane]      = p1;
            Ss[row * 68 + 32 + lane] = p2;
            float ps = p1 + p2;
            #pragma unroll
            for (int oo = 16; oo; oo >>= 1) ps += __shfl_xor_sync(0xffffffffu, ps, oo);
            if (lane == 0) {
                float f = __expf(m_old - m_new);
                f_s[row] = f;
                l_s[row] = l_s[row] * f + ps;
                m_s[row] = m_new;
            }
        }
        __syncthreads();

        // rescale O and accumulate P*V
        float fr0 = f_s[ty * 4 + 0], fr1 = f_s[ty * 4 + 1],
              fr2 = f_s[ty * 4 + 2], fr3 = f_s[ty * 4 + 3];
        #pragma unroll
        for (int c = 0; c < 4; c++) { o[0][c] *= fr0; o[1][c] *= fr1; o[2][c] *= fr2; o[3][c] *= fr3; }

        #pragma unroll 8
        for (int j = 0; j < 64; j++) {
            float4 vv = *reinterpret_cast<const float4*>(&Vs[j * 64 + tx * 4]);
            float p0 = Ss[(ty * 4 + 0) * 68 + j];
            float p1 = Ss[(ty * 4 + 1) * 68 + j];
            float p2 = Ss[(ty * 4 + 2) * 68 + j];
            float p3 = Ss[(ty * 4 + 3) * 68 + j];
            o[0][0] += p0*vv.x; o[0][1] += p0*vv.y; o[0][2] += p0*vv.z; o[0][3] += p0*vv.w;
            o[1][0] += p1*vv.x; o[1][1] += p1*vv.y; o[1][2] += p1*vv.z; o[1][3] += p1*vv.w;
            o[2][0] += p2*vv.x; o[2][1] += p2*vv.y; o[2][2] += p2*vv.z; o[2][3] += p2*vv.w;
            o[3][0] += p3*vv.x; o[3][1] += p3*vv.y; o[3][2] += p3*vv.z; o[3][3] += p3*vv.w;
        }
        __syncthreads();
    }

    int b = bh >> 3, h = bh & 7;
    #pragma unroll
    for (int r = 0; r < 4; r++) {
        float inv = 1.0f / l_s[ty * 4 + r];
        int n = qt * 64 + ty * 4 + r;
        float4 res = make_float4(o[r][0]*inv, o[r][1]*inv, o[r][2]*inv, o[r][3]*inv);
        *reinterpret_cast<float4*>(&g_att[((size_t)b * 2048 + n) * 512 + h * 64 + tx * 4]) = res;
    }
}

// ========================= Output projection ==============================
// out[m, c] = sum_k g_att[m,k] * w_proj[c,k] + b_proj[c]
__global__ void __launch_bounds__(256)
proj_gemm(const float* __restrict__ W, const float* __restrict__ bias,
          float* __restrict__ out)
{
    __shared__ float As[16][68];
    __shared__ float Bs[16][68];

    int tid = threadIdx.x;
    int tx = tid & 15, ty = tid >> 4;
    int m0 = blockIdx.y * 64;
    int n0 = blockIdx.x * 64;

    int lm = tid >> 2;
    int lk = (tid & 3) << 2;
    const float* aptr = g_att + (size_t)(m0 + lm) * 512 + lk;
    const float* bptr = W     + (size_t)(n0 + lm) * 512 + lk;

    float acc[4][4] = {};

    for (int k0 = 0; k0 < 512; k0 += 16) {
        float4 a4 = *reinterpret_cast<const float4*>(aptr + k0);
        float4 b4 = *reinterpret_cast<const float4*>(bptr + k0);
        As[lk+0][lm] = a4.x; As[lk+1][lm] = a4.y; As[lk+2][lm] = a4.z; As[lk+3][lm] = a4.w;
        Bs[lk+0][lm] = b4.x; Bs[lk+1][lm] = b4.y; Bs[lk+2][lm] = b4.z; Bs[lk+3][lm] = b4.w;
        __syncthreads();
        #pragma unroll
        for (int kk = 0; kk < 16; kk++) {
            float4 av = *reinterpret_cast<const float4*>(&As[kk][ty * 4]);
            float4 bv = *reinterpret_cast<const float4*>(&Bs[kk][tx * 4]);
            acc[0][0] += av.x*bv.x; acc[0][1] += av.x*bv.y; acc[0][2] += av.x*bv.z; acc[0][3] += av.x*bv.w;
            acc[1][0] += av.y*bv.x; acc[1][1] += av.y*bv.y; acc[1][2] += av.y*bv.z; acc[1][3] += av.y*bv.w;
            acc[2][0] += av.z*bv.x; acc[2][1] += av.z*bv.y; acc[2][2] += av.z*bv.z; acc[2][3] += av.z*bv.w;
            acc[3][0] += av.w*bv.x; acc[3][1] += av.w*bv.y; acc[3][2] += av.w*bv.z; acc[3][3] += av.w*bv.w;
        }
        __syncthreads();
    }

    int col0 = n0 + tx * 4;
    float4 bi = *reinterpret_cast<const float4*>(&bias[col0]);
    #pragma unroll
    for (int r = 0; r < 4; r++) {
        int m = m0 + ty * 4 + r;
        float4 o4 = make_float4(acc[r][0] + bi.x, acc[r][1] + bi.y,
                                acc[r][2] + bi.z, acc[r][3] + bi.w);
        *reinterpret_cast<float4*>(&out[(size_t)m * 512 + col0]) = o4;
    }
}

// ========================= launch =========================================
extern "C" void kernel_launch(void* const* d_in, const int* in_sizes, int n_in,
                              void* d_out, int out_size)
{
    const float* x      = (const float*)d_in[0];
    const float* w_qkv  = (const float*)d_in[1];
    const float* w_proj = (const float*)d_in[2];
    const float* b_proj = (const float*)d_in[3];
    const float* gamma  = (const float*)d_in[4];
    const float* beta   = (const float*)d_in[5];
    float* out = (float*)d_out;

    cudaFuncSetAttribute(flash_kernel,
                         cudaFuncAttributeMaxDynamicSharedMemorySize,
                         FLASH_SMEM_BYTES);

    ln_kernel<<<ROWS, 128>>>(x, gamma, beta);
    qkv_gemm<<<dim3(TRIPLE / 64, ROWS / 64), 256>>>(w_qkv);
    flash_kernel<<<dim3(SEQ / 64, BATCH * HEADS), 256, FLASH_SMEM_BYTES>>>();
    proj_gemm<<<dim3(DIM / 64, ROWS / 64), 256>>>(w_proj, b_proj, out);
}

// round 3
// speedup vs baseline: 1.4717x; 1.4717x over previous
#include <cuda_runtime.h>
#include <cuda_bf16.h>
#include <stdint.h>
#include <math.h>

// Problem constants
#define BATCH   8
#define SEQ     2048
#define DIM     512
#define HEADS   8
#define DHEAD   64
#define ROWS    (BATCH * SEQ)          // 16384
#define TRIPLE  (3 * DIM)              // 1536

// ---------------- scratch (device globals; no runtime allocation) ----------
__device__ float g_xn [ROWS * DIM];    // layernorm output, [row, dim]
__device__ float g_q  [ROWS * DIM];    // [b][h][n][d], pre-scaled by 1/8
__device__ float g_k  [ROWS * DIM];    // [b][h][n][d]
__device__ float g_v  [ROWS * DIM];    // [b][h][n][d]
__device__ float g_att[ROWS * DIM];    // [b][n][h*64+d]

// ---------------- bf16 split helpers --------------------------------------
__device__ __forceinline__ void split_pack(float x, float y,
                                           uint32_t& hi, uint32_t& lo)
{
    __nv_bfloat16 hx = __float2bfloat16(x);
    __nv_bfloat16 hy = __float2bfloat16(y);
    __nv_bfloat16 lx = __float2bfloat16(x - __bfloat162float(hx));
    __nv_bfloat16 ly = __float2bfloat16(y - __bfloat162float(hy));
    __nv_bfloat162 h2; h2.x = hx; h2.y = hy;
    __nv_bfloat162 l2; l2.x = lx; l2.y = ly;
    hi = *reinterpret_cast<uint32_t*>(&h2);
    lo = *reinterpret_cast<uint32_t*>(&l2);
}

__device__ __forceinline__ void mma_bf16(float* c, const uint32_t* a,
                                         uint32_t b0, uint32_t b1)
{
    asm volatile(
        "mma.sync.aligned.m16n8k16.row.col.f32.bf16.bf16.f32 "
        "{%0,%1,%2,%3}, {%4,%5,%6,%7}, {%8,%9}, {%0,%1,%2,%3};\n"
        : "+f"(c[0]), "+f"(c[1]), "+f"(c[2]), "+f"(c[3])
        : "r"(a[0]), "r"(a[1]), "r"(a[2]), "r"(a[3]), "r"(b0), "r"(b1));
}

// ========================= LayerNorm ======================================
__global__ void __launch_bounds__(128)
ln_kernel(const float* __restrict__ x,
          const float* __restrict__ gamma,
          const float* __restrict__ beta)
{
    int row = blockIdx.x;
    int t   = threadIdx.x;
    const float4* xr = reinterpret_cast<const float4*>(x) + (size_t)row * 128;
    float4 v = xr[t];

    __shared__ float red[4];
    float s = v.x + v.y + v.z + v.w;
    #pragma unroll
    for (int o = 16; o; o >>= 1) s += __shfl_xor_sync(0xffffffffu, s, o);
    if ((t & 31) == 0) red[t >> 5] = s;
    __syncthreads();
    float mu = (red[0] + red[1] + red[2] + red[3]) * (1.0f / 512.0f);

    float dx0 = v.x - mu, dx1 = v.y - mu, dx2 = v.z - mu, dx3 = v.w - mu;
    float s2 = dx0*dx0 + dx1*dx1 + dx2*dx2 + dx3*dx3;
    #pragma unroll
    for (int o = 16; o; o >>= 1) s2 += __shfl_xor_sync(0xffffffffu, s2, o);
    __syncthreads();
    if ((t & 31) == 0) red[t >> 5] = s2;
    __syncthreads();
    float var  = (red[0] + red[1] + red[2] + red[3]) * (1.0f / 512.0f);
    float rstd = rsqrtf(var + 1e-6f);

    float4 g  = reinterpret_cast<const float4*>(gamma)[t];
    float4 bb = reinterpret_cast<const float4*>(beta)[t];
    float4 o4;
    o4.x = dx0 * rstd * g.x + bb.x;
    o4.y = dx1 * rstd * g.y + bb.y;
    o4.z = dx2 * rstd * g.z + bb.z;
    o4.w = dx3 * rstd * g.w + bb.w;
    (reinterpret_cast<float4*>(g_xn) + (size_t)row * 128)[t] = o4;
}

// ========================= GEMM (bf16x3 tensor) ===========================
// C[m,c] = sum_k A[m,k] * W[c,k].  Block tile 128m x 64n, k-chunk 32.
// 256 threads = 8 warps (4m x 2n), warp tile 32x32.
// MODE 0: qkv (scatter to g_q/g_k/g_v, scale q), MODE 1: proj (+bias -> out)
#define GSTR 36   // smem k-stride (bf16 elems), padded

template<int MODE>
__global__ void __launch_bounds__(256)
gemm_mma(const float* __restrict__ A, const float* __restrict__ W,
         const float* __restrict__ bias, float* __restrict__ out)
{
    __shared__ __nv_bfloat16 Ah[128][GSTR], Al[128][GSTR];
    __shared__ __nv_bfloat16 Bh[ 64][GSTR], Bl[ 64][GSTR];

    int tid  = threadIdx.x;
    int lane = tid & 31, warp = tid >> 5;
    int g = lane >> 2, t4 = lane & 3;
    int wm = warp & 3, wn = warp >> 2;
    int m0 = wm * 32, n0 = wn * 32;
    int bm0 = blockIdx.y * 128;
    int bn0 = blockIdx.x * 64;

    float acc[2][4][4] = {};

    for (int k0 = 0; k0 < 512; k0 += 32) {
        // load A tile 128x32 (4 float4 per thread)
        #pragma unroll
        for (int j = 0; j < 4; j++) {
            int idx = tid + j * 256;
            int r = idx >> 3, c4 = (idx & 7) << 2;
            float4 v = *reinterpret_cast<const float4*>(
                A + (size_t)(bm0 + r) * 512 + k0 + c4);
            uint32_t h0, l0, h1, l1;
            split_pack(v.x, v.y, h0, l0);
            split_pack(v.z, v.w, h1, l1);
            *reinterpret_cast<uint32_t*>(&Ah[r][c4])     = h0;
            *reinterpret_cast<uint32_t*>(&Ah[r][c4 + 2]) = h1;
            *reinterpret_cast<uint32_t*>(&Al[r][c4])     = l0;
            *reinterpret_cast<uint32_t*>(&Al[r][c4 + 2]) = l1;
        }
        // load B tile 64x32 (2 float4 per thread)
        #pragma unroll
        for (int j = 0; j < 2; j++) {
            int idx = tid + j * 256;
            int r = idx >> 3, c4 = (idx & 7) << 2;
            float4 v = *reinterpret_cast<const float4*>(
                W + (size_t)(bn0 + r) * 512 + k0 + c4);
            uint32_t h0, l0, h1, l1;
            split_pack(v.x, v.y, h0, l0);
            split_pack(v.z, v.w, h1, l1);
            *reinterpret_cast<uint32_t*>(&Bh[r][c4])     = h0;
            *reinterpret_cast<uint32_t*>(&Bh[r][c4 + 2]) = h1;
            *reinterpret_cast<uint32_t*>(&Bl[r][c4])     = l0;
            *reinterpret_cast<uint32_t*>(&Bl[r][c4 + 2]) = l1;
        }
        __syncthreads();

        #pragma unroll
        for (int kk = 0; kk < 32; kk += 16) {
            uint32_t ah[2][4], al[2][4];
            #pragma unroll
            for (int im = 0; im < 2; im++) {
                int r0 = m0 + im * 16 + g, r1 = r0 + 8;
                int c  = kk + 2 * t4;
                ah[im][0] = *reinterpret_cast<uint32_t*>(&Ah[r0][c]);
                ah[im][1] = *reinterpret_cast<uint32_t*>(&Ah[r1][c]);
                ah[im][2] = *reinterpret_cast<uint32_t*>(&Ah[r0][c + 8]);
                ah[im][3] = *reinterpret_cast<uint32_t*>(&Ah[r1][c + 8]);
                al[im][0] = *reinterpret_cast<uint32_t*>(&Al[r0][c]);
                al[im][1] = *reinterpret_cast<uint32_t*>(&Al[r1][c]);
                al[im][2] = *reinterpret_cast<uint32_t*>(&Al[r0][c + 8]);
                al[im][3] = *reinterpret_cast<uint32_t*>(&Al[r1][c + 8]);
            }
            #pragma unroll
            for (int nf = 0; nf < 4; nf++) {
                int n = n0 + nf * 8 + g;
                int c = kk + 2 * t4;
                uint32_t bh0 = *reinterpret_cast<uint32_t*>(&Bh[n][c]);
                uint32_t bh1 = *reinterpret_cast<uint32_t*>(&Bh[n][c + 8]);
                uint32_t bl0 = *reinterpret_cast<uint32_t*>(&Bl[n][c]);
                uint32_t bl1 = *reinterpret_cast<uint32_t*>(&Bl[n][c + 8]);
                #pragma unroll
                for (int im = 0; im < 2; im++) {
                    mma_bf16(acc[im][nf], ah[im], bh0, bh1);
                    mma_bf16(acc[im][nf], ah[im], bl0, bl1);
                    mma_bf16(acc[im][nf], al[im], bh0, bh1);
                }
            }
        }
        __syncthreads();
    }

    // ---------------- epilogue ----------------
    if (MODE == 0) {
        int which = bn0 >> 9;                 // 0=q 1=k 2=v (tile fits one)
        int h     = (bn0 & 511) >> 6;         // head (constant per block)
        float* dst = (which == 0) ? g_q : (which == 1) ? g_k : g_v;
        float  scl = (which == 0) ? 0.125f : 1.0f;
        #pragma unroll
        for (int im = 0; im < 2; im++) {
            #pragma unroll
            for (int nf = 0; nf < 4; nf++) {
                int d  = n0 + nf * 8 + 2 * t4;       // 0..63
                int m  = bm0 + m0 + im * 16 + g;
                int b  = m >> 11, n = m & 2047;
                float2 v0 = make_float2(acc[im][nf][0] * scl, acc[im][nf][1] * scl);
                float2 v1 = make_float2(acc[im][nf][2] * scl, acc[im][nf][3] * scl);
                *reinterpret_cast<float2*>(&dst[((size_t)((b << 3) + h) * 2048 + n) * 64 + d])       = v0;
                *reinterpret_cast<float2*>(&dst[((size_t)((b << 3) + h) * 2048 + (n + 8)) * 64 + d]) = v1;
            }
        }
    } else {
        #pragma unroll
        for (int im = 0; im < 2; im++) {
            #pragma unroll
            for (int nf = 0; nf < 4; nf++) {
                int col = bn0 + n0 + nf * 8 + 2 * t4;
                float2 bi = *reinterpret_cast<const float2*>(&bias[col]);
                int m = bm0 + m0 + im * 16 + g;
                float2 v0 = make_float2(acc[im][nf][0] + bi.x, acc[im][nf][1] + bi.y);
                float2 v1 = make_float2(acc[im][nf][2] + bi.x, acc[im][nf][3] + bi.y);
                *reinterpret_cast<float2*>(&out[(size_t)m * 512 + col])       = v0;
                *reinterpret_cast<float2*>(&out[(size_t)(m + 8) * 512 + col]) = v1;
            }
        }
    }
}

// ========================= Flash attention (bf16x3 tensor) ================
// grid (32 q-tiles, 64 bh), 256 thr = 8 warps (4m x 2n), Br=Bc=64, Dh=64.
#define DPAD   68
#define TILE_E (64 * DPAD)   // 4352 elems

#define FLASH_SMEM_BYTES (16 * TILE_E /*8 bf16 tiles*/ + 4 * TILE_E /*Ss f32*/ + 4 * (64 * 3))

__global__ void __launch_bounds__(256)
flash_mma()
{
    extern __shared__ char smraw[];
    __nv_bfloat16* Qh  = reinterpret_cast<__nv_bfloat16*>(smraw);
    __nv_bfloat16* Ql  = Qh  + TILE_E;
    __nv_bfloat16* Kh  = Qh  + 2 * TILE_E;
    __nv_bfloat16* Kl  = Qh  + 3 * TILE_E;
    __nv_bfloat16* VtH = Qh  + 4 * TILE_E;   // transposed: [d][j]
    __nv_bfloat16* VtL = Qh  + 5 * TILE_E;
    __nv_bfloat16* Ph  = Qh  + 6 * TILE_E;
    __nv_bfloat16* Pl  = Qh  + 7 * TILE_E;
    float* Ss  = reinterpret_cast<float*>(smraw + 16 * TILE_E);
    float* m_s = Ss + TILE_E;
    float* l_s = m_s + 64;
    float* f_s = l_s + 64;

    int bh = blockIdx.y, qt = blockIdx.x;
    int tid = threadIdx.x;
    int lane = tid & 31, warp = tid >> 5;
    int g = lane >> 2, t4 = lane & 3;
    int wm = warp & 3, wn = warp >> 2;
    int m0 = wm * 16, n0 = wn * 32;

    // load Q (scaled) -> Qh/Ql
    const float* qbase = g_q + ((size_t)bh * 2048 + qt * 64) * 64;
    #pragma unroll
    for (int j = 0; j < 4; j++) {
        int i = tid + j * 256;
        int r = i >> 4, c4 = (i & 15) << 2;
        float4 v = *reinterpret_cast<const float4*>(qbase + r * 64 + c4);
        uint32_t h0, l0, h1, l1;
        split_pack(v.x, v.y, h0, l0);
        split_pack(v.z, v.w, h1, l1);
        *reinterpret_cast<uint32_t*>(&Qh[r * DPAD + c4])     = h0;
        *reinterpret_cast<uint32_t*>(&Qh[r * DPAD + c4 + 2]) = h1;
        *reinterpret_cast<uint32_t*>(&Ql[r * DPAD + c4])     = l0;
        *reinterpret_cast<uint32_t*>(&Ql[r * DPAD + c4 + 2]) = l1;
    }
    if (tid < 64) { m_s[tid] = -1e30f; l_s[tid] = 0.0f; }

    float o[4][4] = {};
    __syncthreads();

    for (int kt = 0; kt < 32; kt++) {
        const float* kb = g_k + ((size_t)bh * 2048 + kt * 64) * 64;
        const float* vb = g_v + ((size_t)bh * 2048 + kt * 64) * 64;
        #pragma unroll
        for (int j = 0; j < 4; j++) {
            int i = tid + j * 256;
            int r = i >> 4, c4 = (i & 15) << 2;
            float4 kv = *reinterpret_cast<const float4*>(kb + r * 64 + c4);
            uint32_t h0, l0, h1, l1;
            split_pack(kv.x, kv.y, h0, l0);
            split_pack(kv.z, kv.w, h1, l1);
            *reinterpret_cast<uint32_t*>(&Kh[r * DPAD + c4])     = h0;
            *reinterpret_cast<uint32_t*>(&Kh[r * DPAD + c4 + 2]) = h1;
            *reinterpret_cast<uint32_t*>(&Kl[r * DPAD + c4])     = l0;
            *reinterpret_cast<uint32_t*>(&Kl[r * DPAD + c4 + 2]) = l1;
            float4 vv = *reinterpret_cast<const float4*>(vb + r * 64 + c4);
            float vf[4] = {vv.x, vv.y, vv.z, vv.w};
            #pragma unroll
            for (int jj = 0; jj < 4; jj++) {
                __nv_bfloat16 hh = __float2bfloat16(vf[jj]);
                VtH[(c4 + jj) * DPAD + r] = hh;
                VtL[(c4 + jj) * DPAD + r] =
                    __float2bfloat16(vf[jj] - __bfloat162float(hh));
            }
        }
        __syncthreads();

        // ---- S = Q K^T ----
        float s[4][4] = {};
        #pragma unroll
        for (int kc = 0; kc < 4; kc++) {
            int c = kc * 16 + 2 * t4;
            int r0 = m0 + g, r1 = r0 + 8;
            uint32_t ah[4], al[4];
            ah[0] = *reinterpret_cast<uint32_t*>(&Qh[r0 * DPAD + c]);
            ah[1] = *reinterpret_cast<uint32_t*>(&Qh[r1 * DPAD + c]);
            ah[2] = *reinterpret_cast<uint32_t*>(&Qh[r0 * DPAD + c + 8]);
            ah[3] = *reinterpret_cast<uint32_t*>(&Qh[r1 * DPAD + c + 8]);
            al[0] = *reinterpret_cast<uint32_t*>(&Ql[r0 * DPAD + c]);
            al[1] = *reinterpret_cast<uint32_t*>(&Ql[r1 * DPAD + c]);
            al[2] = *reinterpret_cast<uint32_t*>(&Ql[r0 * DPAD + c + 8]);
            al[3] = *reinterpret_cast<uint32_t*>(&Ql[r1 * DPAD + c + 8]);
            #pragma unroll
            for (int nf = 0; nf < 4; nf++) {
                int n = n0 + nf * 8 + g;
                uint32_t bh0 = *reinterpret_cast<uint32_t*>(&Kh[n * DPAD + c]);
                uint32_t bh1 = *reinterpret_cast<uint32_t*>(&Kh[n * DPAD + c + 8]);
                uint32_t bl0 = *reinterpret_cast<uint32_t*>(&Kl[n * DPAD + c]);
                uint32_t bl1 = *reinterpret_cast<uint32_t*>(&Kl[n * DPAD + c + 8]);
                mma_bf16(s[nf], ah, bh0, bh1);
                mma_bf16(s[nf], ah, bl0, bl1);
                mma_bf16(s[nf], al, bh0, bh1);
            }
        }
        #pragma unroll
        for (int nf = 0; nf < 4; nf++) {
            int row = m0 + g, col = n0 + nf * 8 + 2 * t4;
            *reinterpret_cast<float2*>(&Ss[row * DPAD + col]) =
                make_float2(s[nf][0], s[nf][1]);
            *reinterpret_cast<float2*>(&Ss[(row + 8) * DPAD + col]) =
                make_float2(s[nf][2], s[nf][3]);
        }
        __syncthreads();

        // ---- online softmax: warp w owns rows [8w, 8w+8) ----
        for (int rr = 0; rr < 8; rr++) {
            int row = warp * 8 + rr;
            float s1 = Ss[row * DPAD + lane];
            float s2 = Ss[row * DPAD + 32 + lane];
            float mx = fmaxf(s1, s2);
            #pragma unroll
            for (int oo = 16; oo; oo >>= 1)
                mx = fmaxf(mx, __shfl_xor_sync(0xffffffffu, mx, oo));
            float m_old = m_s[row];
            float m_new = fmaxf(m_old, mx);
            float p1 = __expf(s1 - m_new);
            float p2 = __expf(s2 - m_new);
            __nv_bfloat16 h1 = __float2bfloat16(p1);
            __nv_bfloat16 h2 = __float2bfloat16(p2);
            Ph[row * DPAD + lane]      = h1;
            Ph[row * DPAD + 32 + lane] = h2;
            Pl[row * DPAD + lane]      = __float2bfloat16(p1 - __bfloat162float(h1));
            Pl[row * DPAD + 32 + lane] = __float2bfloat16(p2 - __bfloat162float(h2));
            float ps = p1 + p2;
            #pragma unroll
            for (int oo = 16; oo; oo >>= 1)
                ps += __shfl_xor_sync(0xffffffffu, ps, oo);
            if (lane == 0) {
                float f = __expf(m_old - m_new);
                f_s[row] = f;
                l_s[row] = l_s[row] * f + ps;
                m_s[row] = m_new;
            }
        }
        __syncthreads();

        // ---- rescale O ----
        float fr0 = f_s[m0 + g], fr1 = f_s[m0 + g + 8];
        #pragma unroll
        for (int nf = 0; nf < 4; nf++) {
            o[nf][0] *= fr0; o[nf][1] *= fr0;
            o[nf][2] *= fr1; o[nf][3] *= fr1;
        }

        // ---- O += P V ----
        #pragma unroll
        for (int kc = 0; kc < 4; kc++) {
            int c = kc * 16 + 2 * t4;
            int r0 = m0 + g, r1 = r0 + 8;
            uint32_t ah[4], al[4];
            ah[0] = *reinterpret_cast<uint32_t*>(&Ph[r0 * DPAD + c]);
            ah[1] = *reinterpret_cast<uint32_t*>(&Ph[r1 * DPAD + c]);
            ah[2] = *reinterpret_cast<uint32_t*>(&Ph[r0 * DPAD + c + 8]);
            ah[3] = *reinterpret_cast<uint32_t*>(&Ph[r1 * DPAD + c + 8]);
            al[0] = *reinterpret_cast<uint32_t*>(&Pl[r0 * DPAD + c]);
            al[1] = *reinterpret_cast<uint32_t*>(&Pl[r1 * DPAD + c]);
            al[2] = *reinterpret_cast<uint32_t*>(&Pl[r0 * DPAD + c + 8]);
            al[3] = *reinterpret_cast<uint32_t*>(&Pl[r1 * DPAD + c + 8]);
            #pragma unroll
            for (int nf = 0; nf < 4; nf++) {
                int n = n0 + nf * 8 + g;   // d column
                uint32_t bh0 = *reinterpret_cast<uint32_t*>(&VtH[n * DPAD + c]);
                uint32_t bh1 = *reinterpret_cast<uint32_t*>(&VtH[n * DPAD + c + 8]);
                uint32_t bl0 = *reinterpret_cast<uint32_t*>(&VtL[n * DPAD + c]);
                uint32_t bl1 = *reinterpret_cast<uint32_t*>(&VtL[n * DPAD + c + 8]);
                mma_bf16(o[nf], ah, bh0, bh1);
                mma_bf16(o[nf], ah, bl0, bl1);
                mma_bf16(o[nf], al, bh0, bh1);
            }
        }
        __syncthreads();
    }

    // ---- epilogue: normalize, write [b][n][h*64+d] ----
    int b = bh >> 3, h = bh & 7;
    #pragma unroll
    for (int nf = 0; nf < 4; nf++) {
        int row0 = m0 + g;
        int n1 = qt * 64 + row0, n2 = n1 + 8;
        int col = h * 64 + n0 + nf * 8 + 2 * t4;
        float inv0 = 1.0f / l_s[row0];
        float inv1 = 1.0f / l_s[row0 + 8];
        *reinterpret_cast<float2*>(&g_att[((size_t)b * 2048 + n1) * 512 + col]) =
            make_float2(o[nf][0] * inv0, o[nf][1] * inv0);
        *reinterpret_cast<float2*>(&g_att[((size_t)b * 2048 + n2) * 512 + col]) =
            make_float2(o[nf][2] * inv1, o[nf][3] * inv1);
    }
}

// ========================= launch =========================================
extern "C" void kernel_launch(void* const* d_in, const int* in_sizes, int n_in,
                              void* d_out, int out_size)
{
    const float* x      = (const float*)d_in[0];
    const float* w_qkv  = (const float*)d_in[1];
    const float* w_proj = (const float*)d_in[2];
    const float* b_proj = (const float*)d_in[3];
    const float* gamma  = (const float*)d_in[4];
    const float* beta   = (const float*)d_in[5];
    float* out = (float*)d_out;

    cudaFuncSetAttribute(flash_mma,
                         cudaFuncAttributeMaxDynamicSharedMemorySize,
                         FLASH_SMEM_BYTES);

    float* g_xn_ptr;
    cudaGetSymbolAddress((void**)&g_xn_ptr, g_xn);
    float* g_att_ptr;
    cudaGetSymbolAddress((void**)&g_att_ptr, g_att);

    ln_kernel<<<ROWS, 128>>>(x, gamma, beta);
    gemm_mma<0><<<dim3(TRIPLE / 64, ROWS / 128), 256>>>(g_xn_ptr, w_qkv, nullptr, nullptr);
    flash_mma<<<dim3(SEQ / 64, BATCH * HEADS), 256, FLASH_SMEM_BYTES>>>();
    gemm_mma<1><<<dim3(DIM / 64, ROWS / 128), 256>>>(g_att_ptr, w_proj, b_proj, out);
}

// round 6
// speedup vs baseline: 2.3513x; 1.5977x over previous
#include <cuda_runtime.h>
#include <cuda_bf16.h>
#include <stdint.h>
#include <math.h>

// Problem constants
#define BATCH   8
#define SEQ     2048
#define DIM     512
#define HEADS   8
#define DHEAD   64
#define ROWS    (BATCH * SEQ)          // 16384
#define TRIPLE  (3 * DIM)              // 1536

// ---------------- scratch (device globals; no runtime allocation) ----------
__device__ float g_xn [ROWS * DIM];    // layernorm output, [row, dim]
__device__ float g_q  [ROWS * DIM];    // [b][h][n][d], pre-scaled by 1/8
__device__ float g_k  [ROWS * DIM];    // [b][h][n][d]
__device__ float g_v  [ROWS * DIM];    // [b][h][n][d]
__device__ float g_att[ROWS * DIM];    // [b][n][h*64+d]

// ---------------- bf16 split helpers --------------------------------------
__device__ __forceinline__ void split_pack(float x, float y,
                                           uint32_t& hi, uint32_t& lo)
{
    __nv_bfloat16 hx = __float2bfloat16(x);
    __nv_bfloat16 hy = __float2bfloat16(y);
    __nv_bfloat16 lx = __float2bfloat16(x - __bfloat162float(hx));
    __nv_bfloat16 ly = __float2bfloat16(y - __bfloat162float(hy));
    __nv_bfloat162 h2; h2.x = hx; h2.y = hy;
    __nv_bfloat162 l2; l2.x = lx; l2.y = ly;
    hi = *reinterpret_cast<uint32_t*>(&h2);
    lo = *reinterpret_cast<uint32_t*>(&l2);
}

__device__ __forceinline__ void mma_bf16(float* c, const uint32_t* a,
                                         uint32_t b0, uint32_t b1)
{
    asm volatile(
        "mma.sync.aligned.m16n8k16.row.col.f32.bf16.bf16.f32 "
        "{%0,%1,%2,%3}, {%4,%5,%6,%7}, {%8,%9}, {%0,%1,%2,%3};\n"
        : "+f"(c[0]), "+f"(c[1]), "+f"(c[2]), "+f"(c[3])
        : "r"(a[0]), "r"(a[1]), "r"(a[2]), "r"(a[3]), "r"(b0), "r"(b1));
}

// ========================= LayerNorm ======================================
__global__ void __launch_bounds__(128)
ln_kernel(const float* __restrict__ x,
          const float* __restrict__ gamma,
          const float* __restrict__ beta)
{
    int row = blockIdx.x;
    int t   = threadIdx.x;
    const float4* xr = reinterpret_cast<const float4*>(x) + (size_t)row * 128;
    float4 v = xr[t];

    __shared__ float red[4];
    float s = v.x + v.y + v.z + v.w;
    #pragma unroll
    for (int o = 16; o; o >>= 1) s += __shfl_xor_sync(0xffffffffu, s, o);
    if ((t & 31) == 0) red[t >> 5] = s;
    __syncthreads();
    float mu = (red[0] + red[1] + red[2] + red[3]) * (1.0f / 512.0f);

    float dx0 = v.x - mu, dx1 = v.y - mu, dx2 = v.z - mu, dx3 = v.w - mu;
    float s2 = dx0*dx0 + dx1*dx1 + dx2*dx2 + dx3*dx3;
    #pragma unroll
    for (int o = 16; o; o >>= 1) s2 += __shfl_xor_sync(0xffffffffu, s2, o);
    __syncthreads();
    if ((t & 31) == 0) red[t >> 5] = s2;
    __syncthreads();
    float var  = (red[0] + red[1] + red[2] + red[3]) * (1.0f / 512.0f);
    float rstd = rsqrtf(var + 1e-6f);

    float4 g  = reinterpret_cast<const float4*>(gamma)[t];
    float4 bb = reinterpret_cast<const float4*>(beta)[t];
    float4 o4;
    o4.x = dx0 * rstd * g.x + bb.x;
    o4.y = dx1 * rstd * g.y + bb.y;
    o4.z = dx2 * rstd * g.z + bb.z;
    o4.w = dx3 * rstd * g.w + bb.w;
    (reinterpret_cast<float4*>(g_xn) + (size_t)row * 128)[t] = o4;
}

// ========================= GEMM (bf16x3 tensor) ===========================
// C[m,c] = sum_k A[m,k] * W[c,k].  Block tile 128m x 64n, k-chunk 32.
// 256 threads = 8 warps (4m x 2n), warp tile 32x32.
// MODE 0: qkv (scatter to g_q/g_k/g_v, scale q), MODE 1: proj (+bias -> out)
#define GSTR 36   // smem k-stride (bf16 elems), padded

template<int MODE>
__global__ void __launch_bounds__(256)
gemm_mma(const float* __restrict__ A, const float* __restrict__ W,
         const float* __restrict__ bias, float* __restrict__ out)
{
    __shared__ __nv_bfloat16 Ah[128][GSTR], Al[128][GSTR];
    __shared__ __nv_bfloat16 Bh[ 64][GSTR], Bl[ 64][GSTR];

    int tid  = threadIdx.x;
    int lane = tid & 31, warp = tid >> 5;
    int g = lane >> 2, t4 = lane & 3;
    int wm = warp & 3, wn = warp >> 2;
    int m0 = wm * 32, n0 = wn * 32;
    int bm0 = blockIdx.y * 128;
    int bn0 = blockIdx.x * 64;

    float acc[2][4][4] = {};

    for (int k0 = 0; k0 < 512; k0 += 32) {
        #pragma unroll
        for (int j = 0; j < 4; j++) {
            int idx = tid + j * 256;
            int r = idx >> 3, c4 = (idx & 7) << 2;
            float4 v = *reinterpret_cast<const float4*>(
                A + (size_t)(bm0 + r) * 512 + k0 + c4);
            uint32_t h0, l0, h1, l1;
            split_pack(v.x, v.y, h0, l0);
            split_pack(v.z, v.w, h1, l1);
            *reinterpret_cast<uint32_t*>(&Ah[r][c4])     = h0;
            *reinterpret_cast<uint32_t*>(&Ah[r][c4 + 2]) = h1;
            *reinterpret_cast<uint32_t*>(&Al[r][c4])     = l0;
            *reinterpret_cast<uint32_t*>(&Al[r][c4 + 2]) = l1;
        }
        #pragma unroll
        for (int j = 0; j < 2; j++) {
            int idx = tid + j * 256;
            int r = idx >> 3, c4 = (idx & 7) << 2;
            float4 v = *reinterpret_cast<const float4*>(
                W + (size_t)(bn0 + r) * 512 + k0 + c4);
            uint32_t h0, l0, h1, l1;
            split_pack(v.x, v.y, h0, l0);
            split_pack(v.z, v.w, h1, l1);
            *reinterpret_cast<uint32_t*>(&Bh[r][c4])     = h0;
            *reinterpret_cast<uint32_t*>(&Bh[r][c4 + 2]) = h1;
            *reinterpret_cast<uint32_t*>(&Bl[r][c4])     = l0;
            *reinterpret_cast<uint32_t*>(&Bl[r][c4 + 2]) = l1;
        }
        __syncthreads();

        #pragma unroll
        for (int kk = 0; kk < 32; kk += 16) {
            uint32_t ah[2][4], al[2][4];
            #pragma unroll
            for (int im = 0; im < 2; im++) {
                int r0 = m0 + im * 16 + g, r1 = r0 + 8;
                int c  = kk + 2 * t4;
                ah[im][0] = *reinterpret_cast<uint32_t*>(&Ah[r0][c]);
                ah[im][1] = *reinterpret_cast<uint32_t*>(&Ah[r1][c]);
                ah[im][2] = *reinterpret_cast<uint32_t*>(&Ah[r0][c + 8]);
                ah[im][3] = *reinterpret_cast<uint32_t*>(&Ah[r1][c + 8]);
                al[im][0] = *reinterpret_cast<uint32_t*>(&Al[r0][c]);
                al[im][1] = *reinterpret_cast<uint32_t*>(&Al[r1][c]);
                al[im][2] = *reinterpret_cast<uint32_t*>(&Al[r0][c + 8]);
                al[im][3] = *reinterpret_cast<uint32_t*>(&Al[r1][c + 8]);
            }
            #pragma unroll
            for (int nf = 0; nf < 4; nf++) {
                int n = n0 + nf * 8 + g;
                int c = kk + 2 * t4;
                uint32_t bh0 = *reinterpret_cast<uint32_t*>(&Bh[n][c]);
                uint32_t bh1 = *reinterpret_cast<uint32_t*>(&Bh[n][c + 8]);
                uint32_t bl0 = *reinterpret_cast<uint32_t*>(&Bl[n][c]);
                uint32_t bl1 = *reinterpret_cast<uint32_t*>(&Bl[n][c + 8]);
                #pragma unroll
                for (int im = 0; im < 2; im++) {
                    mma_bf16(acc[im][nf], ah[im], bh0, bh1);
                    mma_bf16(acc[im][nf], ah[im], bl0, bl1);
                    mma_bf16(acc[im][nf], al[im], bh0, bh1);
                }
            }
        }
        __syncthreads();
    }

    if (MODE == 0) {
        int which = bn0 >> 9;
        int h     = (bn0 & 511) >> 6;
        float* dst = (which == 0) ? g_q : (which == 1) ? g_k : g_v;
        float  scl = (which == 0) ? 0.125f : 1.0f;
        #pragma unroll
        for (int im = 0; im < 2; im++) {
            #pragma unroll
            for (int nf = 0; nf < 4; nf++) {
                int d  = n0 + nf * 8 + 2 * t4;
                int m  = bm0 + m0 + im * 16 + g;
                int b  = m >> 11, n = m & 2047;
                float2 v0 = make_float2(acc[im][nf][0] * scl, acc[im][nf][1] * scl);
                float2 v1 = make_float2(acc[im][nf][2] * scl, acc[im][nf][3] * scl);
                *reinterpret_cast<float2*>(&dst[((size_t)((b << 3) + h) * 2048 + n) * 64 + d])       = v0;
                *reinterpret_cast<float2*>(&dst[((size_t)((b << 3) + h) * 2048 + (n + 8)) * 64 + d]) = v1;
            }
        }
    } else {
        #pragma unroll
        for (int im = 0; im < 2; im++) {
            #pragma unroll
            for (int nf = 0; nf < 4; nf++) {
                int col = bn0 + n0 + nf * 8 + 2 * t4;
                float2 bi = *reinterpret_cast<const float2*>(&bias[col]);
                int m = bm0 + m0 + im * 16 + g;
                float2 v0 = make_float2(acc[im][nf][0] + bi.x, acc[im][nf][1] + bi.y);
                float2 v1 = make_float2(acc[im][nf][2] + bi.x, acc[im][nf][3] + bi.y);
                *reinterpret_cast<float2*>(&out[(size_t)m * 512 + col])       = v0;
                *reinterpret_cast<float2*>(&out[(size_t)(m + 8) * 512 + col]) = v1;
            }
        }
    }
}

// ========================= Flash attention (register-resident, bf16x3) ====
// grid (32 q-tiles, 64 bh), 128 thr = 4 warps; warp w owns q rows [16w,16w+16).
// Br=64, Bc=64, Dh=64.  S and P live in registers; softmax via quad shfl.
#define DPAD   68
#define TILE_E (64 * DPAD)                     // 4352 bf16 elems per tile
#define FLASH_SMEM_BYTES (6 * TILE_E * 2)      // Qh,Ql,Kh,Kl,VtH,VtL

__global__ void __launch_bounds__(128)
flash_mma()
{
    extern __shared__ __nv_bfloat16 smb[];
    __nv_bfloat16* Qh  = smb;
    __nv_bfloat16* Ql  = smb + TILE_E;
    __nv_bfloat16* Kh  = smb + 2 * TILE_E;
    __nv_bfloat16* Kl  = smb + 3 * TILE_E;
    __nv_bfloat16* VtH = smb + 4 * TILE_E;     // transposed: [d][j]
    __nv_bfloat16* VtL = smb + 5 * TILE_E;

    int bh = blockIdx.y, qt = blockIdx.x;
    int tid  = threadIdx.x;
    int lane = tid & 31, warp = tid >> 5;
    int g = lane >> 2, t4 = lane & 3;

    // ---- stage Q (pre-scaled) into smem, split h/l ----
    const float* qbase = g_q + ((size_t)bh * 2048 + qt * 64) * 64;
    #pragma unroll
    for (int j = 0; j < 8; j++) {
        int i = tid + j * 128;                 // 1024 float4 total
        int r = i >> 4, c4 = (i & 15) << 2;
        float4 v = *reinterpret_cast<const float4*>(qbase + r * 64 + c4);
        uint32_t h0, l0, h1, l1;
        split_pack(v.x, v.y, h0, l0);
        split_pack(v.z, v.w, h1, l1);
        *reinterpret_cast<uint32_t*>(&Qh[r * DPAD + c4])     = h0;
        *reinterpret_cast<uint32_t*>(&Qh[r * DPAD + c4 + 2]) = h1;
        *reinterpret_cast<uint32_t*>(&Ql[r * DPAD + c4])     = l0;
        *reinterpret_cast<uint32_t*>(&Ql[r * DPAD + c4 + 2]) = l1;
    }
    __syncthreads();

    // ---- load Q fragments into registers (once) ----
    uint32_t qh[4][4], ql[4][4];
    {
        int r0 = warp * 16 + g, r1 = r0 + 8;
        #pragma unroll
        for (int kc = 0; kc < 4; kc++) {
            int c = kc * 16 + 2 * t4;
            qh[kc][0] = *reinterpret_cast<uint32_t*>(&Qh[r0 * DPAD + c]);
            qh[kc][1] = *reinterpret_cast<uint32_t*>(&Qh[r1 * DPAD + c]);
            qh[kc][2] = *reinterpret_cast<uint32_t*>(&Qh[r0 * DPAD + c + 8]);
            qh[kc][3] = *reinterpret_cast<uint32_t*>(&Qh[r1 * DPAD + c + 8]);
            ql[kc][0] = *reinterpret_cast<uint32_t*>(&Ql[r0 * DPAD + c]);
            ql[kc][1] = *reinterpret_cast<uint32_t*>(&Ql[r1 * DPAD + c]);
            ql[kc][2] = *reinterpret_cast<uint32_t*>(&Ql[r0 * DPAD + c + 8]);
            ql[kc][3] = *reinterpret_cast<uint32_t*>(&Ql[r1 * DPAD + c + 8]);
        }
    }

    float o[8][4] = {};
    float m0 = -1e30f, m1 = -1e30f, l0 = 0.0f, l1 = 0.0f;
    __syncthreads();   // Q frags read before K/V reuse nothing, but keep order

    for (int kt = 0; kt < 32; kt++) {
        const float* kb = g_k + ((size_t)bh * 2048 + kt * 64) * 64;
        const float* vb = g_v + ((size_t)bh * 2048 + kt * 64) * 64;
        #pragma unroll
        for (int j = 0; j < 8; j++) {
            int i = tid + j * 128;
            int r = i >> 4, c4 = (i & 15) << 2;
            float4 kv = *reinterpret_cast<const float4*>(kb + r * 64 + c4);
            uint32_t h0, l0u, h1, l1u;
            split_pack(kv.x, kv.y, h0, l0u);
            split_pack(kv.z, kv.w, h1, l1u);
            *reinterpret_cast<uint32_t*>(&Kh[r * DPAD + c4])     = h0;
            *reinterpret_cast<uint32_t*>(&Kh[r * DPAD + c4 + 2]) = h1;
            *reinterpret_cast<uint32_t*>(&Kl[r * DPAD + c4])     = l0u;
            *reinterpret_cast<uint32_t*>(&Kl[r * DPAD + c4 + 2]) = l1u;
            float4 vv = *reinterpret_cast<const float4*>(vb + r * 64 + c4);
            float vf[4] = {vv.x, vv.y, vv.z, vv.w};
            #pragma unroll
            for (int jj = 0; jj < 4; jj++) {
                __nv_bfloat16 hh = __float2bfloat16(vf[jj]);
                VtH[(c4 + jj) * DPAD + r] = hh;
                VtL[(c4 + jj) * DPAD + r] =
                    __float2bfloat16(vf[jj] - __bfloat162float(hh));
            }
        }
        __syncthreads();

        // ---- S = Q K^T (registers) ----
        float s[8][4] = {};
        #pragma unroll
        for (int kc = 0; kc < 4; kc++) {
            int c = kc * 16 + 2 * t4;
            #pragma unroll
            for (int nf = 0; nf < 8; nf++) {
                int n = nf * 8 + g;
                uint32_t bh0 = *reinterpret_cast<uint32_t*>(&Kh[n * DPAD + c]);
                uint32_t bh1 = *reinterpret_cast<uint32_t*>(&Kh[n * DPAD + c + 8]);
                uint32_t bl0 = *reinterpret_cast<uint32_t*>(&Kl[n * DPAD + c]);
                uint32_t bl1 = *reinterpret_cast<uint32_t*>(&Kl[n * DPAD + c + 8]);
                mma_bf16(s[nf], qh[kc], bh0, bh1);
                mma_bf16(s[nf], qh[kc], bl0, bl1);
                mma_bf16(s[nf], ql[kc], bh0, bh1);
            }
        }

        // ---- online softmax in registers ----
        float mx0 = -1e30f, mx1 = -1e30f;
        #pragma unroll
        for (int nf = 0; nf < 8; nf++) {
            mx0 = fmaxf(mx0, fmaxf(s[nf][0], s[nf][1]));
            mx1 = fmaxf(mx1, fmaxf(s[nf][2], s[nf][3]));
        }
        mx0 = fmaxf(mx0, __shfl_xor_sync(0xffffffffu, mx0, 1));
        mx0 = fmaxf(mx0, __shfl_xor_sync(0xffffffffu, mx0, 2));
        mx1 = fmaxf(mx1, __shfl_xor_sync(0xffffffffu, mx1, 1));
        mx1 = fmaxf(mx1, __shfl_xor_sync(0xffffffffu, mx1, 2));
        float mn0 = fmaxf(m0, mx0);
        float mn1 = fmaxf(m1, mx1);

        float sum0 = 0.0f, sum1 = 0.0f;
        #pragma unroll
        for (int nf = 0; nf < 8; nf++) {
            s[nf][0] = __expf(s[nf][0] - mn0);
            s[nf][1] = __expf(s[nf][1] - mn0);
            s[nf][2] = __expf(s[nf][2] - mn1);
            s[nf][3] = __expf(s[nf][3] - mn1);
            sum0 += s[nf][0] + s[nf][1];
            sum1 += s[nf][2] + s[nf][3];
        }
        sum0 += __shfl_xor_sync(0xffffffffu, sum0, 1);
        sum0 += __shfl_xor_sync(0xffffffffu, sum0, 2);
        sum1 += __shfl_xor_sync(0xffffffffu, sum1, 1);
        sum1 += __shfl_xor_sync(0xffffffffu, sum1, 2);

        float sc0 = __expf(m0 - mn0);
        float sc1 = __expf(m1 - mn1);
        m0 = mn0; m1 = mn1;
        l0 = l0 * sc0 + sum0;
        l1 = l1 * sc1 + sum1;
        #pragma unroll
        for (int nf = 0; nf < 8; nf++) {
            o[nf][0] *= sc0; o[nf][1] *= sc0;
            o[nf][2] *= sc1; o[nf][3] *= sc1;
        }

        // ---- O += P V  (P repacked in registers from S) ----
        #pragma unroll
        for (int kc = 0; kc < 4; kc++) {
            uint32_t ph[4], pl[4];
            split_pack(s[2*kc][0],     s[2*kc][1],     ph[0], pl[0]);
            split_pack(s[2*kc][2],     s[2*kc][3],     ph[1], pl[1]);
            split_pack(s[2*kc + 1][0], s[2*kc + 1][1], ph[2], pl[2]);
            split_pack(s[2*kc + 1][2], s[2*kc + 1][3], ph[3], pl[3]);
            int c = kc * 16 + 2 * t4;
            #pragma unroll
            for (int nf = 0; nf < 8; nf++) {
                int n = nf * 8 + g;   // d column
                uint32_t bh0 = *reinterpret_cast<uint32_t*>(&VtH[n * DPAD + c]);
                uint32_t bh1 = *reinterpret_cast<uint32_t*>(&VtH[n * DPAD + c + 8]);
                uint32_t bl0 = *reinterpret_cast<uint32_t*>(&VtL[n * DPAD + c]);
                uint32_t bl1 = *reinterpret_cast<uint32_t*>(&VtL[n * DPAD + c + 8]);
                mma_bf16(o[nf], ph, bh0, bh1);
                mma_bf16(o[nf], ph, bl0, bl1);
                mma_bf16(o[nf], pl, bh0, bh1);
            }
        }
        __syncthreads();
    }

    // ---- epilogue: normalize, write [b][n][h*64+d] ----
    int b = bh >> 3, h = bh & 7;
    float inv0 = 1.0f / l0;
    float inv1 = 1.0f / l1;
    int r0 = qt * 64 + warp * 16 + g;
    int r1 = r0 + 8;
    #pragma unroll
    for (int nf = 0; nf < 8; nf++) {
        int col = h * 64 + nf * 8 + 2 * t4;
        *reinterpret_cast<float2*>(&g_att[((size_t)b * 2048 + r0) * 512 + col]) =
            make_float2(o[nf][0] * inv0, o[nf][1] * inv0);
        *reinterpret_cast<float2*>(&g_att[((size_t)b * 2048 + r1) * 512 + col]) =
            make_float2(o[nf][2] * inv1, o[nf][3] * inv1);
    }
}

// ========================= launch =========================================
extern "C" void kernel_launch(void* const* d_in, const int* in_sizes, int n_in,
                              void* d_out, int out_size)
{
    const float* x      = (const float*)d_in[0];
    const float* w_qkv  = (const float*)d_in[1];
    const float* w_proj = (const float*)d_in[2];
    const float* b_proj = (const float*)d_in[3];
    const float* gamma  = (const float*)d_in[4];
    const float* beta   = (const float*)d_in[5];
    float* out = (float*)d_out;

    cudaFuncSetAttribute(flash_mma,
                         cudaFuncAttributeMaxDynamicSharedMemorySize,
                         FLASH_SMEM_BYTES);

    float* g_xn_ptr;
    cudaGetSymbolAddress((void**)&g_xn_ptr, g_xn);
    float* g_att_ptr;
    cudaGetSymbolAddress((void**)&g_att_ptr, g_att);

    ln_kernel<<<ROWS, 128>>>(x, gamma, beta);
    gemm_mma<0><<<dim3(TRIPLE / 64, ROWS / 128), 256>>>(g_xn_ptr, w_qkv, nullptr, nullptr);
    flash_mma<<<dim3(SEQ / 64, BATCH * HEADS), 256 / 2, FLASH_SMEM_BYTES>>>();
    gemm_mma<1><<<dim3(DIM / 64, ROWS / 128), 256>>>(g_att_ptr, w_proj, b_proj, out);
}

// round 10
// speedup vs baseline: 3.0573x; 1.3003x over previous
#include <cuda_runtime.h>
#include <cuda_bf16.h>
#include <stdint.h>
#include <math.h>

// Problem constants
#define BATCH   8
#define SEQ     2048
#define DIM     512
#define HEADS   8
#define ROWS    (BATCH * SEQ)          // 16384
#define TRIPLE  (3 * DIM)              // 1536
#define SSTR    72                     // smem row stride in bf16 (144B)

// ---------------- scratch (device globals; no runtime allocation) ----------
// all bf16 hi/lo split pairs
__device__ __nv_bfloat16 g_xh [ROWS * DIM], g_xl [ROWS * DIM];   // LN out [row][512]
__device__ __nv_bfloat16 g_wqh[TRIPLE * DIM], g_wql[TRIPLE * DIM];
__device__ __nv_bfloat16 g_wph[DIM * DIM],    g_wpl[DIM * DIM];
__device__ __nv_bfloat16 g_qh [ROWS * DIM], g_ql [ROWS * DIM];   // [bh][n][64], q pre-scaled
__device__ __nv_bfloat16 g_kh [ROWS * DIM], g_kl [ROWS * DIM];   // [bh][n][64]
__device__ __nv_bfloat16 g_vh [ROWS * DIM], g_vl [ROWS * DIM];   // [bh][n][64] (NOT transposed)
__device__ __nv_bfloat16 g_ah [ROWS * DIM], g_al [ROWS * DIM];   // attn out [b][n][512]

// ---------------- helpers ---------------------------------------------------
__device__ __forceinline__ void split_pack(float x, float y,
                                           uint32_t& hi, uint32_t& lo)
{
    __nv_bfloat16 hx = __float2bfloat16(x);
    __nv_bfloat16 hy = __float2bfloat16(y);
    __nv_bfloat16 lx = __float2bfloat16(x - __bfloat162float(hx));
    __nv_bfloat16 ly = __float2bfloat16(y - __bfloat162float(hy));
    __nv_bfloat162 h2; h2.x = hx; h2.y = hy;
    __nv_bfloat162 l2; l2.x = lx; l2.y = ly;
    hi = *reinterpret_cast<uint32_t*>(&h2);
    lo = *reinterpret_cast<uint32_t*>(&l2);
}

__device__ __forceinline__ void mma_bf16(float* c, const uint32_t* a,
                                         uint32_t b0, uint32_t b1)
{
    asm volatile(
        "mma.sync.aligned.m16n8k16.row.col.f32.bf16.bf16.f32 "
        "{%0,%1,%2,%3}, {%4,%5,%6,%7}, {%8,%9}, {%0,%1,%2,%3};\n"
        : "+f"(c[0]), "+f"(c[1]), "+f"(c[2]), "+f"(c[3])
        : "r"(a[0]), "r"(a[1]), "r"(a[2]), "r"(a[3]), "r"(b0), "r"(b1));
}

__device__ __forceinline__ uint32_t sptr(const void* p)
{
    return (uint32_t)__cvta_generic_to_shared(p);
}

__device__ __forceinline__ void ldsm_x4(uint32_t* r, uint32_t addr)
{
    asm volatile(
        "ldmatrix.sync.aligned.m8n8.x4.shared.b16 {%0,%1,%2,%3}, [%4];\n"
        : "=r"(r[0]), "=r"(r[1]), "=r"(r[2]), "=r"(r[3]) : "r"(addr));
}

__device__ __forceinline__ void ldsm_x4_t(uint32_t* r, uint32_t addr)
{
    asm volatile(
        "ldmatrix.sync.aligned.m8n8.x4.trans.shared.b16 {%0,%1,%2,%3}, [%4];\n"
        : "=r"(r[0]), "=r"(r[1]), "=r"(r[2]), "=r"(r[3]) : "r"(addr));
}

// ========================= weight split (one-off) =========================
__global__ void __launch_bounds__(256)
prep_split(const float* __restrict__ wq, const float* __restrict__ wp)
{
    const int NQ = TRIPLE * DIM / 2;        // 393216 pairs
    const int NP = DIM * DIM / 2;           // 131072 pairs
    int idx = blockIdx.x * 256 + threadIdx.x;
    if (idx < NQ) {
        float2 v = reinterpret_cast<const float2*>(wq)[idx];
        uint32_t h, l; split_pack(v.x, v.y, h, l);
        reinterpret_cast<uint32_t*>(g_wqh)[idx] = h;
        reinterpret_cast<uint32_t*>(g_wql)[idx] = l;
    } else if (idx < NQ + NP) {
        int j = idx - NQ;
        float2 v = reinterpret_cast<const float2*>(wp)[j];
        uint32_t h, l; split_pack(v.x, v.y, h, l);
        reinterpret_cast<uint32_t*>(g_wph)[j] = h;
        reinterpret_cast<uint32_t*>(g_wpl)[j] = l;
    }
}

// ========================= LayerNorm (writes split bf16) ==================
__global__ void __launch_bounds__(128)
ln_kernel(const float* __restrict__ x,
          const float* __restrict__ gamma,
          const float* __restrict__ beta)
{
    int row = blockIdx.x;
    int t   = threadIdx.x;
    const float4* xr = reinterpret_cast<const float4*>(x) + (size_t)row * 128;
    float4 v = xr[t];

    __shared__ float red[4];
    float s = v.x + v.y + v.z + v.w;
    #pragma unroll
    for (int o = 16; o; o >>= 1) s += __shfl_xor_sync(0xffffffffu, s, o);
    if ((t & 31) == 0) red[t >> 5] = s;
    __syncthreads();
    float mu = (red[0] + red[1] + red[2] + red[3]) * (1.0f / 512.0f);

    float dx0 = v.x - mu, dx1 = v.y - mu, dx2 = v.z - mu, dx3 = v.w - mu;
    float s2 = dx0*dx0 + dx1*dx1 + dx2*dx2 + dx3*dx3;
    #pragma unroll
    for (int o = 16; o; o >>= 1) s2 += __shfl_xor_sync(0xffffffffu, s2, o);
    __syncthreads();
    if ((t & 31) == 0) red[t >> 5] = s2;
    __syncthreads();
    float var  = (red[0] + red[1] + red[2] + red[3]) * (1.0f / 512.0f);
    float rstd = rsqrtf(var + 1e-6f);

    float4 g  = reinterpret_cast<const float4*>(gamma)[t];
    float4 bb = reinterpret_cast<const float4*>(beta)[t];
    float o0 = dx0 * rstd * g.x + bb.x;
    float o1 = dx1 * rstd * g.y + bb.y;
    float o2 = dx2 * rstd * g.z + bb.z;
    float o3 = dx3 * rstd * g.w + bb.w;
    uint32_t h0, l0, h1, l1;
    split_pack(o0, o1, h0, l0);
    split_pack(o2, o3, h1, l1);
    uint2 hh = make_uint2(h0, h1);
    uint2 ll = make_uint2(l0, l1);
    *reinterpret_cast<uint2*>(&g_xh[(size_t)row * 512 + t * 4]) = hh;
    *reinterpret_cast<uint2*>(&g_xl[(size_t)row * 512 + t * 4]) = ll;
}

// ========================= GEMM (bf16x3, ldmatrix) ========================
// C[m,c] = sum_k A[m,k] * W[c,k].  Block 128m x 64n, k-chunk 64.
// 256 thr = 8 warps (4m x 2n), warp tile 32x32.
// MODE 0: qkv -> split bf16 q/k/v scatter; MODE 1: proj -> f32 out + bias.
#define GEMM_SMEM ((128 * 2 + 64 * 2) * SSTR * 2)   // 55296 bytes

template<int MODE>
__global__ void __launch_bounds__(256)
gemm_mma(const float* __restrict__ bias, float* __restrict__ out)
{
    extern __shared__ __nv_bfloat16 sm[];
    __nv_bfloat16* As_h = sm;
    __nv_bfloat16* As_l = sm + 128 * SSTR;
    __nv_bfloat16* Bs_h = sm + 256 * SSTR;
    __nv_bfloat16* Bs_l = sm + 320 * SSTR;

    const __nv_bfloat16* Ah_g = (MODE == 0) ? g_xh : g_ah;
    const __nv_bfloat16* Al_g = (MODE == 0) ? g_xl : g_al;
    const __nv_bfloat16* Wh_g = (MODE == 0) ? g_wqh : g_wph;
    const __nv_bfloat16* Wl_g = (MODE == 0) ? g_wql : g_wpl;

    int tid = threadIdx.x, lane = tid & 31, warp = tid >> 5;
    int g = lane >> 2, t4 = lane & 3;
    int wm = warp & 3, wn = warp >> 2;
    int m0 = wm * 32, n0 = wn * 32;
    int bm0 = blockIdx.y * 128, bn0 = blockIdx.x * 64;
    int qS = tid & 7;

    float acc[2][4][4] = {};

    for (int k0 = 0; k0 < 512; k0 += 64) {
        #pragma unroll
        for (int j = 0; j < 4; j++) {
            int r = (tid + j * 256) >> 3;
            *reinterpret_cast<uint4*>(&As_h[r * SSTR + qS * 8]) =
                *reinterpret_cast<const uint4*>(Ah_g + (size_t)(bm0 + r) * 512 + k0 + qS * 8);
            *reinterpret_cast<uint4*>(&As_l[r * SSTR + qS * 8]) =
                *reinterpret_cast<const uint4*>(Al_g + (size_t)(bm0 + r) * 512 + k0 + qS * 8);
        }
        #pragma unroll
        for (int j = 0; j < 2; j++) {
            int r = (tid + j * 256) >> 3;
            *reinterpret_cast<uint4*>(&Bs_h[r * SSTR + qS * 8]) =
                *reinterpret_cast<const uint4*>(Wh_g + (size_t)(bn0 + r) * 512 + k0 + qS * 8);
            *reinterpret_cast<uint4*>(&Bs_l[r * SSTR + qS * 8]) =
                *reinterpret_cast<const uint4*>(Wl_g + (size_t)(bn0 + r) * 512 + k0 + qS * 8);
        }
        __syncthreads();

        #pragma unroll
        for (int kcp = 0; kcp < 2; kcp++) {
            uint32_t ah[2][2][4], al[2][2][4];   // [kk][im][4]
            #pragma unroll
            for (int kk = 0; kk < 2; kk++)
                #pragma unroll
                for (int im = 0; im < 2; im++) {
                    int row = m0 + im * 16 + (lane & 15);
                    int col = kcp * 32 + kk * 16 + (lane >> 4) * 8;
                    ldsm_x4(ah[kk][im], sptr(&As_h[row * SSTR + col]));
                    ldsm_x4(al[kk][im], sptr(&As_l[row * SSTR + col]));
                }
            #pragma unroll
            for (int nf = 0; nf < 4; nf++) {
                uint32_t b4h[4], b4l[4];
                int rowb = n0 + nf * 8 + (lane & 7);
                int colb = kcp * 32 + (lane >> 3) * 8;
                ldsm_x4(b4h, sptr(&Bs_h[rowb * SSTR + colb]));
                ldsm_x4(b4l, sptr(&Bs_l[rowb * SSTR + colb]));
                #pragma unroll
                for (int kk = 0; kk < 2; kk++)
                    #pragma unroll
                    for (int im = 0; im < 2; im++) {
                        mma_bf16(acc[im][nf], ah[kk][im], b4h[2*kk], b4h[2*kk+1]);
                        mma_bf16(acc[im][nf], ah[kk][im], b4l[2*kk], b4l[2*kk+1]);
                        mma_bf16(acc[im][nf], al[kk][im], b4h[2*kk], b4h[2*kk+1]);
                    }
            }
        }
        __syncthreads();
    }

    if (MODE == 0) {
        int which = bn0 >> 9;                 // 0=q 1=k 2=v
        int h     = (bn0 & 511) >> 6;         // head (constant per block)
        __nv_bfloat16* dh = (which == 0) ? g_qh : (which == 1) ? g_kh : g_vh;
        __nv_bfloat16* dl = (which == 0) ? g_ql : (which == 1) ? g_kl : g_vl;
        float scl = (which == 0) ? 0.125f : 1.0f;
        #pragma unroll
        for (int im = 0; im < 2; im++) {
            #pragma unroll
            for (int nf = 0; nf < 4; nf++) {
                int d = n0 + nf * 8 + 2 * t4;
                int m = bm0 + m0 + im * 16 + g;
                int b = m >> 11, n = m & 2047;
                size_t off = ((size_t)((b << 3) + h) * 2048 + n) * 64 + d;
                uint32_t h0, l0;
                split_pack(acc[im][nf][0] * scl, acc[im][nf][1] * scl, h0, l0);
                *reinterpret_cast<uint32_t*>(&dh[off]) = h0;
                *reinterpret_cast<uint32_t*>(&dl[off]) = l0;
                split_pack(acc[im][nf][2] * scl, acc[im][nf][3] * scl, h0, l0);
                *reinterpret_cast<uint32_t*>(&dh[off + 8 * 64]) = h0;
                *reinterpret_cast<uint32_t*>(&dl[off + 8 * 64]) = l0;
            }
        }
    } else {
        #pragma unroll
        for (int im = 0; im < 2; im++) {
            #pragma unroll
            for (int nf = 0; nf < 4; nf++) {
                int col = bn0 + n0 + nf * 8 + 2 * t4;
                float2 bi = *reinterpret_cast<const float2*>(&bias[col]);
                int m = bm0 + m0 + im * 16 + g;
                float2 v0 = make_float2(acc[im][nf][0] + bi.x, acc[im][nf][1] + bi.y);
                float2 v1 = make_float2(acc[im][nf][2] + bi.x, acc[im][nf][3] + bi.y);
                *reinterpret_cast<float2*>(&out[(size_t)m * 512 + col])       = v0;
                *reinterpret_cast<float2*>(&out[(size_t)(m + 8) * 512 + col]) = v1;
            }
        }
    }
}

// ========================= Flash attention (ldmatrix, bf16x3) =============
// grid (32 q-tiles, 64 bh), 128 thr = 4 warps; warp w owns q rows [16w,16w+16).
#define FSM (64 * SSTR)
#define FLASH_SMEM_BYTES (6 * FSM * 2)   // Qh,Ql,Kh,Kl,Vh,Vl = 55296

__global__ void __launch_bounds__(128)
flash_mma()
{
    extern __shared__ __nv_bfloat16 sm[];
    __nv_bfloat16* Qhs = sm;
    __nv_bfloat16* Qls = sm + FSM;
    __nv_bfloat16* Khs = sm + 2 * FSM;
    __nv_bfloat16* Kls = sm + 3 * FSM;
    __nv_bfloat16* Vhs = sm + 4 * FSM;
    __nv_bfloat16* Vls = sm + 5 * FSM;

    int bh = blockIdx.y, qt = blockIdx.x;
    int tid = threadIdx.x, lane = tid & 31, warp = tid >> 5;
    int g = lane >> 2, t4 = lane & 3;
    int qS = tid & 7;

    size_t qoff = ((size_t)bh * 2048 + qt * 64) * 64;
    #pragma unroll
    for (int j = 0; j < 4; j++) {
        int r = (tid + j * 128) >> 3;
        *reinterpret_cast<uint4*>(&Qhs[r * SSTR + qS * 8]) =
            *reinterpret_cast<const uint4*>(g_qh + qoff + (size_t)r * 64 + qS * 8);
        *reinterpret_cast<uint4*>(&Qls[r * SSTR + qS * 8]) =
            *reinterpret_cast<const uint4*>(g_ql + qoff + (size_t)r * 64 + qS * 8);
    }
    __syncthreads();

    uint32_t qh[4][4], ql[4][4];
    #pragma unroll
    for (int kc = 0; kc < 4; kc++) {
        int row = warp * 16 + (lane & 15);
        int col = kc * 16 + (lane >> 4) * 8;
        ldsm_x4(qh[kc], sptr(&Qhs[row * SSTR + col]));
        ldsm_x4(ql[kc], sptr(&Qls[row * SSTR + col]));
    }

    float o[8][4] = {};
    float rm0 = -1e30f, rm1 = -1e30f, rl0 = 0.0f, rl1 = 0.0f;

    for (int kt = 0; kt < 32; kt++) {
        size_t koff = ((size_t)bh * 2048 + kt * 64) * 64;
        #pragma unroll
        for (int j = 0; j < 4; j++) {
            int r = (tid + j * 128) >> 3;
            size_t go = koff + (size_t)r * 64 + qS * 8;
            int so = r * SSTR + qS * 8;
            *reinterpret_cast<uint4*>(&Khs[so]) = *reinterpret_cast<const uint4*>(g_kh + go);
            *reinterpret_cast<uint4*>(&Kls[so]) = *reinterpret_cast<const uint4*>(g_kl + go);
            *reinterpret_cast<uint4*>(&Vhs[so]) = *reinterpret_cast<const uint4*>(g_vh + go);
            *reinterpret_cast<uint4*>(&Vls[so]) = *reinterpret_cast<const uint4*>(g_vl + go);
        }
        __syncthreads();

        // ---- S = Q K^T ----
        float s[8][4] = {};
        #pragma unroll
        for (int nf = 0; nf < 8; nf++) {
            int rowb = nf * 8 + (lane & 7);
            #pragma unroll
            for (int kcp = 0; kcp < 2; kcp++) {
                int colb = kcp * 32 + (lane >> 3) * 8;
                uint32_t b4h[4], b4l[4];
                ldsm_x4(b4h, sptr(&Khs[rowb * SSTR + colb]));
                ldsm_x4(b4l, sptr(&Kls[rowb * SSTR + colb]));
                #pragma unroll
                for (int kk = 0; kk < 2; kk++) {
                    int kc = kcp * 2 + kk;
                    mma_bf16(s[nf], qh[kc], b4h[2*kk], b4h[2*kk+1]);
                    mma_bf16(s[nf], qh[kc], b4l[2*kk], b4l[2*kk+1]);
                    mma_bf16(s[nf], ql[kc], b4h[2*kk], b4h[2*kk+1]);
                }
            }
        }

        // ---- online softmax (registers; quad reductions) ----
        float mx0 = -1e30f, mx1 = -1e30f;
        #pragma unroll
        for (int nf = 0; nf < 8; nf++) {
            mx0 = fmaxf(mx0, fmaxf(s[nf][0], s[nf][1]));
            mx1 = fmaxf(mx1, fmaxf(s[nf][2], s[nf][3]));
        }
        mx0 = fmaxf(mx0, __shfl_xor_sync(0xffffffffu, mx0, 1));
        mx0 = fmaxf(mx0, __shfl_xor_sync(0xffffffffu, mx0, 2));
        mx1 = fmaxf(mx1, __shfl_xor_sync(0xffffffffu, mx1, 1));
        mx1 = fmaxf(mx1, __shfl_xor_sync(0xffffffffu, mx1, 2));
        float mn0 = fmaxf(rm0, mx0);
        float mn1 = fmaxf(rm1, mx1);

        float sum0 = 0.0f, sum1 = 0.0f;
        #pragma unroll
        for (int nf = 0; nf < 8; nf++) {
            s[nf][0] = __expf(s[nf][0] - mn0);
            s[nf][1] = __expf(s[nf][1] - mn0);
            s[nf][2] = __expf(s[nf][2] - mn1);
            s[nf][3] = __expf(s[nf][3] - mn1);
            sum0 += s[nf][0] + s[nf][1];
            sum1 += s[nf][2] + s[nf][3];
        }
        sum0 += __shfl_xor_sync(0xffffffffu, sum0, 1);
        sum0 += __shfl_xor_sync(0xffffffffu, sum0, 2);
        sum1 += __shfl_xor_sync(0xffffffffu, sum1, 1);
        sum1 += __shfl_xor_sync(0xffffffffu, sum1, 2);

        float sc0 = __expf(rm0 - mn0);
        float sc1 = __expf(rm1 - mn1);
        rm0 = mn0; rm1 = mn1;
        rl0 = rl0 * sc0 + sum0;
        rl1 = rl1 * sc1 + sum1;
        #pragma unroll
        for (int nf = 0; nf < 8; nf++) {
            o[nf][0] *= sc0; o[nf][1] *= sc0;
            o[nf][2] *= sc1; o[nf][3] *= sc1;
        }

        // ---- O += P V  (P repacked in regs; V fragments via ldmatrix.trans) ----
        #pragma unroll
        for (int kcp = 0; kcp < 2; kcp++) {
            uint32_t ph[2][4], pl[2][4];
            #pragma unroll
            for (int kk = 0; kk < 2; kk++) {
                int kc = kcp * 2 + kk;
                split_pack(s[2*kc][0],   s[2*kc][1],   ph[kk][0], pl[kk][0]);
                split_pack(s[2*kc][2],   s[2*kc][3],   ph[kk][1], pl[kk][1]);
                split_pack(s[2*kc+1][0], s[2*kc+1][1], ph[kk][2], pl[kk][2]);
                split_pack(s[2*kc+1][2], s[2*kc+1][3], ph[kk][3], pl[kk][3]);
            }
            #pragma unroll
            for (int nf = 0; nf < 8; nf++) {
                uint32_t b4h[4], b4l[4];
                int rowv = kcp * 32 + lane;     // j rows (stored), trans load
                int colv = nf * 8;              // d columns
                ldsm_x4_t(b4h, sptr(&Vhs[rowv * SSTR + colv]));
                ldsm_x4_t(b4l, sptr(&Vls[rowv * SSTR + colv]));
                #pragma unroll
                for (int kk = 0; kk < 2; kk++) {
                    mma_bf16(o[nf], ph[kk], b4h[2*kk], b4h[2*kk+1]);
                    mma_bf16(o[nf], ph[kk], b4l[2*kk], b4l[2*kk+1]);
                    mma_bf16(o[nf], pl[kk], b4h[2*kk], b4h[2*kk+1]);
                }
            }
        }
        __syncthreads();
    }

    // ---- epilogue: normalize, split, write g_ah/g_al [b][n][512] ----
    int b = bh >> 3, h = bh & 7;
    float inv0 = 1.0f / rl0;
    float inv1 = 1.0f / rl1;
    int r0 = qt * 64 + warp * 16 + g;
    int r1 = r0 + 8;
    #pragma unroll
    for (int nf = 0; nf < 8; nf++) {
        int col = h * 64 + nf * 8 + 2 * t4;
        uint32_t h0, l0;
        split_pack(o[nf][0] * inv0, o[nf][1] * inv0, h0, l0);
        *reinterpret_cast<uint32_t*>(&g_ah[((size_t)b * 2048 + r0) * 512 + col]) = h0;
        *reinterpret_cast<uint32_t*>(&g_al[((size_t)b * 2048 + r0) * 512 + col]) = l0;
        split_pack(o[nf][2] * inv1, o[nf][3] * inv1, h0, l0);
        *reinterpret_cast<uint32_t*>(&g_ah[((size_t)b * 2048 + r1) * 512 + col]) = h0;
        *reinterpret_cast<uint32_t*>(&g_al[((size_t)b * 2048 + r1) * 512 + col]) = l0;
    }
}

// ========================= launch =========================================
extern "C" void kernel_launch(void* const* d_in, const int* in_sizes, int n_in,
                              void* d_out, int out_size)
{
    const float* x      = (const float*)d_in[0];
    const float* w_qkv  = (const float*)d_in[1];
    const float* w_proj = (const float*)d_in[2];
    const float* b_proj = (const float*)d_in[3];
    const float* gamma  = (const float*)d_in[4];
    const float* beta   = (const float*)d_in[5];
    float* out = (float*)d_out;

    cudaFuncSetAttribute(flash_mma,
                         cudaFuncAttributeMaxDynamicSharedMemorySize,
                         FLASH_SMEM_BYTES);
    cudaFuncSetAttribute(gemm_mma<0>,
                         cudaFuncAttributeMaxDynamicSharedMemorySize,
                         GEMM_SMEM);
    cudaFuncSetAttribute(gemm_mma<1>,
                         cudaFuncAttributeMaxDynamicSharedMemorySize,
                         GEMM_SMEM);

    prep_split<<<2048, 256>>>(w_qkv, w_proj);
    ln_kernel<<<ROWS, 128>>>(x, gamma, beta);
    gemm_mma<0><<<dim3(TRIPLE / 64, ROWS / 128), 256, GEMM_SMEM>>>(nullptr, nullptr);
    flash_mma<<<dim3(SEQ / 64, BATCH * HEADS), 128, FLASH_SMEM_BYTES>>>();
    gemm_mma<1><<<dim3(DIM / 64, ROWS / 128), 256, GEMM_SMEM>>>(b_proj, out);
}

// round 11
// speedup vs baseline: 3.2167x; 1.0521x over previous
#include <cuda_runtime.h>
#include <cuda_bf16.h>
#include <stdint.h>
#include <math.h>

// Problem constants
#define BATCH   8
#define SEQ     2048
#define DIM     512
#define HEADS   8
#define ROWS    (BATCH * SEQ)          // 16384
#define TRIPLE  (3 * DIM)              // 1536
#define SSTR    72                     // smem row stride in bf16 (144B)

// ---------------- scratch (device globals; no runtime allocation) ----------
__device__ __nv_bfloat16 g_xh [ROWS * DIM], g_xl [ROWS * DIM];   // LN out [row][512]
__device__ __nv_bfloat16 g_wqh[TRIPLE * DIM], g_wql[TRIPLE * DIM];
__device__ __nv_bfloat16 g_wph[DIM * DIM],    g_wpl[DIM * DIM];
__device__ __nv_bfloat16 g_qh [ROWS * DIM], g_ql [ROWS * DIM];   // [bh][n][64], q pre-scaled
__device__ __nv_bfloat16 g_kh [ROWS * DIM], g_kl [ROWS * DIM];   // [bh][n][64]
__device__ __nv_bfloat16 g_vh [ROWS * DIM], g_vl [ROWS * DIM];   // [bh][n][64]
__device__ __nv_bfloat16 g_ah [ROWS * DIM], g_al [ROWS * DIM];   // attn out [b][n][512]

// ---------------- helpers ---------------------------------------------------
__device__ __forceinline__ void split_pack(float x, float y,
                                           uint32_t& hi, uint32_t& lo)
{
    __nv_bfloat16 hx = __float2bfloat16(x);
    __nv_bfloat16 hy = __float2bfloat16(y);
    __nv_bfloat16 lx = __float2bfloat16(x - __bfloat162float(hx));
    __nv_bfloat16 ly = __float2bfloat16(y - __bfloat162float(hy));
    __nv_bfloat162 h2; h2.x = hx; h2.y = hy;
    __nv_bfloat162 l2; l2.x = lx; l2.y = ly;
    hi = *reinterpret_cast<uint32_t*>(&h2);
    lo = *reinterpret_cast<uint32_t*>(&l2);
}

__device__ __forceinline__ void mma_bf16(float* c, const uint32_t* a,
                                         uint32_t b0, uint32_t b1)
{
    asm volatile(
        "mma.sync.aligned.m16n8k16.row.col.f32.bf16.bf16.f32 "
        "{%0,%1,%2,%3}, {%4,%5,%6,%7}, {%8,%9}, {%0,%1,%2,%3};\n"
        : "+f"(c[0]), "+f"(c[1]), "+f"(c[2]), "+f"(c[3])
        : "r"(a[0]), "r"(a[1]), "r"(a[2]), "r"(a[3]), "r"(b0), "r"(b1));
}

__device__ __forceinline__ uint32_t sptr(const void* p)
{
    return (uint32_t)__cvta_generic_to_shared(p);
}

__device__ __forceinline__ void ldsm_x4(uint32_t* r, uint32_t addr)
{
    asm volatile(
        "ldmatrix.sync.aligned.m8n8.x4.shared.b16 {%0,%1,%2,%3}, [%4];\n"
        : "=r"(r[0]), "=r"(r[1]), "=r"(r[2]), "=r"(r[3]) : "r"(addr));
}

__device__ __forceinline__ void ldsm_x4_t(uint32_t* r, uint32_t addr)
{
    asm volatile(
        "ldmatrix.sync.aligned.m8n8.x4.trans.shared.b16 {%0,%1,%2,%3}, [%4];\n"
        : "=r"(r[0]), "=r"(r[1]), "=r"(r[2]), "=r"(r[3]) : "r"(addr));
}

__device__ __forceinline__ void cpa16(uint32_t saddr, const void* gaddr)
{
    asm volatile("cp.async.cg.shared.global [%0], [%1], 16;\n"
                 :: "r"(saddr), "l"(gaddr));
}

__device__ __forceinline__ void cpa_commit()
{
    asm volatile("cp.async.commit_group;\n");
}

template<int N>
__device__ __forceinline__ void cpa_wait()
{
    asm volatile("cp.async.wait_group %0;\n" :: "n"(N));
}

// ========================= weight split (one-off) =========================
__global__ void __launch_bounds__(256)
prep_split(const float* __restrict__ wq, const float* __restrict__ wp)
{
    const int NQ = TRIPLE * DIM / 2;
    const int NP = DIM * DIM / 2;
    int idx = blockIdx.x * 256 + threadIdx.x;
    if (idx < NQ) {
        float2 v = reinterpret_cast<const float2*>(wq)[idx];
        uint32_t h, l; split_pack(v.x, v.y, h, l);
        reinterpret_cast<uint32_t*>(g_wqh)[idx] = h;
        reinterpret_cast<uint32_t*>(g_wql)[idx] = l;
    } else if (idx < NQ + NP) {
        int j = idx - NQ;
        float2 v = reinterpret_cast<const float2*>(wp)[j];
        uint32_t h, l; split_pack(v.x, v.y, h, l);
        reinterpret_cast<uint32_t*>(g_wph)[j] = h;
        reinterpret_cast<uint32_t*>(g_wpl)[j] = l;
    }
}

// ========================= LayerNorm (writes split bf16) ==================
__global__ void __launch_bounds__(128)
ln_kernel(const float* __restrict__ x,
          const float* __restrict__ gamma,
          const float* __restrict__ beta)
{
    int row = blockIdx.x;
    int t   = threadIdx.x;
    const float4* xr = reinterpret_cast<const float4*>(x) + (size_t)row * 128;
    float4 v = xr[t];

    __shared__ float red[4];
    float s = v.x + v.y + v.z + v.w;
    #pragma unroll
    for (int o = 16; o; o >>= 1) s += __shfl_xor_sync(0xffffffffu, s, o);
    if ((t & 31) == 0) red[t >> 5] = s;
    __syncthreads();
    float mu = (red[0] + red[1] + red[2] + red[3]) * (1.0f / 512.0f);

    float dx0 = v.x - mu, dx1 = v.y - mu, dx2 = v.z - mu, dx3 = v.w - mu;
    float s2 = dx0*dx0 + dx1*dx1 + dx2*dx2 + dx3*dx3;
    #pragma unroll
    for (int o = 16; o; o >>= 1) s2 += __shfl_xor_sync(0xffffffffu, s2, o);
    __syncthreads();
    if ((t & 31) == 0) red[t >> 5] = s2;
    __syncthreads();
    float var  = (red[0] + red[1] + red[2] + red[3]) * (1.0f / 512.0f);
    float rstd = rsqrtf(var + 1e-6f);

    float4 g  = reinterpret_cast<const float4*>(gamma)[t];
    float4 bb = reinterpret_cast<const float4*>(beta)[t];
    float o0 = dx0 * rstd * g.x + bb.x;
    float o1 = dx1 * rstd * g.y + bb.y;
    float o2 = dx2 * rstd * g.z + bb.z;
    float o3 = dx3 * rstd * g.w + bb.w;
    uint32_t h0, l0, h1, l1;
    split_pack(o0, o1, h0, l0);
    split_pack(o2, o3, h1, l1);
    uint2 hh = make_uint2(h0, h1);
    uint2 ll = make_uint2(l0, l1);
    *reinterpret_cast<uint2*>(&g_xh[(size_t)row * 512 + t * 4]) = hh;
    *reinterpret_cast<uint2*>(&g_xl[(size_t)row * 512 + t * 4]) = ll;
}

// ========================= GEMM (bf16x3, ldmatrix) ========================
// unchanged from R10 (isolate the flash change this round)
#define GEMM_SMEM ((128 * 2 + 64 * 2) * SSTR * 2)   // 55296 bytes

template<int MODE>
__global__ void __launch_bounds__(256)
gemm_mma(const float* __restrict__ bias, float* __restrict__ out)
{
    extern __shared__ __nv_bfloat16 sm[];
    __nv_bfloat16* As_h = sm;
    __nv_bfloat16* As_l = sm + 128 * SSTR;
    __nv_bfloat16* Bs_h = sm + 256 * SSTR;
    __nv_bfloat16* Bs_l = sm + 320 * SSTR;

    const __nv_bfloat16* Ah_g = (MODE == 0) ? g_xh : g_ah;
    const __nv_bfloat16* Al_g = (MODE == 0) ? g_xl : g_al;
    const __nv_bfloat16* Wh_g = (MODE == 0) ? g_wqh : g_wph;
    const __nv_bfloat16* Wl_g = (MODE == 0) ? g_wql : g_wpl;

    int tid = threadIdx.x, lane = tid & 31, warp = tid >> 5;
    int g = lane >> 2, t4 = lane & 3;
    int wm = warp & 3, wn = warp >> 2;
    int m0 = wm * 32, n0 = wn * 32;
    int bm0 = blockIdx.y * 128, bn0 = blockIdx.x * 64;
    int qS = tid & 7;

    float acc[2][4][4] = {};

    for (int k0 = 0; k0 < 512; k0 += 64) {
        #pragma unroll
        for (int j = 0; j < 4; j++) {
            int r = (tid + j * 256) >> 3;
            *reinterpret_cast<uint4*>(&As_h[r * SSTR + qS * 8]) =
                *reinterpret_cast<const uint4*>(Ah_g + (size_t)(bm0 + r) * 512 + k0 + qS * 8);
            *reinterpret_cast<uint4*>(&As_l[r * SSTR + qS * 8]) =
                *reinterpret_cast<const uint4*>(Al_g + (size_t)(bm0 + r) * 512 + k0 + qS * 8);
        }
        #pragma unroll
        for (int j = 0; j < 2; j++) {
            int r = (tid + j * 256) >> 3;
            *reinterpret_cast<uint4*>(&Bs_h[r * SSTR + qS * 8]) =
                *reinterpret_cast<const uint4*>(Wh_g + (size_t)(bn0 + r) * 512 + k0 + qS * 8);
            *reinterpret_cast<uint4*>(&Bs_l[r * SSTR + qS * 8]) =
                *reinterpret_cast<const uint4*>(Wl_g + (size_t)(bn0 + r) * 512 + k0 + qS * 8);
        }
        __syncthreads();

        #pragma unroll
        for (int kcp = 0; kcp < 2; kcp++) {
            uint32_t ah[2][2][4], al[2][2][4];
            #pragma unroll
            for (int kk = 0; kk < 2; kk++)
                #pragma unroll
                for (int im = 0; im < 2; im++) {
                    int row = m0 + im * 16 + (lane & 15);
                    int col = kcp * 32 + kk * 16 + (lane >> 4) * 8;
                    ldsm_x4(ah[kk][im], sptr(&As_h[row * SSTR + col]));
                    ldsm_x4(al[kk][im], sptr(&As_l[row * SSTR + col]));
                }
            #pragma unroll
            for (int nf = 0; nf < 4; nf++) {
                uint32_t b4h[4], b4l[4];
                int rowb = n0 + nf * 8 + (lane & 7);
                int colb = kcp * 32 + (lane >> 3) * 8;
                ldsm_x4(b4h, sptr(&Bs_h[rowb * SSTR + colb]));
                ldsm_x4(b4l, sptr(&Bs_l[rowb * SSTR + colb]));
                #pragma unroll
                for (int kk = 0; kk < 2; kk++)
                    #pragma unroll
                    for (int im = 0; im < 2; im++) {
                        mma_bf16(acc[im][nf], ah[kk][im], b4h[2*kk], b4h[2*kk+1]);
                        mma_bf16(acc[im][nf], ah[kk][im], b4l[2*kk], b4l[2*kk+1]);
                        mma_bf16(acc[im][nf], al[kk][im], b4h[2*kk], b4h[2*kk+1]);
                    }
            }
        }
        __syncthreads();
    }

    if (MODE == 0) {
        int which = bn0 >> 9;
        int h     = (bn0 & 511) >> 6;
        __nv_bfloat16* dh = (which == 0) ? g_qh : (which == 1) ? g_kh : g_vh;
        __nv_bfloat16* dl = (which == 0) ? g_ql : (which == 1) ? g_kl : g_vl;
        float scl = (which == 0) ? 0.125f : 1.0f;
        #pragma unroll
        for (int im = 0; im < 2; im++) {
            #pragma unroll
            for (int nf = 0; nf < 4; nf++) {
                int d = n0 + nf * 8 + 2 * t4;
                int m = bm0 + m0 + im * 16 + g;
                int b = m >> 11, n = m & 2047;
                size_t off = ((size_t)((b << 3) + h) * 2048 + n) * 64 + d;
                uint32_t h0, l0;
                split_pack(acc[im][nf][0] * scl, acc[im][nf][1] * scl, h0, l0);
                *reinterpret_cast<uint32_t*>(&dh[off]) = h0;
                *reinterpret_cast<uint32_t*>(&dl[off]) = l0;
                split_pack(acc[im][nf][2] * scl, acc[im][nf][3] * scl, h0, l0);
                *reinterpret_cast<uint32_t*>(&dh[off + 8 * 64]) = h0;
                *reinterpret_cast<uint32_t*>(&dl[off + 8 * 64]) = l0;
            }
        }
    } else {
        #pragma unroll
        for (int im = 0; im < 2; im++) {
            #pragma unroll
            for (int nf = 0; nf < 4; nf++) {
                int col = bn0 + n0 + nf * 8 + 2 * t4;
                float2 bi = *reinterpret_cast<const float2*>(&bias[col]);
                int m = bm0 + m0 + im * 16 + g;
                float2 v0 = make_float2(acc[im][nf][0] + bi.x, acc[im][nf][1] + bi.y);
                float2 v1 = make_float2(acc[im][nf][2] + bi.x, acc[im][nf][3] + bi.y);
                *reinterpret_cast<float2*>(&out[(size_t)m * 512 + col])       = v0;
                *reinterpret_cast<float2*>(&out[(size_t)(m + 8) * 512 + col]) = v1;
            }
        }
    }
}

// ========================= Flash attention (cp.async double-buffered) =====
// grid (32 q-tiles, 64 bh), 128 thr = 4 warps; warp w owns q rows [16w,16w+16).
#define FSM (64 * SSTR)                         // 4608 bf16 per tile
#define FLASH_SMEM_BYTES ((2 + 8) * FSM * 2)    // Q(h,l) + 2 bufs x (Kh,Kl,Vh,Vl) = 92160

__global__ void __launch_bounds__(128)
flash_mma()
{
    extern __shared__ __nv_bfloat16 sm[];
    __nv_bfloat16* Qhs = sm;
    __nv_bfloat16* Qls = sm + FSM;
    // KV buffer b (b=0,1): base = sm + (2 + 4*b)*FSM; [Kh | Kl | Vh | Vl]

    int bh = blockIdx.y, qt = blockIdx.x;
    int tid = threadIdx.x, lane = tid & 31, warp = tid >> 5;
    int g = lane >> 2, t4 = lane & 3;
    int qS = tid & 7;

    // per-thread staging coordinates (4 rows, 16B each)
    int srow[4];
    #pragma unroll
    for (int j = 0; j < 4; j++) srow[j] = (tid + j * 128) >> 3;

    // ---- stage Q ----
    size_t qoff = ((size_t)bh * 2048 + qt * 64) * 64;
    #pragma unroll
    for (int j = 0; j < 4; j++) {
        int r = srow[j];
        *reinterpret_cast<uint4*>(&Qhs[r * SSTR + qS * 8]) =
            *reinterpret_cast<const uint4*>(g_qh + qoff + (size_t)r * 64 + qS * 8);
        *reinterpret_cast<uint4*>(&Qls[r * SSTR + qS * 8]) =
            *reinterpret_cast<const uint4*>(g_ql + qoff + (size_t)r * 64 + qS * 8);
    }

    // ---- issue cp.async for kv tile 0 into buffer 0 ----
    {
        __nv_bfloat16* base = sm + 2 * FSM;
        size_t koff = (size_t)bh * 2048 * 64;   // kt = 0
        #pragma unroll
        for (int j = 0; j < 4; j++) {
            int r = srow[j];
            size_t go = koff + (size_t)r * 64 + qS * 8;
            int so = r * SSTR + qS * 8;
            cpa16(sptr(base + so),           g_kh + go);
            cpa16(sptr(base + FSM + so),     g_kl + go);
            cpa16(sptr(base + 2 * FSM + so), g_vh + go);
            cpa16(sptr(base + 3 * FSM + so), g_vl + go);
        }
        cpa_commit();
    }
    __syncthreads();   // Q visible to all warps

    // ---- Q fragments to registers (once) ----
    uint32_t qh[4][4], ql[4][4];
    #pragma unroll
    for (int kc = 0; kc < 4; kc++) {
        int row = warp * 16 + (lane & 15);
        int col = kc * 16 + (lane >> 4) * 8;
        ldsm_x4(qh[kc], sptr(&Qhs[row * SSTR + col]));
        ldsm_x4(ql[kc], sptr(&Qls[row * SSTR + col]));
    }

    float o[8][4] = {};
    float rm0 = -1e30f, rm1 = -1e30f, rl0 = 0.0f, rl1 = 0.0f;

    for (int kt = 0; kt < 32; kt++) {
        // prefetch next kv tile into the other buffer
        if (kt + 1 < 32) {
            __nv_bfloat16* nbase = sm + (2 + 4 * ((kt + 1) & 1)) * FSM;
            size_t koff = ((size_t)bh * 2048 + (kt + 1) * 64) * 64;
            #pragma unroll
            for (int j = 0; j < 4; j++) {
                int r = srow[j];
                size_t go = koff + (size_t)r * 64 + qS * 8;
                int so = r * SSTR + qS * 8;
                cpa16(sptr(nbase + so),           g_kh + go);
                cpa16(sptr(nbase + FSM + so),     g_kl + go);
                cpa16(sptr(nbase + 2 * FSM + so), g_vh + go);
                cpa16(sptr(nbase + 3 * FSM + so), g_vl + go);
            }
            cpa_commit();
            cpa_wait<1>();     // current tile's group complete; next in flight
        } else {
            cpa_wait<0>();
        }
        __syncthreads();       // current buffer visible to all warps

        __nv_bfloat16* base = sm + (2 + 4 * (kt & 1)) * FSM;
        __nv_bfloat16* Khs = base;
        __nv_bfloat16* Kls = base + FSM;
        __nv_bfloat16* Vhs = base + 2 * FSM;
        __nv_bfloat16* Vls = base + 3 * FSM;

        // ---- S = Q K^T ----
        float s[8][4] = {};
        #pragma unroll
        for (int nf = 0; nf < 8; nf++) {
            int rowb = nf * 8 + (lane & 7);
            #pragma unroll
            for (int kcp = 0; kcp < 2; kcp++) {
                int colb = kcp * 32 + (lane >> 3) * 8;
                uint32_t b4h[4], b4l[4];
                ldsm_x4(b4h, sptr(&Khs[rowb * SSTR + colb]));
                ldsm_x4(b4l, sptr(&Kls[rowb * SSTR + colb]));
                #pragma unroll
                for (int kk = 0; kk < 2; kk++) {
                    int kc = kcp * 2 + kk;
                    mma_bf16(s[nf], qh[kc], b4h[2*kk], b4h[2*kk+1]);
                    mma_bf16(s[nf], qh[kc], b4l[2*kk], b4l[2*kk+1]);
                    mma_bf16(s[nf], ql[kc], b4h[2*kk], b4h[2*kk+1]);
                }
            }
        }

        // ---- online softmax (registers; quad reductions) ----
        float mx0 = -1e30f, mx1 = -1e30f;
        #pragma unroll
        for (int nf = 0; nf < 8; nf++) {
            mx0 = fmaxf(mx0, fmaxf(s[nf][0], s[nf][1]));
            mx1 = fmaxf(mx1, fmaxf(s[nf][2], s[nf][3]));
        }
        mx0 = fmaxf(mx0, __shfl_xor_sync(0xffffffffu, mx0, 1));
        mx0 = fmaxf(mx0, __shfl_xor_sync(0xffffffffu, mx0, 2));
        mx1 = fmaxf(mx1, __shfl_xor_sync(0xffffffffu, mx1, 1));
        mx1 = fmaxf(mx1, __shfl_xor_sync(0xffffffffu, mx1, 2));
        float mn0 = fmaxf(rm0, mx0);
        float mn1 = fmaxf(rm1, mx1);

        float sum0 = 0.0f, sum1 = 0.0f;
        #pragma unroll
        for (int nf = 0; nf < 8; nf++) {
            s[nf][0] = __expf(s[nf][0] - mn0);
            s[nf][1] = __expf(s[nf][1] - mn0);
            s[nf][2] = __expf(s[nf][2] - mn1);
            s[nf][3] = __expf(s[nf][3] - mn1);
            sum0 += s[nf][0] + s[nf][1];
            sum1 += s[nf][2] + s[nf][3];
        }
        sum0 += __shfl_xor_sync(0xffffffffu, sum0, 1);
        sum0 += __shfl_xor_sync(0xffffffffu, sum0, 2);
        sum1 += __shfl_xor_sync(0xffffffffu, sum1, 1);
        sum1 += __shfl_xor_sync(0xffffffffu, sum1, 2);

        float sc0 = __expf(rm0 - mn0);
        float sc1 = __expf(rm1 - mn1);
        rm0 = mn0; rm1 = mn1;
        rl0 = rl0 * sc0 + sum0;
        rl1 = rl1 * sc1 + sum1;
        #pragma unroll
        for (int nf = 0; nf < 8; nf++) {
            o[nf][0] *= sc0; o[nf][1] *= sc0;
            o[nf][2] *= sc1; o[nf][3] *= sc1;
        }

        // ---- O += P V ----
        #pragma unroll
        for (int kcp = 0; kcp < 2; kcp++) {
            uint32_t ph[2][4], pl[2][4];
            #pragma unroll
            for (int kk = 0; kk < 2; kk++) {
                int kc = kcp * 2 + kk;
                split_pack(s[2*kc][0],   s[2*kc][1],   ph[kk][0], pl[kk][0]);
                split_pack(s[2*kc][2],   s[2*kc][3],   ph[kk][1], pl[kk][1]);
                split_pack(s[2*kc+1][0], s[2*kc+1][1], ph[kk][2], pl[kk][2]);
                split_pack(s[2*kc+1][2], s[2*kc+1][3], ph[kk][3], pl[kk][3]);
            }
            #pragma unroll
            for (int nf = 0; nf < 8; nf++) {
                uint32_t b4h[4], b4l[4];
                int rowv = kcp * 32 + lane;
                int colv = nf * 8;
                ldsm_x4_t(b4h, sptr(&Vhs[rowv * SSTR + colv]));
                ldsm_x4_t(b4l, sptr(&Vls[rowv * SSTR + colv]));
                #pragma unroll
                for (int kk = 0; kk < 2; kk++) {
                    mma_bf16(o[nf], ph[kk], b4h[2*kk], b4h[2*kk+1]);
                    mma_bf16(o[nf], ph[kk], b4l[2*kk], b4l[2*kk+1]);
                    mma_bf16(o[nf], pl[kk], b4h[2*kk], b4h[2*kk+1]);
                }
            }
        }
        __syncthreads();   // all warps done reading buf before next prefetch overwrites
    }

    // ---- epilogue: normalize, split, write g_ah/g_al [b][n][512] ----
    int b = bh >> 3, h = bh & 7;
    float inv0 = 1.0f / rl0;
    float inv1 = 1.0f / rl1;
    int r0 = qt * 64 + warp * 16 + g;
    int r1 = r0 + 8;
    #pragma unroll
    for (int nf = 0; nf < 8; nf++) {
        int col = h * 64 + nf * 8 + 2 * t4;
        uint32_t h0, l0;
        split_pack(o[nf][0] * inv0, o[nf][1] * inv0, h0, l0);
        *reinterpret_cast<uint32_t*>(&g_ah[((size_t)b * 2048 + r0) * 512 + col]) = h0;
        *reinterpret_cast<uint32_t*>(&g_al[((size_t)b * 2048 + r0) * 512 + col]) = l0;
        split_pack(o[nf][2] * inv1, o[nf][3] * inv1, h0, l0);
        *reinterpret_cast<uint32_t*>(&g_ah[((size_t)b * 2048 + r1) * 512 + col]) = h0;
        *reinterpret_cast<uint32_t*>(&g_al[((size_t)b * 2048 + r1) * 512 + col]) = l0;
    }
}

// ========================= launch =========================================
extern "C" void kernel_launch(void* const* d_in, const int* in_sizes, int n_in,
                              void* d_out, int out_size)
{
    const float* x      = (const float*)d_in[0];
    const float* w_qkv  = (const float*)d_in[1];
    const float* w_proj = (const float*)d_in[2];
    const float* b_proj = (const float*)d_in[3];
    const float* gamma  = (const float*)d_in[4];
    const float* beta   = (const float*)d_in[5];
    float* out = (float*)d_out;

    cudaFuncSetAttribute(flash_mma,
                         cudaFuncAttributeMaxDynamicSharedMemorySize,
                         FLASH_SMEM_BYTES);
    cudaFuncSetAttribute(gemm_mma<0>,
                         cudaFuncAttributeMaxDynamicSharedMemorySize,
                         GEMM_SMEM);
    cudaFuncSetAttribute(gemm_mma<1>,
                         cudaFuncAttributeMaxDynamicSharedMemorySize,
                         GEMM_SMEM);

    prep_split<<<2048, 256>>>(w_qkv, w_proj);
    ln_kernel<<<ROWS, 128>>>(x, gamma, beta);
    gemm_mma<0><<<dim3(TRIPLE / 64, ROWS / 128), 256, GEMM_SMEM>>>(nullptr, nullptr);
    flash_mma<<<dim3(SEQ / 64, BATCH * HEADS), 128, FLASH_SMEM_BYTES>>>();
    gemm_mma<1><<<dim3(DIM / 64, ROWS / 128), 256, GEMM_SMEM>>>(b_proj, out);
}

// round 12
// speedup vs baseline: 3.4898x; 1.0849x over previous
#include <cuda_runtime.h>
#include <cuda_bf16.h>
#include <stdint.h>
#include <math.h>

// Problem constants
#define BATCH   8
#define SEQ     2048
#define DIM     512
#define HEADS   8
#define ROWS    (BATCH * SEQ)          // 16384
#define TRIPLE  (3 * DIM)              // 1536
#define SSTR    72                     // smem row stride in bf16 (144B)

// ---------------- scratch (device globals; no runtime allocation) ----------
__device__ __nv_bfloat16 g_xh [ROWS * DIM], g_xl [ROWS * DIM];   // LN out [row][512]
__device__ __nv_bfloat16 g_wqh[TRIPLE * DIM], g_wql[TRIPLE * DIM];
__device__ __nv_bfloat16 g_wph[DIM * DIM],    g_wpl[DIM * DIM];
__device__ __nv_bfloat16 g_qh [ROWS * DIM], g_ql [ROWS * DIM];   // [bh][n][64], q pre-scaled
__device__ __nv_bfloat16 g_kh [ROWS * DIM], g_kl [ROWS * DIM];   // [bh][n][64]
__device__ __nv_bfloat16 g_vh [ROWS * DIM], g_vl [ROWS * DIM];   // [bh][n][64]
__device__ __nv_bfloat16 g_ah [ROWS * DIM], g_al [ROWS * DIM];   // attn out [b][n][512]

// ---------------- helpers ---------------------------------------------------
__device__ __forceinline__ void split_pack(float x, float y,
                                           uint32_t& hi, uint32_t& lo)
{
    __nv_bfloat16 hx = __float2bfloat16(x);
    __nv_bfloat16 hy = __float2bfloat16(y);
    __nv_bfloat16 lx = __float2bfloat16(x - __bfloat162float(hx));
    __nv_bfloat16 ly = __float2bfloat16(y - __bfloat162float(hy));
    __nv_bfloat162 h2; h2.x = hx; h2.y = hy;
    __nv_bfloat162 l2; l2.x = lx; l2.y = ly;
    hi = *reinterpret_cast<uint32_t*>(&h2);
    lo = *reinterpret_cast<uint32_t*>(&l2);
}

__device__ __forceinline__ void mma_bf16(float* c, const uint32_t* a,
                                         uint32_t b0, uint32_t b1)
{
    asm volatile(
        "mma.sync.aligned.m16n8k16.row.col.f32.bf16.bf16.f32 "
        "{%0,%1,%2,%3}, {%4,%5,%6,%7}, {%8,%9}, {%0,%1,%2,%3};\n"
        : "+f"(c[0]), "+f"(c[1]), "+f"(c[2]), "+f"(c[3])
        : "r"(a[0]), "r"(a[1]), "r"(a[2]), "r"(a[3]), "r"(b0), "r"(b1));
}

__device__ __forceinline__ uint32_t sptr(const void* p)
{
    return (uint32_t)__cvta_generic_to_shared(p);
}

__device__ __forceinline__ void ldsm_x4(uint32_t* r, uint32_t addr)
{
    asm volatile(
        "ldmatrix.sync.aligned.m8n8.x4.shared.b16 {%0,%1,%2,%3}, [%4];\n"
        : "=r"(r[0]), "=r"(r[1]), "=r"(r[2]), "=r"(r[3]) : "r"(addr));
}

__device__ __forceinline__ void ldsm_x4_t(uint32_t* r, uint32_t addr)
{
    asm volatile(
        "ldmatrix.sync.aligned.m8n8.x4.trans.shared.b16 {%0,%1,%2,%3}, [%4];\n"
        : "=r"(r[0]), "=r"(r[1]), "=r"(r[2]), "=r"(r[3]) : "r"(addr));
}

__device__ __forceinline__ void cpa16(uint32_t saddr, const void* gaddr)
{
    asm volatile("cp.async.cg.shared.global [%0], [%1], 16;\n"
                 :: "r"(saddr), "l"(gaddr));
}

__device__ __forceinline__ void cpa_commit()
{
    asm volatile("cp.async.commit_group;\n");
}

template<int N>
__device__ __forceinline__ void cpa_wait()
{
    asm volatile("cp.async.wait_group %0;\n" :: "n"(N));
}

// ========================= weight split (one-off) =========================
__global__ void __launch_bounds__(256)
prep_split(const float* __restrict__ wq, const float* __restrict__ wp)
{
    const int NQ = TRIPLE * DIM / 2;
    const int NP = DIM * DIM / 2;
    int idx = blockIdx.x * 256 + threadIdx.x;
    if (idx < NQ) {
        float2 v = reinterpret_cast<const float2*>(wq)[idx];
        uint32_t h, l; split_pack(v.x, v.y, h, l);
        reinterpret_cast<uint32_t*>(g_wqh)[idx] = h;
        reinterpret_cast<uint32_t*>(g_wql)[idx] = l;
    } else if (idx < NQ + NP) {
        int j = idx - NQ;
        float2 v = reinterpret_cast<const float2*>(wp)[j];
        uint32_t h, l; split_pack(v.x, v.y, h, l);
        reinterpret_cast<uint32_t*>(g_wph)[j] = h;
        reinterpret_cast<uint32_t*>(g_wpl)[j] = l;
    }
}

// ========================= LayerNorm (writes split bf16) ==================
__global__ void __launch_bounds__(128)
ln_kernel(const float* __restrict__ x,
          const float* __restrict__ gamma,
          const float* __restrict__ beta)
{
    int row = blockIdx.x;
    int t   = threadIdx.x;
    const float4* xr = reinterpret_cast<const float4*>(x) + (size_t)row * 128;
    float4 v = xr[t];

    __shared__ float red[4];
    float s = v.x + v.y + v.z + v.w;
    #pragma unroll
    for (int o = 16; o; o >>= 1) s += __shfl_xor_sync(0xffffffffu, s, o);
    if ((t & 31) == 0) red[t >> 5] = s;
    __syncthreads();
    float mu = (red[0] + red[1] + red[2] + red[3]) * (1.0f / 512.0f);

    float dx0 = v.x - mu, dx1 = v.y - mu, dx2 = v.z - mu, dx3 = v.w - mu;
    float s2 = dx0*dx0 + dx1*dx1 + dx2*dx2 + dx3*dx3;
    #pragma unroll
    for (int o = 16; o; o >>= 1) s2 += __shfl_xor_sync(0xffffffffu, s2, o);
    __syncthreads();
    if ((t & 31) == 0) red[t >> 5] = s2;
    __syncthreads();
    float var  = (red[0] + red[1] + red[2] + red[3]) * (1.0f / 512.0f);
    float rstd = rsqrtf(var + 1e-6f);

    float4 g  = reinterpret_cast<const float4*>(gamma)[t];
    float4 bb = reinterpret_cast<const float4*>(beta)[t];
    float o0 = dx0 * rstd * g.x + bb.x;
    float o1 = dx1 * rstd * g.y + bb.y;
    float o2 = dx2 * rstd * g.z + bb.z;
    float o3 = dx3 * rstd * g.w + bb.w;
    uint32_t h0, l0, h1, l1;
    split_pack(o0, o1, h0, l0);
    split_pack(o2, o3, h1, l1);
    uint2 hh = make_uint2(h0, h1);
    uint2 ll = make_uint2(l0, l1);
    *reinterpret_cast<uint2*>(&g_xh[(size_t)row * 512 + t * 4]) = hh;
    *reinterpret_cast<uint2*>(&g_xl[(size_t)row * 512 + t * 4]) = ll;
}

// ========================= GEMM (bf16x3, ldmatrix) ========================
// unchanged from R11 (isolate the flash change this round)
#define GEMM_SMEM ((128 * 2 + 64 * 2) * SSTR * 2)   // 55296 bytes

template<int MODE>
__global__ void __launch_bounds__(256)
gemm_mma(const float* __restrict__ bias, float* __restrict__ out)
{
    extern __shared__ __nv_bfloat16 sm[];
    __nv_bfloat16* As_h = sm;
    __nv_bfloat16* As_l = sm + 128 * SSTR;
    __nv_bfloat16* Bs_h = sm + 256 * SSTR;
    __nv_bfloat16* Bs_l = sm + 320 * SSTR;

    const __nv_bfloat16* Ah_g = (MODE == 0) ? g_xh : g_ah;
    const __nv_bfloat16* Al_g = (MODE == 0) ? g_xl : g_al;
    const __nv_bfloat16* Wh_g = (MODE == 0) ? g_wqh : g_wph;
    const __nv_bfloat16* Wl_g = (MODE == 0) ? g_wql : g_wpl;

    int tid = threadIdx.x, lane = tid & 31, warp = tid >> 5;
    int g = lane >> 2, t4 = lane & 3;
    int wm = warp & 3, wn = warp >> 2;
    int m0 = wm * 32, n0 = wn * 32;
    int bm0 = blockIdx.y * 128, bn0 = blockIdx.x * 64;
    int qS = tid & 7;

    float acc[2][4][4] = {};

    for (int k0 = 0; k0 < 512; k0 += 64) {
        #pragma unroll
        for (int j = 0; j < 4; j++) {
            int r = (tid + j * 256) >> 3;
            *reinterpret_cast<uint4*>(&As_h[r * SSTR + qS * 8]) =
                *reinterpret_cast<const uint4*>(Ah_g + (size_t)(bm0 + r) * 512 + k0 + qS * 8);
            *reinterpret_cast<uint4*>(&As_l[r * SSTR + qS * 8]) =
                *reinterpret_cast<const uint4*>(Al_g + (size_t)(bm0 + r) * 512 + k0 + qS * 8);
        }
        #pragma unroll
        for (int j = 0; j < 2; j++) {
            int r = (tid + j * 256) >> 3;
            *reinterpret_cast<uint4*>(&Bs_h[r * SSTR + qS * 8]) =
                *reinterpret_cast<const uint4*>(Wh_g + (size_t)(bn0 + r) * 512 + k0 + qS * 8);
            *reinterpret_cast<uint4*>(&Bs_l[r * SSTR + qS * 8]) =
                *reinterpret_cast<const uint4*>(Wl_g + (size_t)(bn0 + r) * 512 + k0 + qS * 8);
        }
        __syncthreads();

        #pragma unroll
        for (int kcp = 0; kcp < 2; kcp++) {
            uint32_t ah[2][2][4], al[2][2][4];
            #pragma unroll
            for (int kk = 0; kk < 2; kk++)
                #pragma unroll
                for (int im = 0; im < 2; im++) {
                    int row = m0 + im * 16 + (lane & 15);
                    int col = kcp * 32 + kk * 16 + (lane >> 4) * 8;
                    ldsm_x4(ah[kk][im], sptr(&As_h[row * SSTR + col]));
                    ldsm_x4(al[kk][im], sptr(&As_l[row * SSTR + col]));
                }
            #pragma unroll
            for (int nf = 0; nf < 4; nf++) {
                uint32_t b4h[4], b4l[4];
                int rowb = n0 + nf * 8 + (lane & 7);
                int colb = kcp * 32 + (lane >> 3) * 8;
                ldsm_x4(b4h, sptr(&Bs_h[rowb * SSTR + colb]));
                ldsm_x4(b4l, sptr(&Bs_l[rowb * SSTR + colb]));
                #pragma unroll
                for (int kk = 0; kk < 2; kk++)
                    #pragma unroll
                    for (int im = 0; im < 2; im++) {
                        mma_bf16(acc[im][nf], ah[kk][im], b4h[2*kk], b4h[2*kk+1]);
                        mma_bf16(acc[im][nf], ah[kk][im], b4l[2*kk], b4l[2*kk+1]);
                        mma_bf16(acc[im][nf], al[kk][im], b4h[2*kk], b4h[2*kk+1]);
                    }
            }
        }
        __syncthreads();
    }

    if (MODE == 0) {
        int which = bn0 >> 9;
        int h     = (bn0 & 511) >> 6;
        __nv_bfloat16* dh = (which == 0) ? g_qh : (which == 1) ? g_kh : g_vh;
        __nv_bfloat16* dl = (which == 0) ? g_ql : (which == 1) ? g_kl : g_vl;
        float scl = (which == 0) ? 0.125f : 1.0f;
        #pragma unroll
        for (int im = 0; im < 2; im++) {
            #pragma unroll
            for (int nf = 0; nf < 4; nf++) {
                int d = n0 + nf * 8 + 2 * t4;
                int m = bm0 + m0 + im * 16 + g;
                int b = m >> 11, n = m & 2047;
                size_t off = ((size_t)((b << 3) + h) * 2048 + n) * 64 + d;
                uint32_t h0, l0;
                split_pack(acc[im][nf][0] * scl, acc[im][nf][1] * scl, h0, l0);
                *reinterpret_cast<uint32_t*>(&dh[off]) = h0;
                *reinterpret_cast<uint32_t*>(&dl[off]) = l0;
                split_pack(acc[im][nf][2] * scl, acc[im][nf][3] * scl, h0, l0);
                *reinterpret_cast<uint32_t*>(&dh[off + 8 * 64]) = h0;
                *reinterpret_cast<uint32_t*>(&dl[off + 8 * 64]) = l0;
            }
        }
    } else {
        #pragma unroll
        for (int im = 0; im < 2; im++) {
            #pragma unroll
            for (int nf = 0; nf < 4; nf++) {
                int col = bn0 + n0 + nf * 8 + 2 * t4;
                float2 bi = *reinterpret_cast<const float2*>(&bias[col]);
                int m = bm0 + m0 + im * 16 + g;
                float2 v0 = make_float2(acc[im][nf][0] + bi.x, acc[im][nf][1] + bi.y);
                float2 v1 = make_float2(acc[im][nf][2] + bi.x, acc[im][nf][3] + bi.y);
                *reinterpret_cast<float2*>(&out[(size_t)m * 512 + col])       = v0;
                *reinterpret_cast<float2*>(&out[(size_t)(m + 8) * 512 + col]) = v1;
            }
        }
    }
}

// ========================= Flash attention (3 CTA/SM, K dbl + V single) ===
// grid (32 q-tiles, 64 bh), 128 thr = 4 warps; warp w owns q rows [16w,16w+16).
// smem: Q(h,l) + K dbl-buf(h,l) + V single(h,l) = 8 tiles = 73728 B -> 3 CTA/SM
#define FSM (64 * SSTR)                       // 4608 bf16 per tile
#define FLASH_SMEM_BYTES (8 * FSM * 2)        // 73728

__global__ void __launch_bounds__(128, 3)
flash_mma()
{
    extern __shared__ __nv_bfloat16 sm[];
    __nv_bfloat16* Qhs = sm;
    __nv_bfloat16* Qls = sm + FSM;
    // K buffer b (0,1): base sm + (2+2b)*FSM -> [Kh | Kl]
    __nv_bfloat16* Vhs = sm + 6 * FSM;
    __nv_bfloat16* Vls = sm + 7 * FSM;

    int bh = blockIdx.y, qt = blockIdx.x;
    int tid = threadIdx.x, lane = tid & 31, warp = tid >> 5;
    int g = lane >> 2, t4 = lane & 3;
    int qS = tid & 7;

    int srow[4];
    #pragma unroll
    for (int j = 0; j < 4; j++) srow[j] = (tid + j * 128) >> 3;
    size_t bhoff = (size_t)bh * 2048 * 64;

    // ---- group issue helpers (uniform accounting: every commit = 1 group) --
    auto issue_k = [&](int kt) {
        if (kt < 32) {
            __nv_bfloat16* base = sm + (2 + 2 * (kt & 1)) * FSM;
            size_t koff = bhoff + (size_t)kt * 64 * 64;
            #pragma unroll
            for (int j = 0; j < 4; j++) {
                int r = srow[j];
                size_t go = koff + (size_t)r * 64 + qS * 8;
                int so = r * SSTR + qS * 8;
                cpa16(sptr(base + so),       g_kh + go);
                cpa16(sptr(base + FSM + so), g_kl + go);
            }
        }
        cpa_commit();
    };
    auto issue_v = [&](int kt) {
        if (kt < 32) {
            size_t koff = bhoff + (size_t)kt * 64 * 64;
            #pragma unroll
            for (int j = 0; j < 4; j++) {
                int r = srow[j];
                size_t go = koff + (size_t)r * 64 + qS * 8;
                int so = r * SSTR + qS * 8;
                cpa16(sptr(Vhs + so), g_vh + go);
                cpa16(sptr(Vls + so), g_vl + go);
            }
        }
        cpa_commit();
    };

    // ---- preamble: K0, V0, K1 in flight; stage Q with regular loads -------
    issue_k(0);
    issue_v(0);
    issue_k(1);

    size_t qoff = bhoff + (size_t)qt * 64 * 64;
    #pragma unroll
    for (int j = 0; j < 4; j++) {
        int r = srow[j];
        *reinterpret_cast<uint4*>(&Qhs[r * SSTR + qS * 8]) =
            *reinterpret_cast<const uint4*>(g_qh + qoff + (size_t)r * 64 + qS * 8);
        *reinterpret_cast<uint4*>(&Qls[r * SSTR + qS * 8]) =
            *reinterpret_cast<const uint4*>(g_ql + qoff + (size_t)r * 64 + qS * 8);
    }
    __syncthreads();

    // Q-hi fragments persistent in registers; Q-lo re-read per iter from smem
    uint32_t qh[4][4];
    #pragma unroll
    for (int kc = 0; kc < 4; kc++) {
        int row = warp * 16 + (lane & 15);
        int col = kc * 16 + (lane >> 4) * 8;
        ldsm_x4(qh[kc], sptr(&Qhs[row * SSTR + col]));
    }

    float o[8][4] = {};
    float rm0 = -1e30f, rm1 = -1e30f, rl0 = 0.0f, rl1 = 0.0f;

    for (int kt = 0; kt < 32; kt++) {
        // pending: Kg(kt), Vg(kt), Kg(kt+1)
        cpa_wait<2>();          // Kg(kt) complete
        __syncthreads();

        __nv_bfloat16* kbase = sm + (2 + 2 * (kt & 1)) * FSM;
        __nv_bfloat16* Khs = kbase;
        __nv_bfloat16* Kls = kbase + FSM;

        // ---- S = Q K^T ----
        float s[8][4] = {};
        #pragma unroll
        for (int kcp = 0; kcp < 2; kcp++) {
            uint32_t ql2[2][4];
            #pragma unroll
            for (int kk = 0; kk < 2; kk++) {
                int row = warp * 16 + (lane & 15);
                int col = (kcp * 2 + kk) * 16 + (lane >> 4) * 8;
                ldsm_x4(ql2[kk], sptr(&Qls[row * SSTR + col]));
            }
            #pragma unroll
            for (int nf = 0; nf < 8; nf++) {
                int rowb = nf * 8 + (lane & 7);
                int colb = kcp * 32 + (lane >> 3) * 8;
                uint32_t b4h[4], b4l[4];
                ldsm_x4(b4h, sptr(&Khs[rowb * SSTR + colb]));
                ldsm_x4(b4l, sptr(&Kls[rowb * SSTR + colb]));
                #pragma unroll
                for (int kk = 0; kk < 2; kk++) {
                    int kc = kcp * 2 + kk;
                    mma_bf16(s[nf], qh[kc],  b4h[2*kk], b4h[2*kk+1]);
                    mma_bf16(s[nf], qh[kc],  b4l[2*kk], b4l[2*kk+1]);
                    mma_bf16(s[nf], ql2[kk], b4h[2*kk], b4h[2*kk+1]);
                }
            }
        }

        // ---- online softmax (registers; quad reductions) ----
        float mx0 = -1e30f, mx1 = -1e30f;
        #pragma unroll
        for (int nf = 0; nf < 8; nf++) {
            mx0 = fmaxf(mx0, fmaxf(s[nf][0], s[nf][1]));
            mx1 = fmaxf(mx1, fmaxf(s[nf][2], s[nf][3]));
        }
        mx0 = fmaxf(mx0, __shfl_xor_sync(0xffffffffu, mx0, 1));
        mx0 = fmaxf(mx0, __shfl_xor_sync(0xffffffffu, mx0, 2));
        mx1 = fmaxf(mx1, __shfl_xor_sync(0xffffffffu, mx1, 1));
        mx1 = fmaxf(mx1, __shfl_xor_sync(0xffffffffu, mx1, 2));
        float mn0 = fmaxf(rm0, mx0);
        float mn1 = fmaxf(rm1, mx1);

        float sum0 = 0.0f, sum1 = 0.0f;
        #pragma unroll
        for (int nf = 0; nf < 8; nf++) {
            s[nf][0] = __expf(s[nf][0] - mn0);
            s[nf][1] = __expf(s[nf][1] - mn0);
            s[nf][2] = __expf(s[nf][2] - mn1);
            s[nf][3] = __expf(s[nf][3] - mn1);
            sum0 += s[nf][0] + s[nf][1];
            sum1 += s[nf][2] + s[nf][3];
        }
        sum0 += __shfl_xor_sync(0xffffffffu, sum0, 1);
        sum0 += __shfl_xor_sync(0xffffffffu, sum0, 2);
        sum1 += __shfl_xor_sync(0xffffffffu, sum1, 1);
        sum1 += __shfl_xor_sync(0xffffffffu, sum1, 2);

        float sc0 = __expf(rm0 - mn0);
        float sc1 = __expf(rm1 - mn1);
        rm0 = mn0; rm1 = mn1;
        rl0 = rl0 * sc0 + sum0;
        rl1 = rl1 * sc1 + sum1;
        #pragma unroll
        for (int nf = 0; nf < 8; nf++) {
            o[nf][0] *= sc0; o[nf][1] *= sc0;
            o[nf][2] *= sc1; o[nf][3] *= sc1;
        }

        // ---- V arrival, then PV ----
        cpa_wait<1>();          // Vg(kt) complete (Kg(kt+1) still in flight)
        __syncthreads();

        #pragma unroll
        for (int kcp = 0; kcp < 2; kcp++) {
            uint32_t ph[2][4], pl[2][4];
            #pragma unroll
            for (int kk = 0; kk < 2; kk++) {
                int kc = kcp * 2 + kk;
                split_pack(s[2*kc][0],   s[2*kc][1],   ph[kk][0], pl[kk][0]);
                split_pack(s[2*kc][2],   s[2*kc][3],   ph[kk][1], pl[kk][1]);
                split_pack(s[2*kc+1][0], s[2*kc+1][1], ph[kk][2], pl[kk][2]);
                split_pack(s[2*kc+1][2], s[2*kc+1][3], ph[kk][3], pl[kk][3]);
            }
            #pragma unroll
            for (int nf = 0; nf < 8; nf++) {
                uint32_t b4h[4], b4l[4];
                int rowv = kcp * 32 + lane;
                int colv = nf * 8;
                ldsm_x4_t(b4h, sptr(&Vhs[rowv * SSTR + colv]));
                ldsm_x4_t(b4l, sptr(&Vls[rowv * SSTR + colv]));
                #pragma unroll
                for (int kk = 0; kk < 2; kk++) {
                    mma_bf16(o[nf], ph[kk], b4h[2*kk], b4h[2*kk+1]);
                    mma_bf16(o[nf], ph[kk], b4l[2*kk], b4l[2*kk+1]);
                    mma_bf16(o[nf], pl[kk], b4h[2*kk], b4h[2*kk+1]);
                }
            }
        }
        __syncthreads();        // all warps done with V buf + K buf (kt&1)

        issue_v(kt + 1);        // V single buffer: safe after barrier
        issue_k(kt + 2);        // into buffer (kt+2)&1 = (kt&1), just drained
    }

    // ---- epilogue: normalize, split, write g_ah/g_al [b][n][512] ----
    int b = bh >> 3, h = bh & 7;
    float inv0 = 1.0f / rl0;
    float inv1 = 1.0f / rl1;
    int r0 = qt * 64 + warp * 16 + g;
    int r1 = r0 + 8;
    #pragma unroll
    for (int nf = 0; nf < 8; nf++) {
        int col = h * 64 + nf * 8 + 2 * t4;
        uint32_t h0, l0;
        split_pack(o[nf][0] * inv0, o[nf][1] * inv0, h0, l0);
        *reinterpret_cast<uint32_t*>(&g_ah[((size_t)b * 2048 + r0) * 512 + col]) = h0;
        *reinterpret_cast<uint32_t*>(&g_al[((size_t)b * 2048 + r0) * 512 + col]) = l0;
        split_pack(o[nf][2] * inv1, o[nf][3] * inv1, h0, l0);
        *reinterpret_cast<uint32_t*>(&g_ah[((size_t)b * 2048 + r1) * 512 + col]) = h0;
        *reinterpret_cast<uint32_t*>(&g_al[((size_t)b * 2048 + r1) * 512 + col]) = l0;
    }
}

// ========================= launch =========================================
extern "C" void kernel_launch(void* const* d_in, const int* in_sizes, int n_in,
                              void* d_out, int out_size)
{
    const float* x      = (const float*)d_in[0];
    const float* w_qkv  = (const float*)d_in[1];
    const float* w_proj = (const float*)d_in[2];
    const float* b_proj = (const float*)d_in[3];
    const float* gamma  = (const float*)d_in[4];
    const float* beta   = (const float*)d_in[5];
    float* out = (float*)d_out;

    cudaFuncSetAttribute(flash_mma,
                         cudaFuncAttributeMaxDynamicSharedMemorySize,
                         FLASH_SMEM_BYTES);
    cudaFuncSetAttribute(gemm_mma<0>,
                         cudaFuncAttributeMaxDynamicSharedMemorySize,
                         GEMM_SMEM);
    cudaFuncSetAttribute(gemm_mma<1>,
                         cudaFuncAttributeMaxDynamicSharedMemorySize,
                         GEMM_SMEM);

    prep_split<<<2048, 256>>>(w_qkv, w_proj);
    ln_kernel<<<ROWS, 128>>>(x, gamma, beta);
    gemm_mma<0><<<dim3(TRIPLE / 64, ROWS / 128), 256, GEMM_SMEM>>>(nullptr, nullptr);
    flash_mma<<<dim3(SEQ / 64, BATCH * HEADS), 128, FLASH_SMEM_BYTES>>>();
    gemm_mma<1><<<dim3(DIM / 64, ROWS / 128), 256, GEMM_SMEM>>>(b_proj, out);
}

// round 13
// speedup vs baseline: 3.7190x; 1.0657x over previous
#include <cuda_runtime.h>
#include <cuda_bf16.h>
#include <stdint.h>
#include <math.h>

// Problem constants
#define BATCH   8
#define SEQ     2048
#define DIM     512
#define HEADS   8
#define ROWS    (BATCH * SEQ)          // 16384
#define TRIPLE  (3 * DIM)              // 1536
#define SSTR    72                     // smem row stride in bf16 (144B)

// q pre-scale: 1/sqrt(64) * log2(e), so softmax uses 2^x
#define QSCALE  (0.125f * 1.44269504088896f)

// ---------------- scratch (device globals; no runtime allocation) ----------
__device__ __nv_bfloat16 g_xh [ROWS * DIM], g_xl [ROWS * DIM];   // LN out [row][512]
__device__ __nv_bfloat16 g_wqh[TRIPLE * DIM], g_wql[TRIPLE * DIM];
__device__ __nv_bfloat16 g_wph[DIM * DIM],    g_wpl[DIM * DIM];
__device__ __nv_bfloat16 g_qh [ROWS * DIM], g_ql [ROWS * DIM];   // [bh][n][64], q pre-scaled
__device__ __nv_bfloat16 g_kh [ROWS * DIM], g_kl [ROWS * DIM];   // [bh][n][64]
__device__ __nv_bfloat16 g_vh [ROWS * DIM], g_vl [ROWS * DIM];   // [bh][n][64]
__device__ __nv_bfloat16 g_ah [ROWS * DIM], g_al [ROWS * DIM];   // attn out [b][n][512]

// ---------------- helpers ---------------------------------------------------
__device__ __forceinline__ void split_pack(float x, float y,
                                           uint32_t& hi, uint32_t& lo)
{
    __nv_bfloat16 hx = __float2bfloat16(x);
    __nv_bfloat16 hy = __float2bfloat16(y);
    __nv_bfloat16 lx = __float2bfloat16(x - __bfloat162float(hx));
    __nv_bfloat16 ly = __float2bfloat16(y - __bfloat162float(hy));
    __nv_bfloat162 h2; h2.x = hx; h2.y = hy;
    __nv_bfloat162 l2; l2.x = lx; l2.y = ly;
    hi = *reinterpret_cast<uint32_t*>(&h2);
    lo = *reinterpret_cast<uint32_t*>(&l2);
}

__device__ __forceinline__ void mma_bf16(float* c, const uint32_t* a,
                                         uint32_t b0, uint32_t b1)
{
    asm volatile(
        "mma.sync.aligned.m16n8k16.row.col.f32.bf16.bf16.f32 "
        "{%0,%1,%2,%3}, {%4,%5,%6,%7}, {%8,%9}, {%0,%1,%2,%3};\n"
        : "+f"(c[0]), "+f"(c[1]), "+f"(c[2]), "+f"(c[3])
        : "r"(a[0]), "r"(a[1]), "r"(a[2]), "r"(a[3]), "r"(b0), "r"(b1));
}

__device__ __forceinline__ uint32_t sptr(const void* p)
{
    return (uint32_t)__cvta_generic_to_shared(p);
}

__device__ __forceinline__ void ldsm_x4(uint32_t* r, uint32_t addr)
{
    asm volatile(
        "ldmatrix.sync.aligned.m8n8.x4.shared.b16 {%0,%1,%2,%3}, [%4];\n"
        : "=r"(r[0]), "=r"(r[1]), "=r"(r[2]), "=r"(r[3]) : "r"(addr));
}

__device__ __forceinline__ void ldsm_x4_t(uint32_t* r, uint32_t addr)
{
    asm volatile(
        "ldmatrix.sync.aligned.m8n8.x4.trans.shared.b16 {%0,%1,%2,%3}, [%4];\n"
        : "=r"(r[0]), "=r"(r[1]), "=r"(r[2]), "=r"(r[3]) : "r"(addr));
}

__device__ __forceinline__ void cpa16(uint32_t saddr, const void* gaddr)
{
    asm volatile("cp.async.cg.shared.global [%0], [%1], 16;\n"
                 :: "r"(saddr), "l"(gaddr));
}

__device__ __forceinline__ void cpa_commit()
{
    asm volatile("cp.async.commit_group;\n");
}

template<int N>
__device__ __forceinline__ void cpa_wait()
{
    asm volatile("cp.async.wait_group %0;\n" :: "n"(N));
}

__device__ __forceinline__ float ex2(float x)
{
    float y;
    asm("ex2.approx.ftz.f32 %0, %1;" : "=f"(y) : "f"(x));
    return y;
}

// ========================= weight split (one-off) =========================
__global__ void __launch_bounds__(256)
prep_split(const float* __restrict__ wq, const float* __restrict__ wp)
{
    const int NQ = TRIPLE * DIM / 2;
    const int NP = DIM * DIM / 2;
    int idx = blockIdx.x * 256 + threadIdx.x;
    if (idx < NQ) {
        float2 v = reinterpret_cast<const float2*>(wq)[idx];
        uint32_t h, l; split_pack(v.x, v.y, h, l);
        reinterpret_cast<uint32_t*>(g_wqh)[idx] = h;
        reinterpret_cast<uint32_t*>(g_wql)[idx] = l;
    } else if (idx < NQ + NP) {
        int j = idx - NQ;
        float2 v = reinterpret_cast<const float2*>(wp)[j];
        uint32_t h, l; split_pack(v.x, v.y, h, l);
        reinterpret_cast<uint32_t*>(g_wph)[j] = h;
        reinterpret_cast<uint32_t*>(g_wpl)[j] = l;
    }
}

// ========================= LayerNorm (warp per row) =======================
// 256 thr = 8 warps, 8 rows/block, grid 2048. Pure shfl reductions.
__global__ void __launch_bounds__(256)
ln_kernel(const float* __restrict__ x,
          const float* __restrict__ gamma,
          const float* __restrict__ beta)
{
    int warp = threadIdx.x >> 5, lane = threadIdx.x & 31;
    int row  = blockIdx.x * 8 + warp;

    const float4* xr = reinterpret_cast<const float4*>(x + (size_t)row * 512);
    float4 v[4];
    float s = 0.0f;
    #pragma unroll
    for (int j = 0; j < 4; j++) {
        v[j] = xr[j * 32 + lane];
        s += v[j].x + v[j].y + v[j].z + v[j].w;
    }
    #pragma unroll
    for (int o = 16; o; o >>= 1) s += __shfl_xor_sync(0xffffffffu, s, o);
    float mu = s * (1.0f / 512.0f);

    float s2 = 0.0f;
    #pragma unroll
    for (int j = 0; j < 4; j++) {
        v[j].x -= mu; v[j].y -= mu; v[j].z -= mu; v[j].w -= mu;
        s2 += v[j].x*v[j].x + v[j].y*v[j].y + v[j].z*v[j].z + v[j].w*v[j].w;
    }
    #pragma unroll
    for (int o = 16; o; o >>= 1) s2 += __shfl_xor_sync(0xffffffffu, s2, o);
    float rstd = rsqrtf(s2 * (1.0f / 512.0f) + 1e-6f);

    #pragma unroll
    for (int j = 0; j < 4; j++) {
        float4 g  = reinterpret_cast<const float4*>(gamma)[j * 32 + lane];
        float4 bb = reinterpret_cast<const float4*>(beta)[j * 32 + lane];
        float o0 = v[j].x * rstd * g.x + bb.x;
        float o1 = v[j].y * rstd * g.y + bb.y;
        float o2 = v[j].z * rstd * g.z + bb.z;
        float o3 = v[j].w * rstd * g.w + bb.w;
        uint32_t h0, l0, h1, l1;
        split_pack(o0, o1, h0, l0);
        split_pack(o2, o3, h1, l1);
        int col = j * 128 + lane * 4;
        *reinterpret_cast<uint2*>(&g_xh[(size_t)row * 512 + col]) = make_uint2(h0, h1);
        *reinterpret_cast<uint2*>(&g_xl[(size_t)row * 512 + col]) = make_uint2(l0, l1);
    }
}

// ========================= GEMM (bf16x3, ldmatrix, cp.async dbl-buf) ======
// C[m,c] = sum_k A[m,k] * W[c,k].  Block 128m x 64n, k-chunk 64, 8 chunks.
// MODE 0: qkv -> split bf16 q/k/v scatter; MODE 1: proj -> f32 out + bias.
#define GBUF (384 * SSTR)                       // elems per buffer
#define GEMM_SMEM (2 * GBUF * 2)                // 110592 bytes

template<int MODE>
__global__ void __launch_bounds__(256)
gemm_mma(const float* __restrict__ bias, float* __restrict__ out)
{
    extern __shared__ __nv_bfloat16 sm[];
    // buffer b: [As_h(128) | As_l(128) | Bs_h(64) | Bs_l(64)] rows of SSTR

    const __nv_bfloat16* Ah_g = (MODE == 0) ? g_xh : g_ah;
    const __nv_bfloat16* Al_g = (MODE == 0) ? g_xl : g_al;
    const __nv_bfloat16* Wh_g = (MODE == 0) ? g_wqh : g_wph;
    const __nv_bfloat16* Wl_g = (MODE == 0) ? g_wql : g_wpl;

    int tid = threadIdx.x, lane = tid & 31, warp = tid >> 5;
    int g = lane >> 2, t4 = lane & 3;
    int wm = warp & 3, wn = warp >> 2;
    int m0 = wm * 32, n0 = wn * 32;
    int bm0 = blockIdx.y * 128, bn0 = blockIdx.x * 64;
    int qS = tid & 7;

    auto issue = [&](int chunk) {
        if (chunk < 8) {
            __nv_bfloat16* base = sm + (chunk & 1) * GBUF;
            int k0 = chunk * 64;
            #pragma unroll
            for (int j = 0; j < 4; j++) {
                int r = (tid + j * 256) >> 3;
                size_t go = (size_t)(bm0 + r) * 512 + k0 + qS * 8;
                int so = r * SSTR + qS * 8;
                cpa16(sptr(base + so),              Ah_g + go);
                cpa16(sptr(base + 128 * SSTR + so), Al_g + go);
            }
            #pragma unroll
            for (int j = 0; j < 2; j++) {
                int r = (tid + j * 256) >> 3;
                size_t go = (size_t)(bn0 + r) * 512 + k0 + qS * 8;
                int so = r * SSTR + qS * 8;
                cpa16(sptr(base + 256 * SSTR + so), Wh_g + go);
                cpa16(sptr(base + 320 * SSTR + so), Wl_g + go);
            }
        }
        cpa_commit();
    };

    issue(0);
    issue(1);

    float acc[2][4][4] = {};

    for (int c = 0; c < 8; c++) {
        cpa_wait<1>();
        __syncthreads();
        __nv_bfloat16* base = sm + (c & 1) * GBUF;
        __nv_bfloat16* As_h = base;
        __nv_bfloat16* As_l = base + 128 * SSTR;
        __nv_bfloat16* Bs_h = base + 256 * SSTR;
        __nv_bfloat16* Bs_l = base + 320 * SSTR;

        #pragma unroll
        for (int kcp = 0; kcp < 2; kcp++) {
            uint32_t ah[2][2][4], al[2][2][4];
            #pragma unroll
            for (int kk = 0; kk < 2; kk++)
                #pragma unroll
                for (int im = 0; im < 2; im++) {
                    int row = m0 + im * 16 + (lane & 15);
                    int col = kcp * 32 + kk * 16 + (lane >> 4) * 8;
                    ldsm_x4(ah[kk][im], sptr(&As_h[row * SSTR + col]));
                    ldsm_x4(al[kk][im], sptr(&As_l[row * SSTR + col]));
                }
            #pragma unroll
            for (int nf = 0; nf < 4; nf++) {
                uint32_t b4h[4], b4l[4];
                int rowb = n0 + nf * 8 + (lane & 7);
                int colb = kcp * 32 + (lane >> 3) * 8;
                ldsm_x4(b4h, sptr(&Bs_h[rowb * SSTR + colb]));
                ldsm_x4(b4l, sptr(&Bs_l[rowb * SSTR + colb]));
                #pragma unroll
                for (int kk = 0; kk < 2; kk++)
                    #pragma unroll
                    for (int im = 0; im < 2; im++) {
                        mma_bf16(acc[im][nf], ah[kk][im], b4h[2*kk], b4h[2*kk+1]);
                        mma_bf16(acc[im][nf], ah[kk][im], b4l[2*kk], b4l[2*kk+1]);
                        mma_bf16(acc[im][nf], al[kk][im], b4h[2*kk], b4h[2*kk+1]);
                    }
            }
        }
        __syncthreads();
        issue(c + 2);
    }

    if (MODE == 0) {
        int which = bn0 >> 9;
        int h     = (bn0 & 511) >> 6;
        __nv_bfloat16* dh = (which == 0) ? g_qh : (which == 1) ? g_kh : g_vh;
        __nv_bfloat16* dl = (which == 0) ? g_ql : (which == 1) ? g_kl : g_vl;
        float scl = (which == 0) ? QSCALE : 1.0f;
        #pragma unroll
        for (int im = 0; im < 2; im++) {
            #pragma unroll
            for (int nf = 0; nf < 4; nf++) {
                int d = n0 + nf * 8 + 2 * t4;
                int m = bm0 + m0 + im * 16 + g;
                int b = m >> 11, n = m & 2047;
                size_t off = ((size_t)((b << 3) + h) * 2048 + n) * 64 + d;
                uint32_t h0, l0;
                split_pack(acc[im][nf][0] * scl, acc[im][nf][1] * scl, h0, l0);
                *reinterpret_cast<uint32_t*>(&dh[off]) = h0;
                *reinterpret_cast<uint32_t*>(&dl[off]) = l0;
                split_pack(acc[im][nf][2] * scl, acc[im][nf][3] * scl, h0, l0);
                *reinterpret_cast<uint32_t*>(&dh[off + 8 * 64]) = h0;
                *reinterpret_cast<uint32_t*>(&dl[off + 8 * 64]) = l0;
            }
        }
    } else {
        #pragma unroll
        for (int im = 0; im < 2; im++) {
            #pragma unroll
            for (int nf = 0; nf < 4; nf++) {
                int col = bn0 + n0 + nf * 8 + 2 * t4;
                float2 bi = *reinterpret_cast<const float2*>(&bias[col]);
                int m = bm0 + m0 + im * 16 + g;
                float2 v0 = make_float2(acc[im][nf][0] + bi.x, acc[im][nf][1] + bi.y);
                float2 v1 = make_float2(acc[im][nf][2] + bi.x, acc[im][nf][3] + bi.y);
                *reinterpret_cast<float2*>(&out[(size_t)m * 512 + col])       = v0;
                *reinterpret_cast<float2*>(&out[(size_t)(m + 8) * 512 + col]) = v1;
            }
        }
    }
}

// ========================= Flash attention (3 CTA/SM, K dbl + V single) ===
// grid (32 q-tiles, 64 bh), 128 thr = 4 warps; warp w owns q rows [16w,16w+16).
// q pre-scaled by log2(e)/8; softmax in base-2 via ex2.
#define FSM (64 * SSTR)                       // 4608 bf16 per tile
#define FLASH_SMEM_BYTES (8 * FSM * 2)        // 73728

__global__ void __launch_bounds__(128, 3)
flash_mma()
{
    extern __shared__ __nv_bfloat16 sm[];
    __nv_bfloat16* Qhs = sm;
    __nv_bfloat16* Qls = sm + FSM;
    // K buffer b (0,1): base sm + (2+2b)*FSM -> [Kh | Kl]
    __nv_bfloat16* Vhs = sm + 6 * FSM;
    __nv_bfloat16* Vls = sm + 7 * FSM;

    int bh = blockIdx.y, qt = blockIdx.x;
    int tid = threadIdx.x, lane = tid & 31, warp = tid >> 5;
    int g = lane >> 2, t4 = lane & 3;
    int qS = tid & 7;

    int srow[4];
    #pragma unroll
    for (int j = 0; j < 4; j++) srow[j] = (tid + j * 128) >> 3;
    size_t bhoff = (size_t)bh * 2048 * 64;

    auto issue_k = [&](int kt) {
        if (kt < 32) {
            __nv_bfloat16* base = sm + (2 + 2 * (kt & 1)) * FSM;
            size_t koff = bhoff + (size_t)kt * 64 * 64;
            #pragma unroll
            for (int j = 0; j < 4; j++) {
                int r = srow[j];
                size_t go = koff + (size_t)r * 64 + qS * 8;
                int so = r * SSTR + qS * 8;
                cpa16(sptr(base + so),       g_kh + go);
                cpa16(sptr(base + FSM + so), g_kl + go);
            }
        }
        cpa_commit();
    };
    auto issue_v = [&](int kt) {
        if (kt < 32) {
            size_t koff = bhoff + (size_t)kt * 64 * 64;
            #pragma unroll
            for (int j = 0; j < 4; j++) {
                int r = srow[j];
                size_t go = koff + (size_t)r * 64 + qS * 8;
                int so = r * SSTR + qS * 8;
                cpa16(sptr(Vhs + so), g_vh + go);
                cpa16(sptr(Vls + so), g_vl + go);
            }
        }
        cpa_commit();
    };

    issue_k(0);
    issue_v(0);
    issue_k(1);

    size_t qoff = bhoff + (size_t)qt * 64 * 64;
    #pragma unroll
    for (int j = 0; j < 4; j++) {
        int r = srow[j];
        *reinterpret_cast<uint4*>(&Qhs[r * SSTR + qS * 8]) =
            *reinterpret_cast<const uint4*>(g_qh + qoff + (size_t)r * 64 + qS * 8);
        *reinterpret_cast<uint4*>(&Qls[r * SSTR + qS * 8]) =
            *reinterpret_cast<const uint4*>(g_ql + qoff + (size_t)r * 64 + qS * 8);
    }
    __syncthreads();

    uint32_t qh[4][4];
    #pragma unroll
    for (int kc = 0; kc < 4; kc++) {
        int row = warp * 16 + (lane & 15);
        int col = kc * 16 + (lane >> 4) * 8;
        ldsm_x4(qh[kc], sptr(&Qhs[row * SSTR + col]));
    }

    float o[8][4] = {};
    float rm0 = -1e30f, rm1 = -1e30f, rl0 = 0.0f, rl1 = 0.0f;

    for (int kt = 0; kt < 32; kt++) {
        cpa_wait<2>();          // Kg(kt) complete
        __syncthreads();

        __nv_bfloat16* kbase = sm + (2 + 2 * (kt & 1)) * FSM;
        __nv_bfloat16* Khs = kbase;
        __nv_bfloat16* Kls = kbase + FSM;

        // ---- S = Q K^T ----
        float s[8][4] = {};
        #pragma unroll
        for (int kcp = 0; kcp < 2; kcp++) {
            uint32_t ql2[2][4];
            #pragma unroll
            for (int kk = 0; kk < 2; kk++) {
                int row = warp * 16 + (lane & 15);
                int col = (kcp * 2 + kk) * 16 + (lane >> 4) * 8;
                ldsm_x4(ql2[kk], sptr(&Qls[row * SSTR + col]));
            }
            #pragma unroll
            for (int nf = 0; nf < 8; nf++) {
                int rowb = nf * 8 + (lane & 7);
                int colb = kcp * 32 + (lane >> 3) * 8;
                uint32_t b4h[4], b4l[4];
                ldsm_x4(b4h, sptr(&Khs[rowb * SSTR + colb]));
                ldsm_x4(b4l, sptr(&Kls[rowb * SSTR + colb]));
                #pragma unroll
                for (int kk = 0; kk < 2; kk++) {
                    int kc = kcp * 2 + kk;
                    mma_bf16(s[nf], qh[kc],  b4h[2*kk], b4h[2*kk+1]);
                    mma_bf16(s[nf], qh[kc],  b4l[2*kk], b4l[2*kk+1]);
                    mma_bf16(s[nf], ql2[kk], b4h[2*kk], b4h[2*kk+1]);
                }
            }
        }

        // ---- online softmax (base-2, registers, quad reductions) ----
        float mx0 = -1e30f, mx1 = -1e30f;
        #pragma unroll
        for (int nf = 0; nf < 8; nf++) {
            mx0 = fmaxf(mx0, fmaxf(s[nf][0], s[nf][1]));
            mx1 = fmaxf(mx1, fmaxf(s[nf][2], s[nf][3]));
        }
        mx0 = fmaxf(mx0, __shfl_xor_sync(0xffffffffu, mx0, 1));
        mx0 = fmaxf(mx0, __shfl_xor_sync(0xffffffffu, mx0, 2));
        mx1 = fmaxf(mx1, __shfl_xor_sync(0xffffffffu, mx1, 1));
        mx1 = fmaxf(mx1, __shfl_xor_sync(0xffffffffu, mx1, 2));
        float mn0 = fmaxf(rm0, mx0);
        float mn1 = fmaxf(rm1, mx1);

        float sum0 = 0.0f, sum1 = 0.0f;
        #pragma unroll
        for (int nf = 0; nf < 8; nf++) {
            s[nf][0] = ex2(s[nf][0] - mn0);
            s[nf][1] = ex2(s[nf][1] - mn0);
            s[nf][2] = ex2(s[nf][2] - mn1);
            s[nf][3] = ex2(s[nf][3] - mn1);
            sum0 += s[nf][0] + s[nf][1];
            sum1 += s[nf][2] + s[nf][3];
        }
        sum0 += __shfl_xor_sync(0xffffffffu, sum0, 1);
        sum0 += __shfl_xor_sync(0xffffffffu, sum0, 2);
        sum1 += __shfl_xor_sync(0xffffffffu, sum1, 1);
        sum1 += __shfl_xor_sync(0xffffffffu, sum1, 2);

        float sc0 = ex2(rm0 - mn0);
        float sc1 = ex2(rm1 - mn1);
        rm0 = mn0; rm1 = mn1;
        rl0 = rl0 * sc0 + sum0;
        rl1 = rl1 * sc1 + sum1;
        #pragma unroll
        for (int nf = 0; nf < 8; nf++) {
            o[nf][0] *= sc0; o[nf][1] *= sc0;
            o[nf][2] *= sc1; o[nf][3] *= sc1;
        }

        // ---- V arrival, then PV ----
        cpa_wait<1>();          // Vg(kt) complete (Kg(kt+1) still in flight)
        __syncthreads();

        #pragma unroll
        for (int kcp = 0; kcp < 2; kcp++) {
            uint32_t ph[2][4], pl[2][4];
            #pragma unroll
            for (int kk = 0; kk < 2; kk++) {
                int kc = kcp * 2 + kk;
                split_pack(s[2*kc][0],   s[2*kc][1],   ph[kk][0], pl[kk][0]);
                split_pack(s[2*kc][2],   s[2*kc][3],   ph[kk][1], pl[kk][1]);
                split_pack(s[2*kc+1][0], s[2*kc+1][1], ph[kk][2], pl[kk][2]);
                split_pack(s[2*kc+1][2], s[2*kc+1][3], ph[kk][3], pl[kk][3]);
            }
            #pragma unroll
            for (int nf = 0; nf < 8; nf++) {
                uint32_t b4h[4], b4l[4];
                int rowv = kcp * 32 + lane;
                int colv = nf * 8;
                ldsm_x4_t(b4h, sptr(&Vhs[rowv * SSTR + colv]));
                ldsm_x4_t(b4l, sptr(&Vls[rowv * SSTR + colv]));
                #pragma unroll
                for (int kk = 0; kk < 2; kk++) {
                    mma_bf16(o[nf], ph[kk], b4h[2*kk], b4h[2*kk+1]);
                    mma_bf16(o[nf], ph[kk], b4l[2*kk], b4l[2*kk+1]);
                    mma_bf16(o[nf], pl[kk], b4h[2*kk], b4h[2*kk+1]);
                }
            }
        }
        __syncthreads();        // all warps done with V buf + K buf (kt&1)

        issue_v(kt + 1);
        issue_k(kt + 2);
    }

    // ---- epilogue: normalize, split, write g_ah/g_al [b][n][512] ----
    int b = bh >> 3, h = bh & 7;
    float inv0 = 1.0f / rl0;
    float inv1 = 1.0f / rl1;
    int r0 = qt * 64 + warp * 16 + g;
    int r1 = r0 + 8;
    #pragma unroll
    for (int nf = 0; nf < 8; nf++) {
        int col = h * 64 + nf * 8 + 2 * t4;
        uint32_t h0, l0;
        split_pack(o[nf][0] * inv0, o[nf][1] * inv0, h0, l0);
        *reinterpret_cast<uint32_t*>(&g_ah[((size_t)b * 2048 + r0) * 512 + col]) = h0;
        *reinterpret_cast<uint32_t*>(&g_al[((size_t)b * 2048 + r0) * 512 + col]) = l0;
        split_pack(o[nf][2] * inv1, o[nf][3] * inv1, h0, l0);
        *reinterpret_cast<uint32_t*>(&g_ah[((size_t)b * 2048 + r1) * 512 + col]) = h0;
        *reinterpret_cast<uint32_t*>(&g_al[((size_t)b * 2048 + r1) * 512 + col]) = l0;
    }
}

// ========================= launch =========================================
extern "C" void kernel_launch(void* const* d_in, const int* in_sizes, int n_in,
                              void* d_out, int out_size)
{
    const float* x      = (const float*)d_in[0];
    const float* w_qkv  = (const float*)d_in[1];
    const float* w_proj = (const float*)d_in[2];
    const float* b_proj = (const float*)d_in[3];
    const float* gamma  = (const float*)d_in[4];
    const float* beta   = (const float*)d_in[5];
    float* out = (float*)d_out;

    cudaFuncSetAttribute(flash_mma,
                         cudaFuncAttributeMaxDynamicSharedMemorySize,
                         FLASH_SMEM_BYTES);
    cudaFuncSetAttribute(gemm_mma<0>,
                         cudaFuncAttributeMaxDynamicSharedMemorySize,
                         GEMM_SMEM);
    cudaFuncSetAttribute(gemm_mma<1>,
                         cudaFuncAttributeMaxDynamicSharedMemorySize,
                         GEMM_SMEM);

    prep_split<<<2048, 256>>>(w_qkv, w_proj);
    ln_kernel<<<ROWS / 8, 256>>>(x, gamma, beta);
    gemm_mma<0><<<dim3(TRIPLE / 64, ROWS / 128), 256, GEMM_SMEM>>>(nullptr, nullptr);
    flash_mma<<<dim3(SEQ / 64, BATCH * HEADS), 128, FLASH_SMEM_BYTES>>>();
    gemm_mma<1><<<dim3(DIM / 64, ROWS / 128), 256, GEMM_SMEM>>>(b_proj, out);
}

// round 15
// speedup vs baseline: 3.7352x; 1.0044x over previous
#include <cuda_runtime.h>
#include <cuda_bf16.h>
#include <stdint.h>
#include <math.h>

// Problem constants
#define BATCH   8
#define SEQ     2048
#define DIM     512
#define HEADS   8
#define ROWS    (BATCH * SEQ)          // 16384
#define TRIPLE  (3 * DIM)              // 1536
#define SSTR    72                     // smem row stride in bf16 (144B)

// q pre-scale: 1/sqrt(64) * log2(e), softmax in base-2
#define QSCALE  (0.125f * 1.44269504088896f)

// ---------------- scratch (device globals; no runtime allocation) ----------
__device__ __nv_bfloat16 g_xh [ROWS * DIM], g_xl [ROWS * DIM];   // LN out [row][512]
__device__ __nv_bfloat16 g_wqh[TRIPLE * DIM], g_wql[TRIPLE * DIM];
__device__ __nv_bfloat16 g_wph[DIM * DIM],    g_wpl[DIM * DIM];
__device__ __nv_bfloat16 g_qh [ROWS * DIM], g_ql [ROWS * DIM];   // [bh][n][64], q pre-scaled
__device__ __nv_bfloat16 g_kh [ROWS * DIM], g_kl [ROWS * DIM];   // [bh][n][64]
__device__ __nv_bfloat16 g_vh [ROWS * DIM], g_vl [ROWS * DIM];   // [bh][n][64]
__device__ __nv_bfloat16 g_ah [ROWS * DIM], g_al [ROWS * DIM];   // attn out [b][n][512]

// ---------------- helpers ---------------------------------------------------
// Fast hi/lo split: hi = truncated-bf16 pair via PRMT (exact), lo = rounded
// residuals packed by one cvt.rn.bf16x2.f32.  ~6 SASS vs ~11 for the CVT chain.
__device__ __forceinline__ void split_pack(float x, float y,
                                           uint32_t& hi, uint32_t& lo)
{
    uint32_t bx = __float_as_uint(x), by = __float_as_uint(y);
    hi = __byte_perm(bx, by, 0x7632);                 // {y.hi16, x.hi16}
    float lx = x - __uint_as_float(bx & 0xFFFF0000u);
    float ly = y - __uint_as_float(by & 0xFFFF0000u);
    asm("cvt.rn.bf16x2.f32 %0, %1, %2;" : "=r"(lo) : "f"(ly), "f"(lx));
}

__device__ __forceinline__ void mma_bf16(float* c, const uint32_t* a,
                                         uint32_t b0, uint32_t b1)
{
    asm volatile(
        "mma.sync.aligned.m16n8k16.row.col.f32.bf16.bf16.f32 "
        "{%0,%1,%2,%3}, {%4,%5,%6,%7}, {%8,%9}, {%0,%1,%2,%3};\n"
        : "+f"(c[0]), "+f"(c[1]), "+f"(c[2]), "+f"(c[3])
        : "r"(a[0]), "r"(a[1]), "r"(a[2]), "r"(a[3]), "r"(b0), "r"(b1));
}

__device__ __forceinline__ uint32_t sptr(const void* p)
{
    return (uint32_t)__cvta_generic_to_shared(p);
}

__device__ __forceinline__ void ldsm_x4(uint32_t* r, uint32_t addr)
{
    asm volatile(
        "ldmatrix.sync.aligned.m8n8.x4.shared.b16 {%0,%1,%2,%3}, [%4];\n"
        : "=r"(r[0]), "=r"(r[1]), "=r"(r[2]), "=r"(r[3]) : "r"(addr));
}

__device__ __forceinline__ void ldsm_x4_t(uint32_t* r, uint32_t addr)
{
    asm volatile(
        "ldmatrix.sync.aligned.m8n8.x4.trans.shared.b16 {%0,%1,%2,%3}, [%4];\n"
        : "=r"(r[0]), "=r"(r[1]), "=r"(r[2]), "=r"(r[3]) : "r"(addr));
}

__device__ __forceinline__ void cpa16(uint32_t saddr, const void* gaddr)
{
    asm volatile("cp.async.cg.shared.global [%0], [%1], 16;\n"
                 :: "r"(saddr), "l"(gaddr));
}

__device__ __forceinline__ void cpa_commit()
{
    asm volatile("cp.async.commit_group;\n");
}

template<int N>
__device__ __forceinline__ void cpa_wait()
{
    asm volatile("cp.async.wait_group %0;\n" :: "n"(N));
}

__device__ __forceinline__ float ex2(float x)
{
    float y;
    asm("ex2.approx.ftz.f32 %0, %1;" : "=f"(y) : "f"(x));
    return y;
}

// ========================= weight split (one-off) =========================
__global__ void __launch_bounds__(256)
prep_split(const float* __restrict__ wq, const float* __restrict__ wp)
{
    const int NQ = TRIPLE * DIM / 2;
    const int NP = DIM * DIM / 2;
    int idx = blockIdx.x * 256 + threadIdx.x;
    if (idx < NQ) {
        float2 v = reinterpret_cast<const float2*>(wq)[idx];
        uint32_t h, l; split_pack(v.x, v.y, h, l);
        reinterpret_cast<uint32_t*>(g_wqh)[idx] = h;
        reinterpret_cast<uint32_t*>(g_wql)[idx] = l;
    } else if (idx < NQ + NP) {
        int j = idx - NQ;
        float2 v = reinterpret_cast<const float2*>(wp)[j];
        uint32_t h, l; split_pack(v.x, v.y, h, l);
        reinterpret_cast<uint32_t*>(g_wph)[j] = h;
        reinterpret_cast<uint32_t*>(g_wpl)[j] = l;
    }
}

// ========================= LayerNorm (warp per row) =======================
__global__ void __launch_bounds__(256)
ln_kernel(const float* __restrict__ x,
          const float* __restrict__ gamma,
          const float* __restrict__ beta)
{
    int warp = threadIdx.x >> 5, lane = threadIdx.x & 31;
    int row  = blockIdx.x * 8 + warp;

    const float4* xr = reinterpret_cast<const float4*>(x + (size_t)row * 512);
    float4 v[4];
    float s = 0.0f;
    #pragma unroll
    for (int j = 0; j < 4; j++) {
        v[j] = xr[j * 32 + lane];
        s += v[j].x + v[j].y + v[j].z + v[j].w;
    }
    #pragma unroll
    for (int o = 16; o; o >>= 1) s += __shfl_xor_sync(0xffffffffu, s, o);
    float mu = s * (1.0f / 512.0f);

    float s2 = 0.0f;
    #pragma unroll
    for (int j = 0; j < 4; j++) {
        v[j].x -= mu; v[j].y -= mu; v[j].z -= mu; v[j].w -= mu;
        s2 += v[j].x*v[j].x + v[j].y*v[j].y + v[j].z*v[j].z + v[j].w*v[j].w;
    }
    #pragma unroll
    for (int o = 16; o; o >>= 1) s2 += __shfl_xor_sync(0xffffffffu, s2, o);
    float rstd = rsqrtf(s2 * (1.0f / 512.0f) + 1e-6f);

    #pragma unroll
    for (int j = 0; j < 4; j++) {
        float4 g  = reinterpret_cast<const float4*>(gamma)[j * 32 + lane];
        float4 bb = reinterpret_cast<const float4*>(beta)[j * 32 + lane];
        float o0 = v[j].x * rstd * g.x + bb.x;
        float o1 = v[j].y * rstd * g.y + bb.y;
        float o2 = v[j].z * rstd * g.z + bb.z;
        float o3 = v[j].w * rstd * g.w + bb.w;
        uint32_t h0, l0, h1, l1;
        split_pack(o0, o1, h0, l0);
        split_pack(o2, o3, h1, l1);
        int col = j * 128 + lane * 4;
        *reinterpret_cast<uint2*>(&g_xh[(size_t)row * 512 + col]) = make_uint2(h0, h1);
        *reinterpret_cast<uint2*>(&g_xl[(size_t)row * 512 + col]) = make_uint2(l0, l1);
    }
}

// ========================= GEMM (bf16x3, ldmatrix, cp.async dbl-buf) ======
// C[m,c] = sum_k A[m,k] * W[c,k].  Block 128m x 64n, k-chunk 64, 8 chunks.
// MODE 0: qkv -> split bf16 q/k/v scatter; MODE 1: proj -> f32 out + bias.
#define GBUF (384 * SSTR)                       // elems per buffer
#define GEMM_SMEM (2 * GBUF * 2)                // 110592 bytes

template<int MODE>
__global__ void __launch_bounds__(256)
gemm_mma(const float* __restrict__ bias, float* __restrict__ out)
{
    extern __shared__ __nv_bfloat16 sm[];
    // buffer b: [As_h(128) | As_l(128) | Bs_h(64) | Bs_l(64)] rows of SSTR

    const __nv_bfloat16* Ah_g = (MODE == 0) ? g_xh : g_ah;
    const __nv_bfloat16* Al_g = (MODE == 0) ? g_xl : g_al;
    const __nv_bfloat16* Wh_g = (MODE == 0) ? g_wqh : g_wph;
    const __nv_bfloat16* Wl_g = (MODE == 0) ? g_wql : g_wpl;

    int tid = threadIdx.x, lane = tid & 31, warp = tid >> 5;
    int g = lane >> 2, t4 = lane & 3;
    int wm = warp & 3, wn = warp >> 2;
    int m0 = wm * 32, n0 = wn * 32;
    int bm0 = blockIdx.y * 128, bn0 = blockIdx.x * 64;
    int qS = tid & 7;

    auto issue = [&](int chunk) {
        if (chunk < 8) {
            __nv_bfloat16* base = sm + (chunk & 1) * GBUF;
            int k0 = chunk * 64;
            #pragma unroll
            for (int j = 0; j < 4; j++) {
                int r = (tid + j * 256) >> 3;
                size_t go = (size_t)(bm0 + r) * 512 + k0 + qS * 8;
                int so = r * SSTR + qS * 8;
                cpa16(sptr(base + so),              Ah_g + go);
                cpa16(sptr(base + 128 * SSTR + so), Al_g + go);
            }
            #pragma unroll
            for (int j = 0; j < 2; j++) {
                int r = (tid + j * 256) >> 3;
                size_t go = (size_t)(bn0 + r) * 512 + k0 + qS * 8;
                int so = r * SSTR + qS * 8;
                cpa16(sptr(base + 256 * SSTR + so), Wh_g + go);
                cpa16(sptr(base + 320 * SSTR + so), Wl_g + go);
            }
        }
        cpa_commit();
    };

    issue(0);
    issue(1);

    float acc[2][4][4] = {};

    for (int c = 0; c < 8; c++) {
        cpa_wait<1>();
        __syncthreads();
        __nv_bfloat16* base = sm + (c & 1) * GBUF;
        __nv_bfloat16* As_h = base;
        __nv_bfloat16* As_l = base + 128 * SSTR;
        __nv_bfloat16* Bs_h = base + 256 * SSTR;
        __nv_bfloat16* Bs_l = base + 320 * SSTR;

        #pragma unroll
        for (int kcp = 0; kcp < 2; kcp++) {
            uint32_t ah[2][2][4], al[2][2][4];
            #pragma unroll
            for (int kk = 0; kk < 2; kk++)
                #pragma unroll
                for (int im = 0; im < 2; im++) {
                    int row = m0 + im * 16 + (lane & 15);
                    int col = kcp * 32 + kk * 16 + (lane >> 4) * 8;
                    ldsm_x4(ah[kk][im], sptr(&As_h[row * SSTR + col]));
                    ldsm_x4(al[kk][im], sptr(&As_l[row * SSTR + col]));
                }
            #pragma unroll
            for (int nf = 0; nf < 4; nf++) {
                uint32_t b4h[4], b4l[4];
                int rowb = n0 + nf * 8 + (lane & 7);
                int colb = kcp * 32 + (lane >> 3) * 8;
                ldsm_x4(b4h, sptr(&Bs_h[rowb * SSTR + colb]));
                ldsm_x4(b4l, sptr(&Bs_l[rowb * SSTR + colb]));
                #pragma unroll
                for (int kk = 0; kk < 2; kk++)
                    #pragma unroll
                    for (int im = 0; im < 2; im++) {
                        mma_bf16(acc[im][nf], ah[kk][im], b4h[2*kk], b4h[2*kk+1]);
                        mma_bf16(acc[im][nf], ah[kk][im], b4l[2*kk], b4l[2*kk+1]);
                        mma_bf16(acc[im][nf], al[kk][im], b4h[2*kk], b4h[2*kk+1]);
                    }
            }
        }
        __syncthreads();
        issue(c + 2);
    }

    if (MODE == 0) {
        int which = bn0 >> 9;
        int h     = (bn0 & 511) >> 6;
        __nv_bfloat16* dh = (which == 0) ? g_qh : (which == 1) ? g_kh : g_vh;
        __nv_bfloat16* dl = (which == 0) ? g_ql : (which == 1) ? g_kl : g_vl;
        float scl = (which == 0) ? QSCALE : 1.0f;
        #pragma unroll
        for (int im = 0; im < 2; im++) {
            #pragma unroll
            for (int nf = 0; nf < 4; nf++) {
                int d = n0 + nf * 8 + 2 * t4;
                int m = bm0 + m0 + im * 16 + g;
                int b = m >> 11, n = m & 2047;
                size_t off = ((size_t)((b << 3) + h) * 2048 + n) * 64 + d;
                uint32_t h0, l0;
                split_pack(acc[im][nf][0] * scl, acc[im][nf][1] * scl, h0, l0);
                *reinterpret_cast<uint32_t*>(&dh[off]) = h0;
                *reinterpret_cast<uint32_t*>(&dl[off]) = l0;
                split_pack(acc[im][nf][2] * scl, acc[im][nf][3] * scl, h0, l0);
                *reinterpret_cast<uint32_t*>(&dh[off + 8 * 64]) = h0;
                *reinterpret_cast<uint32_t*>(&dl[off + 8 * 64]) = l0;
            }
        }
    } else {
        #pragma unroll
        for (int im = 0; im < 2; im++) {
            #pragma unroll
            for (int nf = 0; nf < 4; nf++) {
                int col = bn0 + n0 + nf * 8 + 2 * t4;
                float2 bi = *reinterpret_cast<const float2*>(&bias[col]);
                int m = bm0 + m0 + im * 16 + g;
                float2 v0 = make_float2(acc[im][nf][0] + bi.x, acc[im][nf][1] + bi.y);
                float2 v1 = make_float2(acc[im][nf][2] + bi.x, acc[im][nf][3] + bi.y);
                *reinterpret_cast<float2*>(&out[(size_t)m * 512 + col])       = v0;
                *reinterpret_cast<float2*>(&out[(size_t)(m + 8) * 512 + col]) = v1;
            }
        }
    }
}

// ========================= Flash attention (3 CTA/SM, K dbl + V single) ===
// grid (32 q-tiles, 64 bh), 128 thr = 4 warps; warp w owns q rows [16w,16w+16).
// q pre-scaled by log2(e)/8; softmax in base-2 via ex2.
#define FSM (64 * SSTR)                       // 4608 bf16 per tile
#define FLASH_SMEM_BYTES (8 * FSM * 2)        // 73728

__global__ void __launch_bounds__(128, 3)
flash_mma()
{
    extern __shared__ __nv_bfloat16 sm[];
    __nv_bfloat16* Qhs = sm;
    __nv_bfloat16* Qls = sm + FSM;
    // K buffer b (0,1): base sm + (2+2b)*FSM -> [Kh | Kl]
    __nv_bfloat16* Vhs = sm + 6 * FSM;
    __nv_bfloat16* Vls = sm + 7 * FSM;

    int bh = blockIdx.y, qt = blockIdx.x;
    int tid = threadIdx.x, lane = tid & 31, warp = tid >> 5;
    int g = lane >> 2, t4 = lane & 3;
    int qS = tid & 7;

    int srow[4];
    #pragma unroll
    for (int j = 0; j < 4; j++) srow[j] = (tid + j * 128) >> 3;
    size_t bhoff = (size_t)bh * 2048 * 64;

    auto issue_k = [&](int kt) {
        if (kt < 32) {
            __nv_bfloat16* base = sm + (2 + 2 * (kt & 1)) * FSM;
            size_t koff = bhoff + (size_t)kt * 64 * 64;
            #pragma unroll
            for (int j = 0; j < 4; j++) {
                int r = srow[j];
                size_t go = koff + (size_t)r * 64 + qS * 8;
                int so = r * SSTR + qS * 8;
                cpa16(sptr(base + so),       g_kh + go);
                cpa16(sptr(base + FSM + so), g_kl + go);
            }
        }
        cpa_commit();
    };
    auto issue_v = [&](int kt) {
        if (kt < 32) {
            size_t koff = bhoff + (size_t)kt * 64 * 64;
            #pragma unroll
            for (int j = 0; j < 4; j++) {
                int r = srow[j];
                size_t go = koff + (size_t)r * 64 + qS * 8;
                int so = r * SSTR + qS * 8;
                cpa16(sptr(Vhs + so), g_vh + go);
                cpa16(sptr(Vls + so), g_vl + go);
            }
        }
        cpa_commit();
    };

    issue_k(0);
    issue_v(0);
    issue_k(1);

    size_t qoff = bhoff + (size_t)qt * 64 * 64;
    #pragma unroll
    for (int j = 0; j < 4; j++) {
        int r = srow[j];
        *reinterpret_cast<uint4*>(&Qhs[r * SSTR + qS * 8]) =
            *reinterpret_cast<const uint4*>(g_qh + qoff + (size_t)r * 64 + qS * 8);
        *reinterpret_cast<uint4*>(&Qls[r * SSTR + qS * 8]) =
            *reinterpret_cast<const uint4*>(g_ql + qoff + (size_t)r * 64 + qS * 8);
    }
    __syncthreads();

    uint32_t qh[4][4];
    #pragma unroll
    for (int kc = 0; kc < 4; kc++) {
        int row = warp * 16 + (lane & 15);
        int col = kc * 16 + (lane >> 4) * 8;
        ldsm_x4(qh[kc], sptr(&Qhs[row * SSTR + col]));
    }

    float o[8][4] = {};
    float rm0 = -1e30f, rm1 = -1e30f, rl0 = 0.0f, rl1 = 0.0f;

    for (int kt = 0; kt < 32; kt++) {
        cpa_wait<2>();          // Kg(kt) complete
        __syncthreads();

        __nv_bfloat16* kbase = sm + (2 + 2 * (kt & 1)) * FSM;
        __nv_bfloat16* Khs = kbase;
        __nv_bfloat16* Kls = kbase + FSM;

        // ---- S = Q K^T ----
        float s[8][4] = {};
        #pragma unroll
        for (int kcp = 0; kcp < 2; kcp++) {
            uint32_t ql2[2][4];
            #pragma unroll
            for (int kk = 0; kk < 2; kk++) {
                int row = warp * 16 + (lane & 15);
                int col = (kcp * 2 + kk) * 16 + (lane >> 4) * 8;
                ldsm_x4(ql2[kk], sptr(&Qls[row * SSTR + col]));
            }
            #pragma unroll
            for (int nf = 0; nf < 8; nf++) {
                int rowb = nf * 8 + (lane & 7);
                int colb = kcp * 32 + (lane >> 3) * 8;
                uint32_t b4h[4], b4l[4];
                ldsm_x4(b4h, sptr(&Khs[rowb * SSTR + colb]));
                ldsm_x4(b4l, sptr(&Kls[rowb * SSTR + colb]));
                #pragma unroll
                for (int kk = 0; kk < 2; kk++) {
                    int kc = kcp * 2 + kk;
                    mma_bf16(s[nf], qh[kc],  b4h[2*kk], b4h[2*kk+1]);
                    mma_bf16(s[nf], qh[kc],  b4l[2*kk], b4l[2*kk+1]);
                    mma_bf16(s[nf], ql2[kk], b4h[2*kk], b4h[2*kk+1]);
                }
            }
        }

        // ---- online softmax (base-2, registers, quad reductions) ----
        float mx0 = -1e30f, mx1 = -1e30f;
        #pragma unroll
        for (int nf = 0; nf < 8; nf++) {
            mx0 = fmaxf(mx0, fmaxf(s[nf][0], s[nf][1]));
            mx1 = fmaxf(mx1, fmaxf(s[nf][2], s[nf][3]));
        }
        mx0 = fmaxf(mx0, __shfl_xor_sync(0xffffffffu, mx0, 1));
        mx0 = fmaxf(mx0, __shfl_xor_sync(0xffffffffu, mx0, 2));
        mx1 = fmaxf(mx1, __shfl_xor_sync(0xffffffffu, mx1, 1));
        mx1 = fmaxf(mx1, __shfl_xor_sync(0xffffffffu, mx1, 2));
        float mn0 = fmaxf(rm0, mx0);
        float mn1 = fmaxf(rm1, mx1);

        float sum0 = 0.0f, sum1 = 0.0f;
        #pragma unroll
        for (int nf = 0; nf < 8; nf++) {
            s[nf][0] = ex2(s[nf][0] - mn0);
            s[nf][1] = ex2(s[nf][1] - mn0);
            s[nf][2] = ex2(s[nf][2] - mn1);
            s[nf][3] = ex2(s[nf][3] - mn1);
            sum0 += s[nf][0] + s[nf][1];
            sum1 += s[nf][2] + s[nf][3];
        }
        sum0 += __shfl_xor_sync(0xffffffffu, sum0, 1);
        sum0 += __shfl_xor_sync(0xffffffffu, sum0, 2);
        sum1 += __shfl_xor_sync(0xffffffffu, sum1, 1);
        sum1 += __shfl_xor_sync(0xffffffffu, sum1, 2);

        float sc0 = ex2(rm0 - mn0);
        float sc1 = ex2(rm1 - mn1);
        rm0 = mn0; rm1 = mn1;
        rl0 = rl0 * sc0 + sum0;
        rl1 = rl1 * sc1 + sum1;
        #pragma unroll
        for (int nf = 0; nf < 8; nf++) {
            o[nf][0] *= sc0; o[nf][1] *= sc0;
            o[nf][2] *= sc1; o[nf][3] *= sc1;
        }

        // ---- V arrival, then PV ----
        cpa_wait<1>();          // Vg(kt) complete (Kg(kt+1) still in flight)
        __syncthreads();

        #pragma unroll
        for (int kcp = 0; kcp < 2; kcp++) {
            uint32_t ph[2][4], pl[2][4];
            #pragma unroll
            for (int kk = 0; kk < 2; kk++) {
                int kc = kcp * 2 + kk;
                split_pack(s[2*kc][0],   s[2*kc][1],   ph[kk][0], pl[kk][0]);
                split_pack(s[2*kc][2],   s[2*kc][3],   ph[kk][1], pl[kk][1]);
                split_pack(s[2*kc+1][0], s[2*kc+1][1], ph[kk][2], pl[kk][2]);
                split_pack(s[2*kc+1][2], s[2*kc+1][3], ph[kk][3], pl[kk][3]);
            }
            #pragma unroll
            for (int nf = 0; nf < 8; nf++) {
                uint32_t b4h[4], b4l[4];
                int rowv = kcp * 32 + lane;
                int colv = nf * 8;
                ldsm_x4_t(b4h, sptr(&Vhs[rowv * SSTR + colv]));
                ldsm_x4_t(b4l, sptr(&Vls[rowv * SSTR + colv]));
                #pragma unroll
                for (int kk = 0; kk < 2; kk++) {
                    mma_bf16(o[nf], ph[kk], b4h[2*kk], b4h[2*kk+1]);
                    mma_bf16(o[nf], ph[kk], b4l[2*kk], b4l[2*kk+1]);
                    mma_bf16(o[nf], pl[kk], b4h[2*kk], b4h[2*kk+1]);
                }
            }
        }
        __syncthreads();        // all warps done with V buf + K buf (kt&1)

        issue_v(kt + 1);
        issue_k(kt + 2);
    }

    // ---- epilogue: normalize, split, write g_ah/g_al [b][n][512] ----
    int b = bh >> 3, h = bh & 7;
    float inv0 = 1.0f / rl0;
    float inv1 = 1.0f / rl1;
    int r0 = qt * 64 + warp * 16 + g;
    int r1 = r0 + 8;
    #pragma unroll
    for (int nf = 0; nf < 8; nf++) {
        int col = h * 64 + nf * 8 + 2 * t4;
        uint32_t h0, l0;
        split_pack(o[nf][0] * inv0, o[nf][1] * inv0, h0, l0);
        *reinterpret_cast<uint32_t*>(&g_ah[((size_t)b * 2048 + r0) * 512 + col]) = h0;
        *reinterpret_cast<uint32_t*>(&g_al[((size_t)b * 2048 + r0) * 512 + col]) = l0;
        split_pack(o[nf][2] * inv1, o[nf][3] * inv1, h0, l0);
        *reinterpret_cast<uint32_t*>(&g_ah[((size_t)b * 2048 + r1) * 512 + col]) = h0;
        *reinterpret_cast<uint32_t*>(&g_al[((size_t)b * 2048 + r1) * 512 + col]) = l0;
    }
}

// ========================= launch =========================================
extern "C" void kernel_launch(void* const* d_in, const int* in_sizes, int n_in,
                              void* d_out, int out_size)
{
    const float* x      = (const float*)d_in[0];
    const float* w_qkv  = (const float*)d_in[1];
    const float* w_proj = (const float*)d_in[2];
    const float* b_proj = (const float*)d_in[3];
    const float* gamma  = (const float*)d_in[4];
    const float* beta   = (const float*)d_in[5];
    float* out = (float*)d_out;

    cudaFuncSetAttribute(flash_mma,
                         cudaFuncAttributeMaxDynamicSharedMemorySize,
                         FLASH_SMEM_BYTES);
    cudaFuncSetAttribute(gemm_mma<0>,
                         cudaFuncAttributeMaxDynamicSharedMemorySize,
                         GEMM_SMEM);
    cudaFuncSetAttribute(gemm_mma<1>,
                         cudaFuncAttributeMaxDynamicSharedMemorySize,
                         GEMM_SMEM);

    prep_split<<<2048, 256>>>(w_qkv, w_proj);
    ln_kernel<<<ROWS / 8, 256>>>(x, gamma, beta);
    gemm_mma<0><<<dim3(TRIPLE / 64, ROWS / 128), 256, GEMM_SMEM>>>(nullptr, nullptr);
    flash_mma<<<dim3(SEQ / 64, BATCH * HEADS), 128, FLASH_SMEM_BYTES>>>();
    gemm_mma<1><<<dim3(DIM / 64, ROWS / 128), 256, GEMM_SMEM>>>(b_proj, out);
}

// round 17
// speedup vs baseline: 3.7526x; 1.0046x over previous
#include <cuda_runtime.h>
#include <cuda_bf16.h>
#include <stdint.h>
#include <math.h>

// Problem constants
#define BATCH   8
#define SEQ     2048
#define DIM     512
#define HEADS   8
#define ROWS    (BATCH * SEQ)          // 16384
#define TRIPLE  (3 * DIM)              // 1536
#define SSTR    72                     // smem row stride in bf16 (144B)

// q pre-scale: 1/sqrt(64) * log2(e), softmax in base-2
#define QSCALE  (0.125f * 1.44269504088896f)

// ---------------- scratch (device globals; no runtime allocation) ----------
__device__ __nv_bfloat16 g_xh [ROWS * DIM], g_xl [ROWS * DIM];   // LN out [row][512]
__device__ __nv_bfloat16 g_wqh[TRIPLE * DIM], g_wql[TRIPLE * DIM];
__device__ __nv_bfloat16 g_wph[DIM * DIM],    g_wpl[DIM * DIM];
__device__ __nv_bfloat16 g_qh [ROWS * DIM], g_ql [ROWS * DIM];   // [bh][n][64], q pre-scaled
__device__ __nv_bfloat16 g_kh [ROWS * DIM], g_kl [ROWS * DIM];   // [bh][n][64]
__device__ __nv_bfloat16 g_vh [ROWS * DIM], g_vl [ROWS * DIM];   // [bh][n][64]
__device__ __nv_bfloat16 g_ah [ROWS * DIM], g_al [ROWS * DIM];   // attn out [b][n][512]

// ---------------- helpers ---------------------------------------------------
// Fast hi/lo split: hi = truncated-bf16 pair via PRMT (exact), lo = rounded
// residuals packed by one cvt.rn.bf16x2.f32.
__device__ __forceinline__ void split_pack(float x, float y,
                                           uint32_t& hi, uint32_t& lo)
{
    uint32_t bx = __float_as_uint(x), by = __float_as_uint(y);
    hi = __byte_perm(bx, by, 0x7632);                 // {y.hi16, x.hi16}
    float lx = x - __uint_as_float(bx & 0xFFFF0000u);
    float ly = y - __uint_as_float(by & 0xFFFF0000u);
    asm("cvt.rn.bf16x2.f32 %0, %1, %2;" : "=r"(lo) : "f"(ly), "f"(lx));
}

__device__ __forceinline__ void mma_bf16(float* c, const uint32_t* a,
                                         uint32_t b0, uint32_t b1)
{
    asm volatile(
        "mma.sync.aligned.m16n8k16.row.col.f32.bf16.bf16.f32 "
        "{%0,%1,%2,%3}, {%4,%5,%6,%7}, {%8,%9}, {%0,%1,%2,%3};\n"
        : "+f"(c[0]), "+f"(c[1]), "+f"(c[2]), "+f"(c[3])
        : "r"(a[0]), "r"(a[1]), "r"(a[2]), "r"(a[3]), "r"(b0), "r"(b1));
}

__device__ __forceinline__ uint32_t sptr(const void* p)
{
    return (uint32_t)__cvta_generic_to_shared(p);
}

__device__ __forceinline__ void ldsm_x4(uint32_t* r, uint32_t addr)
{
    asm volatile(
        "ldmatrix.sync.aligned.m8n8.x4.shared.b16 {%0,%1,%2,%3}, [%4];\n"
        : "=r"(r[0]), "=r"(r[1]), "=r"(r[2]), "=r"(r[3]) : "r"(addr));
}

__device__ __forceinline__ void ldsm_x4_t(uint32_t* r, uint32_t addr)
{
    asm volatile(
        "ldmatrix.sync.aligned.m8n8.x4.trans.shared.b16 {%0,%1,%2,%3}, [%4];\n"
        : "=r"(r[0]), "=r"(r[1]), "=r"(r[2]), "=r"(r[3]) : "r"(addr));
}

__device__ __forceinline__ void cpa16(uint32_t saddr, const void* gaddr)
{
    asm volatile("cp.async.cg.shared.global [%0], [%1], 16;\n"
                 :: "r"(saddr), "l"(gaddr));
}

__device__ __forceinline__ void cpa_commit()
{
    asm volatile("cp.async.commit_group;\n");
}

template<int N>
__device__ __forceinline__ void cpa_wait()
{
    asm volatile("cp.async.wait_group %0;\n" :: "n"(N));
}

__device__ __forceinline__ float ex2(float x)
{
    float y;
    asm("ex2.approx.ftz.f32 %0, %1;" : "=f"(y) : "f"(x));
    return y;
}

// ========================= fused LayerNorm + weight split =================
// grid 2048 x 256.  Each block: LN for 8 rows (warp-per-row) AND its
// weight-split slice (2048*256 == NQ+NP exactly).
__global__ void __launch_bounds__(256)
ln_prep_kernel(const float* __restrict__ x,
               const float* __restrict__ gamma,
               const float* __restrict__ beta,
               const float* __restrict__ wq,
               const float* __restrict__ wp)
{
    // ---- weight split slice ----
    {
        const int NQ = TRIPLE * DIM / 2;
        const int NP = DIM * DIM / 2;
        int idx = blockIdx.x * 256 + threadIdx.x;
        if (idx < NQ) {
            float2 v = reinterpret_cast<const float2*>(wq)[idx];
            uint32_t h, l; split_pack(v.x, v.y, h, l);
            reinterpret_cast<uint32_t*>(g_wqh)[idx] = h;
            reinterpret_cast<uint32_t*>(g_wql)[idx] = l;
        } else if (idx < NQ + NP) {
            int j = idx - NQ;
            float2 v = reinterpret_cast<const float2*>(wp)[j];
            uint32_t h, l; split_pack(v.x, v.y, h, l);
            reinterpret_cast<uint32_t*>(g_wph)[j] = h;
            reinterpret_cast<uint32_t*>(g_wpl)[j] = l;
        }
    }

    // ---- LayerNorm: warp per row ----
    int warp = threadIdx.x >> 5, lane = threadIdx.x & 31;
    int row  = blockIdx.x * 8 + warp;

    const float4* xr = reinterpret_cast<const float4*>(x + (size_t)row * 512);
    float4 v[4];
    float s = 0.0f;
    #pragma unroll
    for (int j = 0; j < 4; j++) {
        v[j] = xr[j * 32 + lane];
        s += v[j].x + v[j].y + v[j].z + v[j].w;
    }
    #pragma unroll
    for (int o = 16; o; o >>= 1) s += __shfl_xor_sync(0xffffffffu, s, o);
    float mu = s * (1.0f / 512.0f);

    float s2 = 0.0f;
    #pragma unroll
    for (int j = 0; j < 4; j++) {
        v[j].x -= mu; v[j].y -= mu; v[j].z -= mu; v[j].w -= mu;
        s2 += v[j].x*v[j].x + v[j].y*v[j].y + v[j].z*v[j].z + v[j].w*v[j].w;
    }
    #pragma unroll
    for (int o = 16; o; o >>= 1) s2 += __shfl_xor_sync(0xffffffffu, s2, o);
    float rstd = rsqrtf(s2 * (1.0f / 512.0f) + 1e-6f);

    #pragma unroll
    for (int j = 0; j < 4; j++) {
        float4 g  = reinterpret_cast<const float4*>(gamma)[j * 32 + lane];
        float4 bb = reinterpret_cast<const float4*>(beta)[j * 32 + lane];
        float o0 = v[j].x * rstd * g.x + bb.x;
        float o1 = v[j].y * rstd * g.y + bb.y;
        float o2 = v[j].z * rstd * g.z + bb.z;
        float o3 = v[j].w * rstd * g.w + bb.w;
        uint32_t h0, l0, h1, l1;
        split_pack(o0, o1, h0, l0);
        split_pack(o2, o3, h1, l1);
        int col = j * 128 + lane * 4;
        *reinterpret_cast<uint2*>(&g_xh[(size_t)row * 512 + col]) = make_uint2(h0, h1);
        *reinterpret_cast<uint2*>(&g_xl[(size_t)row * 512 + col]) = make_uint2(l0, l1);
    }
}

// ========================= GEMM (bf16x3, ldmatrix, cp.async dbl-buf) ======
// C[m,c] = sum_k A[m,k] * W[c,k].  Block 128m x 64n, k-chunk 64, 8 chunks.
// MODE 0: qkv -> split bf16 q/k/v scatter; MODE 1: proj -> f32 out + bias.
#define GBUF (384 * SSTR)                       // elems per buffer
#define GEMM_SMEM (2 * GBUF * 2)                // 110592 bytes

template<int MODE>
__global__ void __launch_bounds__(256)
gemm_mma(const float* __restrict__ bias, float* __restrict__ out)
{
    extern __shared__ __nv_bfloat16 sm[];
    // buffer b: [As_h(128) | As_l(128) | Bs_h(64) | Bs_l(64)] rows of SSTR

    const __nv_bfloat16* Ah_g = (MODE == 0) ? g_xh : g_ah;
    const __nv_bfloat16* Al_g = (MODE == 0) ? g_xl : g_al;
    const __nv_bfloat16* Wh_g = (MODE == 0) ? g_wqh : g_wph;
    const __nv_bfloat16* Wl_g = (MODE == 0) ? g_wql : g_wpl;

    int tid = threadIdx.x, lane = tid & 31, warp = tid >> 5;
    int g = lane >> 2, t4 = lane & 3;
    int wm = warp & 3, wn = warp >> 2;
    int m0 = wm * 32, n0 = wn * 32;
    int bm0 = blockIdx.y * 128, bn0 = blockIdx.x * 64;
    int qS = tid & 7;

    auto issue = [&](int chunk) {
        if (chunk < 8) {
            __nv_bfloat16* base = sm + (chunk & 1) * GBUF;
            int k0 = chunk * 64;
            #pragma unroll
            for (int j = 0; j < 4; j++) {
                int r = (tid + j * 256) >> 3;
                size_t go = (size_t)(bm0 + r) * 512 + k0 + qS * 8;
                int so = r * SSTR + qS * 8;
                cpa16(sptr(base + so),              Ah_g + go);
                cpa16(sptr(base + 128 * SSTR + so), Al_g + go);
            }
            #pragma unroll
            for (int j = 0; j < 2; j++) {
                int r = (tid + j * 256) >> 3;
                size_t go = (size_t)(bn0 + r) * 512 + k0 + qS * 8;
                int so = r * SSTR + qS * 8;
                cpa16(sptr(base + 256 * SSTR + so), Wh_g + go);
                cpa16(sptr(base + 320 * SSTR + so), Wl_g + go);
            }
        }
        cpa_commit();
    };

    issue(0);
    issue(1);

    float acc[2][4][4] = {};

    for (int c = 0; c < 8; c++) {
        cpa_wait<1>();
        __syncthreads();
        __nv_bfloat16* base = sm + (c & 1) * GBUF;
        __nv_bfloat16* As_h = base;
        __nv_bfloat16* As_l = base + 128 * SSTR;
        __nv_bfloat16* Bs_h = base + 256 * SSTR;
        __nv_bfloat16* Bs_l = base + 320 * SSTR;

        #pragma unroll
        for (int kcp = 0; kcp < 2; kcp++) {
            uint32_t ah[2][2][4], al[2][2][4];
            #pragma unroll
            for (int kk = 0; kk < 2; kk++)
                #pragma unroll
                for (int im = 0; im < 2; im++) {
                    int row = m0 + im * 16 + (lane & 15);
                    int col = kcp * 32 + kk * 16 + (lane >> 4) * 8;
                    ldsm_x4(ah[kk][im], sptr(&As_h[row * SSTR + col]));
                    ldsm_x4(al[kk][im], sptr(&As_l[row * SSTR + col]));
                }
            #pragma unroll
            for (int nf = 0; nf < 4; nf++) {
                uint32_t b4h[4], b4l[4];
                int rowb = n0 + nf * 8 + (lane & 7);
                int colb = kcp * 32 + (lane >> 3) * 8;
                ldsm_x4(b4h, sptr(&Bs_h[rowb * SSTR + colb]));
                ldsm_x4(b4l, sptr(&Bs_l[rowb * SSTR + colb]));
                #pragma unroll
                for (int kk = 0; kk < 2; kk++)
                    #pragma unroll
                    for (int im = 0; im < 2; im++) {
                        mma_bf16(acc[im][nf], ah[kk][im], b4h[2*kk], b4h[2*kk+1]);
                        mma_bf16(acc[im][nf], ah[kk][im], b4l[2*kk], b4l[2*kk+1]);
                        mma_bf16(acc[im][nf], al[kk][im], b4h[2*kk], b4h[2*kk+1]);
                    }
            }
        }
        __syncthreads();
        issue(c + 2);
    }

    if (MODE == 0) {
        int which = bn0 >> 9;
        int h     = (bn0 & 511) >> 6;
        __nv_bfloat16* dh = (which == 0) ? g_qh : (which == 1) ? g_kh : g_vh;
        __nv_bfloat16* dl = (which == 0) ? g_ql : (which == 1) ? g_kl : g_vl;
        float scl = (which == 0) ? QSCALE : 1.0f;
        #pragma unroll
        for (int im = 0; im < 2; im++) {
            #pragma unroll
            for (int nf = 0; nf < 4; nf++) {
                int d = n0 + nf * 8 + 2 * t4;
                int m = bm0 + m0 + im * 16 + g;
                int b = m >> 11, n = m & 2047;
                size_t off = ((size_t)((b << 3) + h) * 2048 + n) * 64 + d;
                uint32_t h0, l0;
                split_pack(acc[im][nf][0] * scl, acc[im][nf][1] * scl, h0, l0);
                *reinterpret_cast<uint32_t*>(&dh[off]) = h0;
                *reinterpret_cast<uint32_t*>(&dl[off]) = l0;
                split_pack(acc[im][nf][2] * scl, acc[im][nf][3] * scl, h0, l0);
                *reinterpret_cast<uint32_t*>(&dh[off + 8 * 64]) = h0;
                *reinterpret_cast<uint32_t*>(&dl[off + 8 * 64]) = l0;
            }
        }
    } else {
        #pragma unroll
        for (int im = 0; im < 2; im++) {
            #pragma unroll
            for (int nf = 0; nf < 4; nf++) {
                int col = bn0 + n0 + nf * 8 + 2 * t4;
                float2 bi = *reinterpret_cast<const float2*>(&bias[col]);
                int m = bm0 + m0 + im * 16 + g;
                float2 v0 = make_float2(acc[im][nf][0] + bi.x, acc[im][nf][1] + bi.y);
                float2 v1 = make_float2(acc[im][nf][2] + bi.x, acc[im][nf][3] + bi.y);
                *reinterpret_cast<float2*>(&out[(size_t)m * 512 + col])       = v0;
                *reinterpret_cast<float2*>(&out[(size_t)(m + 8) * 512 + col]) = v1;
            }
        }
    }
}

// ========================= Flash attention (3 CTA/SM, 2 syncs/iter) =======
// grid (32 q-tiles, 64 bh), 128 thr = 4 warps; warp w owns q rows [16w,16w+16).
// Merged K+V wait at iteration top; group invariant before wait: {K(t),V(t),K(t+1)}.
#define FSM (64 * SSTR)                       // 4608 bf16 per tile
#define FLASH_SMEM_BYTES (8 * FSM * 2)        // 73728

__global__ void __launch_bounds__(128, 3)
flash_mma()
{
    extern __shared__ __nv_bfloat16 sm[];
    __nv_bfloat16* Qhs = sm;
    __nv_bfloat16* Qls = sm + FSM;
    // K buffer b (0,1): base sm + (2+2b)*FSM -> [Kh | Kl]
    __nv_bfloat16* Vhs = sm + 6 * FSM;
    __nv_bfloat16* Vls = sm + 7 * FSM;

    int bh = blockIdx.y, qt = blockIdx.x;
    int tid = threadIdx.x, lane = tid & 31, warp = tid >> 5;
    int g = lane >> 2, t4 = lane & 3;
    int qS = tid & 7;

    int srow[4];
    #pragma unroll
    for (int j = 0; j < 4; j++) srow[j] = (tid + j * 128) >> 3;
    size_t bhoff = (size_t)bh * 2048 * 64;

    auto issue_k = [&](int kt) {
        if (kt < 32) {
            __nv_bfloat16* base = sm + (2 + 2 * (kt & 1)) * FSM;
            size_t koff = bhoff + (size_t)kt * 64 * 64;
            #pragma unroll
            for (int j = 0; j < 4; j++) {
                int r = srow[j];
                size_t go = koff + (size_t)r * 64 + qS * 8;
                int so = r * SSTR + qS * 8;
                cpa16(sptr(base + so),       g_kh + go);
                cpa16(sptr(base + FSM + so), g_kl + go);
            }
        }
        cpa_commit();
    };
    auto issue_v = [&](int kt) {
        if (kt < 32) {
            size_t koff = bhoff + (size_t)kt * 64 * 64;
            #pragma unroll
            for (int j = 0; j < 4; j++) {
                int r = srow[j];
                size_t go = koff + (size_t)r * 64 + qS * 8;
                int so = r * SSTR + qS * 8;
                cpa16(sptr(Vhs + so), g_vh + go);
                cpa16(sptr(Vls + so), g_vl + go);
            }
        }
        cpa_commit();
    };

    issue_k(0);
    issue_v(0);
    issue_k(1);

    size_t qoff = bhoff + (size_t)qt * 64 * 64;
    #pragma unroll
    for (int j = 0; j < 4; j++) {
        int r = srow[j];
        *reinterpret_cast<uint4*>(&Qhs[r * SSTR + qS * 8]) =
            *reinterpret_cast<const uint4*>(g_qh + qoff + (size_t)r * 64 + qS * 8);
        *reinterpret_cast<uint4*>(&Qls[r * SSTR + qS * 8]) =
            *reinterpret_cast<const uint4*>(g_ql + qoff + (size_t)r * 64 + qS * 8);
    }
    __syncthreads();

    uint32_t qh[4][4];
    #pragma unroll
    for (int kc = 0; kc < 4; kc++) {
        int row = warp * 16 + (lane & 15);
        int col = kc * 16 + (lane >> 4) * 8;
        ldsm_x4(qh[kc], sptr(&Qhs[row * SSTR + col]));
    }

    float o[8][4] = {};
    float rm0 = -1e30f, rm1 = -1e30f, rl0 = 0.0f, rl1 = 0.0f;

    for (int kt = 0; kt < 32; kt++) {
        // pending groups: {K(kt), V(kt), K(kt+1)} -> wait<1> completes K(kt)+V(kt)
        cpa_wait<1>();
        __syncthreads();

        __nv_bfloat16* kbase = sm + (2 + 2 * (kt & 1)) * FSM;
        __nv_bfloat16* Khs = kbase;
        __nv_bfloat16* Kls = kbase + FSM;

        // ---- S = Q K^T ----
        float s[8][4] = {};
        #pragma unroll
        for (int kcp = 0; kcp < 2; kcp++) {
            uint32_t ql2[2][4];
            #pragma unroll
            for (int kk = 0; kk < 2; kk++) {
                int row = warp * 16 + (lane & 15);
                int col = (kcp * 2 + kk) * 16 + (lane >> 4) * 8;
                ldsm_x4(ql2[kk], sptr(&Qls[row * SSTR + col]));
            }
            #pragma unroll
            for (int nf = 0; nf < 8; nf++) {
                int rowb = nf * 8 + (lane & 7);
                int colb = kcp * 32 + (lane >> 3) * 8;
                uint32_t b4h[4], b4l[4];
                ldsm_x4(b4h, sptr(&Khs[rowb * SSTR + colb]));
                ldsm_x4(b4l, sptr(&Kls[rowb * SSTR + colb]));
                #pragma unroll
                for (int kk = 0; kk < 2; kk++) {
                    int kc = kcp * 2 + kk;
                    mma_bf16(s[nf], qh[kc],  b4h[2*kk], b4h[2*kk+1]);
                    mma_bf16(s[nf], qh[kc],  b4l[2*kk], b4l[2*kk+1]);
                    mma_bf16(s[nf], ql2[kk], b4h[2*kk], b4h[2*kk+1]);
                }
            }
        }

        // ---- online softmax (base-2, registers, quad reductions) ----
        float mx0 = -1e30f, mx1 = -1e30f;
        #pragma unroll
        for (int nf = 0; nf < 8; nf++) {
            mx0 = fmaxf(mx0, fmaxf(s[nf][0], s[nf][1]));
            mx1 = fmaxf(mx1, fmaxf(s[nf][2], s[nf][3]));
        }
        mx0 = fmaxf(mx0, __shfl_xor_sync(0xffffffffu, mx0, 1));
        mx0 = fmaxf(mx0, __shfl_xor_sync(0xffffffffu, mx0, 2));
        mx1 = fmaxf(mx1, __shfl_xor_sync(0xffffffffu, mx1, 1));
        mx1 = fmaxf(mx1, __shfl_xor_sync(0xffffffffu, mx1, 2));
        float mn0 = fmaxf(rm0, mx0);
        float mn1 = fmaxf(rm1, mx1);

        float sum0 = 0.0f, sum1 = 0.0f;
        #pragma unroll
        for (int nf = 0; nf < 8; nf++) {
            s[nf][0] = ex2(s[nf][0] - mn0);
            s[nf][1] = ex2(s[nf][1] - mn0);
            s[nf][2] = ex2(s[nf][2] - mn1);
            s[nf][3] = ex2(s[nf][3] - mn1);
            sum0 += s[nf][0] + s[nf][1];
            sum1 += s[nf][2] + s[nf][3];
        }
        sum0 += __shfl_xor_sync(0xffffffffu, sum0, 1);
        sum0 += __shfl_xor_sync(0xffffffffu, sum0, 2);
        sum1 += __shfl_xor_sync(0xffffffffu, sum1, 1);
        sum1 += __shfl_xor_sync(0xffffffffu, sum1, 2);

        float sc0 = ex2(rm0 - mn0);
        float sc1 = ex2(rm1 - mn1);
        rm0 = mn0; rm1 = mn1;
        rl0 = rl0 * sc0 + sum0;
        rl1 = rl1 * sc1 + sum1;
        #pragma unroll
        for (int nf = 0; nf < 8; nf++) {
            o[nf][0] *= sc0; o[nf][1] *= sc0;
            o[nf][2] *= sc1; o[nf][3] *= sc1;
        }

        // ---- PV (V already arrived with the merged wait) ----
        #pragma unroll
        for (int kcp = 0; kcp < 2; kcp++) {
            uint32_t ph[2][4], pl[2][4];
            #pragma unroll
            for (int kk = 0; kk < 2; kk++) {
                int kc = kcp * 2 + kk;
                split_pack(s[2*kc][0],   s[2*kc][1],   ph[kk][0], pl[kk][0]);
                split_pack(s[2*kc][2],   s[2*kc][3],   ph[kk][1], pl[kk][1]);
                split_pack(s[2*kc+1][0], s[2*kc+1][1], ph[kk][2], pl[kk][2]);
                split_pack(s[2*kc+1][2], s[2*kc+1][3], ph[kk][3], pl[kk][3]);
            }
            #pragma unroll
            for (int nf = 0; nf < 8; nf++) {
                uint32_t b4h[4], b4l[4];
                int rowv = kcp * 32 + lane;
                int colv = nf * 8;
                ldsm_x4_t(b4h, sptr(&Vhs[rowv * SSTR + colv]));
                ldsm_x4_t(b4l, sptr(&Vls[rowv * SSTR + colv]));
                #pragma unroll
                for (int kk = 0; kk < 2; kk++) {
                    mma_bf16(o[nf], ph[kk], b4h[2*kk], b4h[2*kk+1]);
                    mma_bf16(o[nf], ph[kk], b4l[2*kk], b4l[2*kk+1]);
                    mma_bf16(o[nf], pl[kk], b4h[2*kk], b4h[2*kk+1]);
                }
            }
        }
        __syncthreads();        // all warps done with V buf + K buf (kt&1)

        issue_v(kt + 1);        // V single buffer: safe after barrier
        issue_k(kt + 2);        // into buffer (kt+2)&1 = (kt&1), just drained
    }

    // ---- epilogue: normalize, split, write g_ah/g_al [b][n][512] ----
    int b = bh >> 3, h = bh & 7;
    float inv0 = 1.0f / rl0;
    float inv1 = 1.0f / rl1;
    int r0 = qt * 64 + warp * 16 + g;
    int r1 = r0 + 8;
    #pragma unroll
    for (int nf = 0; nf < 8; nf++) {
        int col = h * 64 + nf * 8 + 2 * t4;
        uint32_t h0, l0;
        split_pack(o[nf][0] * inv0, o[nf][1] * inv0, h0, l0);
        *reinterpret_cast<uint32_t*>(&g_ah[((size_t)b * 2048 + r0) * 512 + col]) = h0;
        *reinterpret_cast<uint32_t*>(&g_al[((size_t)b * 2048 + r0) * 512 + col]) = l0;
        split_pack(o[nf][2] * inv1, o[nf][3] * inv1, h0, l0);
        *reinterpret_cast<uint32_t*>(&g_ah[((size_t)b * 2048 + r1) * 512 + col]) = h0;
        *reinterpret_cast<uint32_t*>(&g_al[((size_t)b * 2048 + r1) * 512 + col]) = l0;
    }
}

// ========================= launch =========================================
extern "C" void kernel_launch(void* const* d_in, const int* in_sizes, int n_in,
                              void* d_out, int out_size)
{
    const float* x      = (const float*)d_in[0];
    const float* w_qkv  = (const float*)d_in[1];
    const float* w_proj = (const float*)d_in[2];
    const float* b_proj = (const float*)d_in[3];
    const float* gamma  = (const float*)d_in[4];
    const float* beta   = (const float*)d_in[5];
    float* out = (float*)d_out;

    cudaFuncSetAttribute(flash_mma,
                         cudaFuncAttributeMaxDynamicSharedMemorySize,
                         FLASH_SMEM_BYTES);
    cudaFuncSetAttribute(gemm_mma<0>,
                         cudaFuncAttributeMaxDynamicSharedMemorySize,
                         GEMM_SMEM);
    cudaFuncSetAttribute(gemm_mma<1>,
                         cudaFuncAttributeMaxDynamicSharedMemorySize,
                         GEMM_SMEM);

    ln_prep_kernel<<<2048, 256>>>(x, gamma, beta, w_qkv, w_proj);
    gemm_mma<0><<<dim3(TRIPLE / 64, ROWS / 128), 256, GEMM_SMEM>>>(nullptr, nullptr);
    flash_mma<<<dim3(SEQ / 64, BATCH * HEADS), 128, FLASH_SMEM_BYTES>>>();
    gemm_mma<1><<<dim3(DIM / 64, ROWS / 128), 256, GEMM_SMEM>>>(b_proj, out);
}